// round 1
// baseline (speedup 1.0000x reference)
#include <cuda_runtime.h>

// ---------------------------------------------------------------------------
// EGCL_Multi: N=512 nodes, H=8 heads, HD=128, M=256 MLP width.
// Key algebraic optimization: first edge-MLP layer is separable:
//   edge_in = [sqn(8) | hc[j](192) | hc[i](192)]
//   pre0(i,j) = sqn(i,j)@We0[0:8] + A[j] + B[i] + be0
// with A = hc@We0[8:200], B = hc@We0[200:392] precomputed per node.
// Per-edge heavy work: 3x (64x256)@(256x256) GEMMs done with packed
// fma.rn.f32x2 (2x fp32 FMA rate on sm_103a).
// ---------------------------------------------------------------------------

#define NN 512
#define TJ 64

// scratch (no allocation allowed)
__device__ float g_hc[NN * 192];
__device__ float g_A[NN * 256];
__device__ float g_B[NN * 256];
__device__ float g_mi[NN * 256];
__device__ float g_shift[NN * 24];

__device__ __forceinline__ unsigned long long pk2(float lo, float hi) {
    unsigned long long r;
    asm("mov.b64 %0, {%1, %2};" : "=l"(r) : "f"(lo), "f"(hi));
    return r;
}
__device__ __forceinline__ void upk2(unsigned long long v, float& lo, float& hi) {
    asm("mov.b64 {%0, %1}, %2;" : "=f"(lo), "=f"(hi) : "l"(v));
}
__device__ __forceinline__ void fma2(unsigned long long& d, unsigned long long a,
                                     unsigned long long b) {
    asm("fma.rn.f32x2 %0, %1, %2, %0;" : "+l"(d) : "l"(a), "l"(b));
}
__device__ __forceinline__ float silu_f(float v) {
    return v * (1.0f / (1.0f + __expf(-v)));
}

// C[64,N] = act(In[64,K] @ W[K,N] + bias), In in smem, W streamed global->smem,
// out may be smem or global. 256 threads. K % 32 == 0, N in {128, 256}.
template <int N, bool ACT>
__device__ __forceinline__ void gemm64(const float* sIn, int K,
                                       const float* __restrict__ Wg,
                                       const float* __restrict__ bias,
                                       float* out, float* ws) {
    constexpr int COLG = N / 8;        // col groups of 8
    constexpr int RPT = COLG / 4;      // rows per thread (8 for N=256, 4 for N=128)
    const int t = threadIdx.x;
    const int nc = t % COLG, mr = t / COLG;
    const int r0 = mr * RPT, c0 = nc * 8;
    unsigned long long acc[RPT][4];
#pragma unroll
    for (int r = 0; r < RPT; r++)
#pragma unroll
        for (int p = 0; p < 4; p++) acc[r][p] = 0ULL;

    for (int kt = 0; kt < K; kt += 32) {
        __syncthreads();
        for (int idx = t; idx < 32 * N / 4; idx += 256) {
            int wr = idx / (N / 4);
            int wc = (idx - wr * (N / 4)) * 4;
            *(float4*)&ws[wr * N + wc] = *(const float4*)&Wg[(kt + wr) * N + wc];
        }
        __syncthreads();
#pragma unroll
        for (int k4 = 0; k4 < 8; k4++) {
            float4 av[RPT];
#pragma unroll
            for (int r = 0; r < RPT; r++)
                av[r] = *(const float4*)&sIn[(r0 + r) * K + kt + k4 * 4];
#pragma unroll
            for (int kk = 0; kk < 4; kk++) {
                const float* wrow = &ws[(k4 * 4 + kk) * N + c0];
                float4 w0 = *(const float4*)&wrow[0];
                float4 w1 = *(const float4*)&wrow[4];
                unsigned long long b0 = pk2(w0.x, w0.y), b1 = pk2(w0.z, w0.w);
                unsigned long long b2 = pk2(w1.x, w1.y), b3 = pk2(w1.z, w1.w);
#pragma unroll
                for (int r = 0; r < RPT; r++) {
                    float a = (kk == 0) ? av[r].x
                            : (kk == 1) ? av[r].y
                            : (kk == 2) ? av[r].z
                                        : av[r].w;
                    unsigned long long a2 = pk2(a, a);
                    fma2(acc[r][0], a2, b0);
                    fma2(acc[r][1], a2, b1);
                    fma2(acc[r][2], a2, b2);
                    fma2(acc[r][3], a2, b3);
                }
            }
        }
    }
#pragma unroll
    for (int r = 0; r < RPT; r++) {
#pragma unroll
        for (int p = 0; p < 4; p++) {
            float lo, hi;
            upk2(acc[r][p], lo, hi);
            int c = c0 + p * 2;
            if (bias) {
                float2 bb = *(const float2*)&bias[c];
                lo += bb.x;
                hi += bb.y;
            }
            if (ACT) {
                lo = silu_f(lo);
                hi = silu_f(hi);
            }
            float2 o;
            o.x = lo;
            o.y = hi;
            *(float2*)&out[(r0 + r) * N + c] = o;
        }
    }
    __syncthreads();
}

// ---------------------------------------------------------------------------
__global__ void zero_kernel() {
    int idx = blockIdx.x * 256 + threadIdx.x;
    if (idx < NN * 256) g_mi[idx] = 0.f;
    if (idx < NN * 24) g_shift[idx] = 0.f;
}

// hc[n] = [h[n] (128) | per-head-pair sq dists (64)]
__global__ void prep_hc(const float* __restrict__ x, const float* __restrict__ h) {
    int n = blockIdx.x, t = threadIdx.x;
    if (t < 128) {
        g_hc[n * 192 + t] = h[n * 128 + t];
    } else {
        int p = t - 128;
        int a = p >> 3, b = p & 7;
        float dx = x[n * 24 + a * 3 + 0] - x[n * 24 + b * 3 + 0];
        float dy = x[n * 24 + a * 3 + 1] - x[n * 24 + b * 3 + 1];
        float dz = x[n * 24 + a * 3 + 2] - x[n * 24 + b * 3 + 2];
        g_hc[n * 192 + 128 + p] = dx * dx + dy * dy + dz * dz;
    }
}

// A = hc @ We0[8:200], B = hc @ We0[200:392]   (grid: 8 row tiles x 2)
__global__ void __launch_bounds__(256) prep_ab(const float* __restrict__ We0) {
    extern __shared__ float sm[];
    float* sIn = sm;              // 64*192
    float* ws = sm + 64 * 192;    // 32*256
    int r0g = blockIdx.x * 64, t = threadIdx.x;
    for (int idx = t; idx < 64 * 192 / 4; idx += 256)
        *(float4*)&sIn[idx * 4] = *(const float4*)&g_hc[r0g * 192 + idx * 4];
    __syncthreads();
    const float* Wg = We0 + (blockIdx.y == 0 ? 8 : 200) * 256;
    float* outp = (blockIdx.y == 0 ? g_A : g_B) + r0g * 256;
    gemm64<256, false>(sIn, 192, Wg, nullptr, outp, ws);
}

// ---------------------------------------------------------------------------
// Fused edge kernel: one CTA = receiver i x 64 senders j.
__global__ void __launch_bounds__(256) edge_kernel(
    const float* __restrict__ x,
    const float* __restrict__ We0, const float* __restrict__ be0,
    const float* __restrict__ We1, const float* __restrict__ be1,
    const float* __restrict__ Winf, const float* __restrict__ binf,
    const float* __restrict__ Wx0, const float* __restrict__ bx0,
    const float* __restrict__ Wx1, const float* __restrict__ bx1,
    const float* __restrict__ Wxo, const float* __restrict__ bxo) {
    extern __shared__ float sm[];
    float* sA = sm;                 // 16384
    float* sB = sA + 16384;         // 16384
    float* sW = sB + 16384;         // 8192 (GEMM weight staging)
    float* sAux = sW + 8192;        // 2048 (We0[0:8] then Wxo^T)
    float* sXj = sAux + 2048;       // 1536
    float* sXi = sXj + 1536;        // 24
    float* sSqn = sXi + 24;         // 512
    float* sBC = sSqn + 512;        // 256 (B[i]+be0, then Winf)
    float* sE = sBC + 256;          // 64
    float* sPx = sE + 64;           // 512
    float* sSh = sPx + 512;         // 24

    const int i = blockIdx.y;
    const int j0 = blockIdx.x * TJ;
    const int t = threadIdx.x;

    for (int idx = t; idx < TJ * 24; idx += 256) sXj[idx] = x[j0 * 24 + idx];
    if (t < 24) sXi[t] = x[i * 24 + t];
    for (int idx = t; idx < 2048; idx += 256) sAux[idx] = We0[idx];  // rows 0..7
    sBC[t] = g_B[i * 256 + t] + be0[t];
    __syncthreads();

    // per-edge head distances sqn[j][hh]
    for (int p = t; p < 512; p += 256) {
        int j = p >> 3, hh = p & 7;
        float dx = sXj[j * 24 + hh * 3 + 0] - sXi[hh * 3 + 0];
        float dy = sXj[j * 24 + hh * 3 + 1] - sXi[hh * 3 + 1];
        float dz = sXj[j * 24 + hh * 3 + 2] - sXi[hh * 3 + 2];
        sSqn[p] = dx * dx + dy * dy + dz * dz;
    }
    __syncthreads();

    // t0 = silu(A[j] + (B[i]+be0) + sqn @ We0[0:8])
    for (int it = 0; it < 16; ++it) {
        int idx = it * 256 + t;
        int j = idx >> 6;
        int c = (idx & 63) * 4;
        float4 v = *(const float4*)&g_A[(j0 + j) * 256 + c];
        v.x += sBC[c]; v.y += sBC[c + 1]; v.z += sBC[c + 2]; v.w += sBC[c + 3];
#pragma unroll
        for (int q = 0; q < 8; q++) {
            float s = sSqn[j * 8 + q];
            float4 w = *(const float4*)&sAux[q * 256 + c];
            v.x += s * w.x; v.y += s * w.y; v.z += s * w.z; v.w += s * w.w;
        }
        v.x = silu_f(v.x); v.y = silu_f(v.y); v.z = silu_f(v.z); v.w = silu_f(v.w);
        *(float4*)&sA[j * 256 + c] = v;
    }
    __syncthreads();

    // m = silu(t0 @ We1 + be1)
    gemm64<256, true>(sA, 256, We1, be1, sB, sW);

    // stage Winf into sBC, Wxo^T into sAux
    for (int idx = t; idx < 2048; idx += 256) {
        int c = idx >> 3, hh = idx & 7;
        sAux[hh * 256 + c] = Wxo[idx];
    }
    sBC[t] = Winf[t];
    __syncthreads();

    // e[j] = sigmoid(m @ Winf + binf), masked at j==i
    {
        int row = t >> 2, l4 = t & 3;
        float s = 0.f;
        for (int c = l4 * 64; c < l4 * 64 + 64; ++c) s += sB[row * 256 + c] * sBC[c];
        s += __shfl_xor_sync(0xffffffffu, s, 1);
        s += __shfl_xor_sync(0xffffffffu, s, 2);
        if (l4 == 0) {
            float ee = 1.0f / (1.0f + __expf(-(s + binf[0])));
            if (j0 + row == i) ee = 0.f;
            sE[row] = ee;
        }
    }
    __syncthreads();

    // m_i partial: sum_j m[j][c]*e[j]
    {
        float acc = 0.f;
#pragma unroll 8
        for (int j = 0; j < TJ; j++) acc += sB[j * 256 + t] * sE[j];
        atomicAdd(&g_mi[i * 256 + t], acc);
    }

    // phi_x hidden layers
    gemm64<256, true>(sB, 256, Wx0, bx0, sA, sW);
    gemm64<256, true>(sA, 256, Wx1, bx1, sB, sW);

    // px[j][hh] = u2 @ Wxo + bxo
    for (int p = t; p < 512; p += 256) {
        int row = p >> 3, hh = p & 7;
        float s = bxo[hh];
        const float* br = &sB[row * 256];
        const float* wr2 = &sAux[hh * 256];
#pragma unroll 16
        for (int c = 0; c < 256; c += 4) {
            float4 b4 = *(const float4*)&br[c];
            float4 w4 = *(const float4*)&wr2[c];
            s += b4.x * w4.x + b4.y * w4.y + b4.z * w4.z + b4.w * w4.w;
        }
        sPx[p] = s;
    }
    if (t < 24) sSh[t] = 0.f;
    __syncthreads();

    // shift partial: sum_j px/(sqrt(sqn)+1) * (x[j]-x[i])
    for (int p = t; p < 512; p += 256) {
        int row = p >> 3, hh = p & 7;
        float nrm = sqrtf(sSqn[p] + 1e-8f) + 1.0f;
        float w = sPx[p] / nrm;
#pragma unroll
        for (int d = 0; d < 3; ++d) {
            float dn = sXj[row * 24 + hh * 3 + d] - sXi[hh * 3 + d];
            atomicAdd(&sSh[hh * 3 + d], w * dn);
        }
    }
    __syncthreads();
    if (t < 24) atomicAdd(&g_shift[i * 24 + t], sSh[t]);
}

// ---------------------------------------------------------------------------
// h_new = h + MLP([m_i, h])
__global__ void __launch_bounds__(256) hnew_kernel(
    const float* __restrict__ h,
    const float* __restrict__ Wh0, const float* __restrict__ bh0,
    const float* __restrict__ Wh1, const float* __restrict__ bh1,
    const float* __restrict__ Who, const float* __restrict__ bho,
    float* __restrict__ out) {
    extern __shared__ float sm[];
    float* buf0 = sm;                 // 64*384
    float* buf1 = buf0 + 64 * 384;    // 64*256
    float* ws = buf1 + 64 * 256;      // 32*256
    int r0g = blockIdx.x * 64, t = threadIdx.x;
    for (int idx = t; idx < 64 * 384; idx += 256) {
        int row = idx / 384, c = idx - row * 384;
        buf0[idx] = (c < 256) ? g_mi[(r0g + row) * 256 + c]
                              : h[(r0g + row) * 128 + (c - 256)];
    }
    __syncthreads();
    gemm64<256, true>(buf0, 384, Wh0, bh0, buf1, ws);
    gemm64<256, true>(buf1, 256, Wh1, bh1, buf0, ws);
    gemm64<128, false>(buf0, 256, Who, bho, buf1, ws);
    for (int idx = t; idx < 64 * 128; idx += 256)
        out[r0g * 128 + idx] = buf1[idx] + h[r0g * 128 + idx];
}

__global__ void xnew_kernel(const float* __restrict__ x, float* __restrict__ out) {
    int idx = blockIdx.x * 256 + threadIdx.x;
    if (idx < NN * 24) out[idx] = x[idx] + g_shift[idx] * (1.0f / 511.0f);
}

// ---------------------------------------------------------------------------
extern "C" void kernel_launch(void* const* d_in, const int* in_sizes, int n_in,
                              void* d_out, int out_size) {
    const float* x = (const float*)d_in[0];
    const float* h = (const float*)d_in[1];
    const float* We0 = (const float*)d_in[2];
    const float* be0 = (const float*)d_in[3];
    const float* We1 = (const float*)d_in[4];
    const float* be1 = (const float*)d_in[5];
    const float* Winf = (const float*)d_in[6];
    const float* binf = (const float*)d_in[7];
    const float* Wx0 = (const float*)d_in[8];
    const float* bx0 = (const float*)d_in[9];
    const float* Wx1 = (const float*)d_in[10];
    const float* bx1 = (const float*)d_in[11];
    const float* Wxo = (const float*)d_in[12];
    const float* bxo = (const float*)d_in[13];
    const float* Wh0 = (const float*)d_in[14];
    const float* bh0 = (const float*)d_in[15];
    const float* Wh1 = (const float*)d_in[16];
    const float* bh1 = (const float*)d_in[17];
    const float* Who = (const float*)d_in[18];
    const float* bho = (const float*)d_in[19];
    float* out = (float*)d_out;  // [x_new (512*8*3) | h_new (512*128)]

    const int EDGE_SMEM = 45936 * 4;
    const int AB_SMEM = (64 * 192 + 32 * 256) * 4;
    const int HNEW_SMEM = (64 * 384 + 64 * 256 + 32 * 256) * 4;
    cudaFuncSetAttribute(edge_kernel, cudaFuncAttributeMaxDynamicSharedMemorySize,
                         EDGE_SMEM);
    cudaFuncSetAttribute(prep_ab, cudaFuncAttributeMaxDynamicSharedMemorySize,
                         AB_SMEM);
    cudaFuncSetAttribute(hnew_kernel, cudaFuncAttributeMaxDynamicSharedMemorySize,
                         HNEW_SMEM);

    zero_kernel<<<512, 256>>>();
    prep_hc<<<NN, 192>>>(x, h);
    prep_ab<<<dim3(8, 2), 256, AB_SMEM>>>(We0);
    edge_kernel<<<dim3(8, NN), 256, EDGE_SMEM>>>(x, We0, be0, We1, be1, Winf, binf,
                                                 Wx0, bx0, Wx1, bx1, Wxo, bxo);
    hnew_kernel<<<8, 256, HNEW_SMEM>>>(h, Wh0, bh0, Wh1, bh1, Who, bho,
                                       out + NN * 24);
    xnew_kernel<<<48, 256>>>(x, out);
}

// round 2
// speedup vs baseline: 1.0012x; 1.0012x over previous
#include <cuda_runtime.h>

// ---------------------------------------------------------------------------
// EGCL_Multi: N=512 nodes, H=8 heads, HD=128, M=256 MLP width.
// Key algebraic optimization: first edge-MLP layer is separable:
//   edge_in = [sqn(8) | hc[j](192) | hc[i](192)]
//   pre0(i,j) = sqn(i,j)@We0[0:8] + A[j] + B[i] + be0
// with A = hc@We0[8:200], B = hc@We0[200:392] precomputed per node.
// Per-edge heavy work: 3x (64x256)@(256x256) GEMMs done with packed
// fma.rn.f32x2 (2x fp32 FMA rate on sm_103a).
// ---------------------------------------------------------------------------

#define NN 512
#define TJ 64

// scratch (no allocation allowed)
__device__ float g_hc[NN * 192];
__device__ float g_A[NN * 256];
__device__ float g_B[NN * 256];
__device__ float g_mi[NN * 256];
__device__ float g_shift[NN * 24];

__device__ __forceinline__ unsigned long long pk2(float lo, float hi) {
    unsigned long long r;
    asm("mov.b64 %0, {%1, %2};" : "=l"(r) : "f"(lo), "f"(hi));
    return r;
}
__device__ __forceinline__ void upk2(unsigned long long v, float& lo, float& hi) {
    asm("mov.b64 {%0, %1}, %2;" : "=f"(lo), "=f"(hi) : "l"(v));
}
__device__ __forceinline__ void fma2(unsigned long long& d, unsigned long long a,
                                     unsigned long long b) {
    asm("fma.rn.f32x2 %0, %1, %2, %0;" : "+l"(d) : "l"(a), "l"(b));
}
__device__ __forceinline__ float silu_f(float v) {
    return v * (1.0f / (1.0f + __expf(-v)));
}

// C[64,N] = act(In[64,K] @ W[K,N] + bias), In in smem, W streamed global->smem,
// out may be smem or global. 256 threads. K % 32 == 0, N in {128, 256}.
template <int N, bool ACT>
__device__ __forceinline__ void gemm64(const float* sIn, int K,
                                       const float* __restrict__ Wg,
                                       const float* __restrict__ bias,
                                       float* out, float* ws) {
    constexpr int COLG = N / 8;        // col groups of 8
    constexpr int RPT = COLG / 4;      // rows per thread (8 for N=256, 4 for N=128)
    const int t = threadIdx.x;
    const int nc = t % COLG, mr = t / COLG;
    const int r0 = mr * RPT, c0 = nc * 8;
    unsigned long long acc[RPT][4];
#pragma unroll
    for (int r = 0; r < RPT; r++)
#pragma unroll
        for (int p = 0; p < 4; p++) acc[r][p] = 0ULL;

    for (int kt = 0; kt < K; kt += 32) {
        __syncthreads();
        for (int idx = t; idx < 32 * N / 4; idx += 256) {
            int wr = idx / (N / 4);
            int wc = (idx - wr * (N / 4)) * 4;
            *(float4*)&ws[wr * N + wc] = *(const float4*)&Wg[(kt + wr) * N + wc];
        }
        __syncthreads();
#pragma unroll
        for (int k4 = 0; k4 < 8; k4++) {
            float4 av[RPT];
#pragma unroll
            for (int r = 0; r < RPT; r++)
                av[r] = *(const float4*)&sIn[(r0 + r) * K + kt + k4 * 4];
#pragma unroll
            for (int kk = 0; kk < 4; kk++) {
                const float* wrow = &ws[(k4 * 4 + kk) * N + c0];
                float4 w0 = *(const float4*)&wrow[0];
                float4 w1 = *(const float4*)&wrow[4];
                unsigned long long b0 = pk2(w0.x, w0.y), b1 = pk2(w0.z, w0.w);
                unsigned long long b2 = pk2(w1.x, w1.y), b3 = pk2(w1.z, w1.w);
#pragma unroll
                for (int r = 0; r < RPT; r++) {
                    float a = (kk == 0) ? av[r].x
                            : (kk == 1) ? av[r].y
                            : (kk == 2) ? av[r].z
                                        : av[r].w;
                    unsigned long long a2 = pk2(a, a);
                    fma2(acc[r][0], a2, b0);
                    fma2(acc[r][1], a2, b1);
                    fma2(acc[r][2], a2, b2);
                    fma2(acc[r][3], a2, b3);
                }
            }
        }
    }
#pragma unroll
    for (int r = 0; r < RPT; r++) {
#pragma unroll
        for (int p = 0; p < 4; p++) {
            float lo, hi;
            upk2(acc[r][p], lo, hi);
            int c = c0 + p * 2;
            if (bias) {
                float2 bb = *(const float2*)&bias[c];
                lo += bb.x;
                hi += bb.y;
            }
            if (ACT) {
                lo = silu_f(lo);
                hi = silu_f(hi);
            }
            float2 o;
            o.x = lo;
            o.y = hi;
            *(float2*)&out[(r0 + r) * N + c] = o;
        }
    }
    __syncthreads();
}

// ---------------------------------------------------------------------------
__global__ void zero_kernel() {
    int idx = blockIdx.x * 256 + threadIdx.x;
    if (idx < NN * 256) g_mi[idx] = 0.f;
    if (idx < NN * 24) g_shift[idx] = 0.f;
}

// hc[n] = [h[n] (128) | per-head-pair sq dists (64)]
__global__ void prep_hc(const float* __restrict__ x, const float* __restrict__ h) {
    int n = blockIdx.x, t = threadIdx.x;
    if (t < 128) {
        g_hc[n * 192 + t] = h[n * 128 + t];
    } else {
        int p = t - 128;
        int a = p >> 3, b = p & 7;
        float dx = x[n * 24 + a * 3 + 0] - x[n * 24 + b * 3 + 0];
        float dy = x[n * 24 + a * 3 + 1] - x[n * 24 + b * 3 + 1];
        float dz = x[n * 24 + a * 3 + 2] - x[n * 24 + b * 3 + 2];
        g_hc[n * 192 + 128 + p] = dx * dx + dy * dy + dz * dz;
    }
}

// A = hc @ We0[8:200], B = hc @ We0[200:392]   (grid: 8 row tiles x 2)
__global__ void __launch_bounds__(256) prep_ab(const float* __restrict__ We0) {
    extern __shared__ float sm[];
    float* sIn = sm;              // 64*192
    float* ws = sm + 64 * 192;    // 32*256
    int r0g = blockIdx.x * 64, t = threadIdx.x;
    for (int idx = t; idx < 64 * 192 / 4; idx += 256)
        *(float4*)&sIn[idx * 4] = *(const float4*)&g_hc[r0g * 192 + idx * 4];
    __syncthreads();
    const float* Wg = We0 + (blockIdx.y == 0 ? 8 : 200) * 256;
    float* outp = (blockIdx.y == 0 ? g_A : g_B) + r0g * 256;
    gemm64<256, false>(sIn, 192, Wg, nullptr, outp, ws);
}

// ---------------------------------------------------------------------------
// Fused edge kernel: one CTA = receiver i x 64 senders j.
__global__ void __launch_bounds__(256) edge_kernel(
    const float* __restrict__ x,
    const float* __restrict__ We0, const float* __restrict__ be0,
    const float* __restrict__ We1, const float* __restrict__ be1,
    const float* __restrict__ Winf, const float* __restrict__ binf,
    const float* __restrict__ Wx0, const float* __restrict__ bx0,
    const float* __restrict__ Wx1, const float* __restrict__ bx1,
    const float* __restrict__ Wxo, const float* __restrict__ bxo) {
    extern __shared__ float sm[];
    float* sA = sm;                 // 16384
    float* sB = sA + 16384;         // 16384
    float* sW = sB + 16384;         // 8192 (GEMM weight staging)
    float* sAux = sW + 8192;        // 2048 (We0[0:8] then Wxo^T)
    float* sXj = sAux + 2048;       // 1536
    float* sXi = sXj + 1536;        // 24
    float* sSqn = sXi + 24;         // 512
    float* sBC = sSqn + 512;        // 256 (B[i]+be0, then Winf)
    float* sE = sBC + 256;          // 64
    float* sPx = sE + 64;           // 512
    float* sSh = sPx + 512;         // 24

    const int i = blockIdx.y;
    const int j0 = blockIdx.x * TJ;
    const int t = threadIdx.x;

    for (int idx = t; idx < TJ * 24; idx += 256) sXj[idx] = x[j0 * 24 + idx];
    if (t < 24) sXi[t] = x[i * 24 + t];
    for (int idx = t; idx < 2048; idx += 256) sAux[idx] = We0[idx];  // rows 0..7
    sBC[t] = g_B[i * 256 + t] + be0[t];
    __syncthreads();

    // per-edge head distances sqn[j][hh]
    for (int p = t; p < 512; p += 256) {
        int j = p >> 3, hh = p & 7;
        float dx = sXj[j * 24 + hh * 3 + 0] - sXi[hh * 3 + 0];
        float dy = sXj[j * 24 + hh * 3 + 1] - sXi[hh * 3 + 1];
        float dz = sXj[j * 24 + hh * 3 + 2] - sXi[hh * 3 + 2];
        sSqn[p] = dx * dx + dy * dy + dz * dz;
    }
    __syncthreads();

    // t0 = silu(A[j] + (B[i]+be0) + sqn @ We0[0:8])
    for (int it = 0; it < 16; ++it) {
        int idx = it * 256 + t;
        int j = idx >> 6;
        int c = (idx & 63) * 4;
        float4 v = *(const float4*)&g_A[(j0 + j) * 256 + c];
        v.x += sBC[c]; v.y += sBC[c + 1]; v.z += sBC[c + 2]; v.w += sBC[c + 3];
#pragma unroll
        for (int q = 0; q < 8; q++) {
            float s = sSqn[j * 8 + q];
            float4 w = *(const float4*)&sAux[q * 256 + c];
            v.x += s * w.x; v.y += s * w.y; v.z += s * w.z; v.w += s * w.w;
        }
        v.x = silu_f(v.x); v.y = silu_f(v.y); v.z = silu_f(v.z); v.w = silu_f(v.w);
        *(float4*)&sA[j * 256 + c] = v;
    }
    __syncthreads();

    // m = silu(t0 @ We1 + be1)
    gemm64<256, true>(sA, 256, We1, be1, sB, sW);

    // stage Winf into sBC, Wxo^T into sAux
    for (int idx = t; idx < 2048; idx += 256) {
        int c = idx >> 3, hh = idx & 7;
        sAux[hh * 256 + c] = Wxo[idx];
    }
    sBC[t] = Winf[t];
    __syncthreads();

    // e[j] = sigmoid(m @ Winf + binf), masked at j==i
    {
        int row = t >> 2, l4 = t & 3;
        float s = 0.f;
        for (int c = l4 * 64; c < l4 * 64 + 64; ++c) s += sB[row * 256 + c] * sBC[c];
        s += __shfl_xor_sync(0xffffffffu, s, 1);
        s += __shfl_xor_sync(0xffffffffu, s, 2);
        if (l4 == 0) {
            float ee = 1.0f / (1.0f + __expf(-(s + binf[0])));
            if (j0 + row == i) ee = 0.f;
            sE[row] = ee;
        }
    }
    __syncthreads();

    // m_i partial: sum_j m[j][c]*e[j]
    {
        float acc = 0.f;
#pragma unroll 8
        for (int j = 0; j < TJ; j++) acc += sB[j * 256 + t] * sE[j];
        atomicAdd(&g_mi[i * 256 + t], acc);
    }

    // phi_x hidden layers
    gemm64<256, true>(sB, 256, Wx0, bx0, sA, sW);
    gemm64<256, true>(sA, 256, Wx1, bx1, sB, sW);

    // px[j][hh] = u2 @ Wxo + bxo
    for (int p = t; p < 512; p += 256) {
        int row = p >> 3, hh = p & 7;
        float s = bxo[hh];
        const float* br = &sB[row * 256];
        const float* wr2 = &sAux[hh * 256];
#pragma unroll 16
        for (int c = 0; c < 256; c += 4) {
            float4 b4 = *(const float4*)&br[c];
            float4 w4 = *(const float4*)&wr2[c];
            s += b4.x * w4.x + b4.y * w4.y + b4.z * w4.z + b4.w * w4.w;
        }
        sPx[p] = s;
    }
    if (t < 24) sSh[t] = 0.f;
    __syncthreads();

    // shift partial: sum_j px/(sqrt(sqn)+1) * (x[j]-x[i])
    for (int p = t; p < 512; p += 256) {
        int row = p >> 3, hh = p & 7;
        float nrm = sqrtf(sSqn[p] + 1e-8f) + 1.0f;
        float w = sPx[p] / nrm;
#pragma unroll
        for (int d = 0; d < 3; ++d) {
            float dn = sXj[row * 24 + hh * 3 + d] - sXi[hh * 3 + d];
            atomicAdd(&sSh[hh * 3 + d], w * dn);
        }
    }
    __syncthreads();
    if (t < 24) atomicAdd(&g_shift[i * 24 + t], sSh[t]);
}

// ---------------------------------------------------------------------------
// h_new = h + MLP([m_i, h])
__global__ void __launch_bounds__(256) hnew_kernel(
    const float* __restrict__ h,
    const float* __restrict__ Wh0, const float* __restrict__ bh0,
    const float* __restrict__ Wh1, const float* __restrict__ bh1,
    const float* __restrict__ Who, const float* __restrict__ bho,
    float* __restrict__ out) {
    extern __shared__ float sm[];
    float* buf0 = sm;                 // 64*384
    float* buf1 = buf0 + 64 * 384;    // 64*256
    float* ws = buf1 + 64 * 256;      // 32*256
    int r0g = blockIdx.x * 64, t = threadIdx.x;
    for (int idx = t; idx < 64 * 384; idx += 256) {
        int row = idx / 384, c = idx - row * 384;
        buf0[idx] = (c < 256) ? g_mi[(r0g + row) * 256 + c]
                              : h[(r0g + row) * 128 + (c - 256)];
    }
    __syncthreads();
    gemm64<256, true>(buf0, 384, Wh0, bh0, buf1, ws);
    gemm64<256, true>(buf1, 256, Wh1, bh1, buf0, ws);
    gemm64<128, false>(buf0, 256, Who, bho, buf1, ws);
    for (int idx = t; idx < 64 * 128; idx += 256)
        out[r0g * 128 + idx] = buf1[idx] + h[r0g * 128 + idx];
}

__global__ void xnew_kernel(const float* __restrict__ x, float* __restrict__ out) {
    int idx = blockIdx.x * 256 + threadIdx.x;
    if (idx < NN * 24) out[idx] = x[idx] + g_shift[idx] * (1.0f / 511.0f);
}

// ---------------------------------------------------------------------------
extern "C" void kernel_launch(void* const* d_in, const int* in_sizes, int n_in,
                              void* d_out, int out_size) {
    const float* x = (const float*)d_in[0];
    const float* h = (const float*)d_in[1];
    const float* We0 = (const float*)d_in[2];
    const float* be0 = (const float*)d_in[3];
    const float* We1 = (const float*)d_in[4];
    const float* be1 = (const float*)d_in[5];
    const float* Winf = (const float*)d_in[6];
    const float* binf = (const float*)d_in[7];
    const float* Wx0 = (const float*)d_in[8];
    const float* bx0 = (const float*)d_in[9];
    const float* Wx1 = (const float*)d_in[10];
    const float* bx1 = (const float*)d_in[11];
    const float* Wxo = (const float*)d_in[12];
    const float* bxo = (const float*)d_in[13];
    const float* Wh0 = (const float*)d_in[14];
    const float* bh0 = (const float*)d_in[15];
    const float* Wh1 = (const float*)d_in[16];
    const float* bh1 = (const float*)d_in[17];
    const float* Who = (const float*)d_in[18];
    const float* bho = (const float*)d_in[19];
    float* out = (float*)d_out;  // [x_new (512*8*3) | h_new (512*128)]

    const int EDGE_SMEM = 45936 * 4;
    const int AB_SMEM = (64 * 192 + 32 * 256) * 4;
    const int HNEW_SMEM = (64 * 384 + 64 * 256 + 32 * 256) * 4;
    cudaFuncSetAttribute(edge_kernel, cudaFuncAttributeMaxDynamicSharedMemorySize,
                         EDGE_SMEM);
    cudaFuncSetAttribute(prep_ab, cudaFuncAttributeMaxDynamicSharedMemorySize,
                         AB_SMEM);
    cudaFuncSetAttribute(hnew_kernel, cudaFuncAttributeMaxDynamicSharedMemorySize,
                         HNEW_SMEM);

    zero_kernel<<<512, 256>>>();
    prep_hc<<<NN, 192>>>(x, h);
    prep_ab<<<dim3(8, 2), 256, AB_SMEM>>>(We0);
    edge_kernel<<<dim3(8, NN), 256, EDGE_SMEM>>>(x, We0, be0, We1, be1, Winf, binf,
                                                 Wx0, bx0, Wx1, bx1, Wxo, bxo);
    hnew_kernel<<<8, 256, HNEW_SMEM>>>(h, Wh0, bh0, Wh1, bh1, Who, bho,
                                       out + NN * 24);
    xnew_kernel<<<48, 256>>>(x, out);
}

// round 4
// speedup vs baseline: 1.9893x; 1.9869x over previous
#include <cuda_runtime.h>
#include <cuda_fp16.h>

// EGCL_Multi via mma.sync.m16n8k16 fp16 split hi/lo (3-product) — sm_103.
#define NN 512

__device__ __align__(16) float g_hc[NN * 192];
__device__ __align__(16) float g_A[NN * 256];
__device__ __align__(16) float g_B[NN * 256];
__device__ __align__(16) float g_mi[NN * 256];
__device__ __align__(16) float g_shift[NN * 24];
__device__ __align__(16) __half g_Whi[3][256 * 256];  // [n][k]
__device__ __align__(16) __half g_Wlo[3][256 * 256];

// ---------------- small helpers ----------------
__device__ __forceinline__ float silu_f(float v) {
    return v * (1.0f / (1.0f + __expf(-v)));
}
__device__ __forceinline__ unsigned smem_u32(const void* p) {
    unsigned a;
    asm("{ .reg .u64 t; cvta.to.shared.u64 t, %1; cvt.u32.u64 %0, t; }"
        : "=r"(a) : "l"(p));
    return a;
}
__device__ __forceinline__ unsigned lds32(unsigned addr) {
    unsigned v;
    asm volatile("ld.shared.b32 %0, [%1];" : "=r"(v) : "r"(addr));
    return v;
}
__device__ __forceinline__ void sts32(unsigned addr, unsigned v) {
    asm volatile("st.shared.b32 [%0], %1;" :: "r"(addr), "r"(v) : "memory");
}
__device__ __forceinline__ void cp16(unsigned dst, const void* src) {
    asm volatile("cp.async.ca.shared.global [%0], [%1], 16;"
                 :: "r"(dst), "l"(src) : "memory");
}
__device__ __forceinline__ void hsplit2(float a, float b, unsigned& hp, unsigned& lp) {
    __half2 h = __floats2half2_rn(a, b);
    float2 r = __half22float2(h);
    __half2 l = __floats2half2_rn(a - r.x, b - r.y);
    hp = *(unsigned*)&h;
    lp = *(unsigned*)&l;
}
__device__ __forceinline__ void mma16816(float* d, const unsigned* a, unsigned b0,
                                         unsigned b1) {
    asm volatile(
        "mma.sync.aligned.m16n8k16.row.col.f32.f16.f16.f32 "
        "{%0,%1,%2,%3}, {%4,%5,%6,%7}, {%8,%9}, {%0,%1,%2,%3};"
        : "+f"(d[0]), "+f"(d[1]), "+f"(d[2]), "+f"(d[3])
        : "r"(a[0]), "r"(a[1]), "r"(a[2]), "r"(a[3]), "r"(b0), "r"(b1));
}

// ---------------- f32x2 SIMT gemm (node-side) ----------------
__device__ __forceinline__ unsigned long long pk2(float lo, float hi) {
    unsigned long long r;
    asm("mov.b64 %0, {%1, %2};" : "=l"(r) : "f"(lo), "f"(hi));
    return r;
}
__device__ __forceinline__ void upk2(unsigned long long v, float& lo, float& hi) {
    asm("mov.b64 {%0, %1}, %2;" : "=f"(lo), "=f"(hi) : "l"(v));
}
__device__ __forceinline__ void fma2(unsigned long long& d, unsigned long long a,
                                     unsigned long long b) {
    asm("fma.rn.f32x2 %0, %1, %2, %0;" : "+l"(d) : "l"(a), "l"(b));
}
template <int N, bool ACT>
__device__ __forceinline__ void gemm64(const float* sIn, int K,
                                       const float* __restrict__ Wg,
                                       const float* __restrict__ bias, float* out,
                                       float* ws) {
    constexpr int COLG = N / 8;
    constexpr int RPT = COLG / 4;
    const int t = threadIdx.x;
    const int nc = t % COLG, mr = t / COLG;
    const int r0 = mr * RPT, c0 = nc * 8;
    unsigned long long acc[RPT][4];
#pragma unroll
    for (int r = 0; r < RPT; r++)
#pragma unroll
        for (int p = 0; p < 4; p++) acc[r][p] = 0ULL;
    for (int kt = 0; kt < K; kt += 32) {
        __syncthreads();
        for (int idx = t; idx < 32 * N / 4; idx += 256) {
            int wr = idx / (N / 4), wc = (idx - wr * (N / 4)) * 4;
            *(float4*)&ws[wr * N + wc] = *(const float4*)&Wg[(kt + wr) * N + wc];
        }
        __syncthreads();
#pragma unroll
        for (int k4 = 0; k4 < 8; k4++) {
            float4 av[RPT];
#pragma unroll
            for (int r = 0; r < RPT; r++)
                av[r] = *(const float4*)&sIn[(r0 + r) * K + kt + k4 * 4];
#pragma unroll
            for (int kk = 0; kk < 4; kk++) {
                const float* wr_ = &ws[(k4 * 4 + kk) * N + c0];
                float4 w0 = *(const float4*)&wr_[0];
                float4 w1 = *(const float4*)&wr_[4];
                unsigned long long b0 = pk2(w0.x, w0.y), b1 = pk2(w0.z, w0.w);
                unsigned long long b2 = pk2(w1.x, w1.y), b3 = pk2(w1.z, w1.w);
#pragma unroll
                for (int r = 0; r < RPT; r++) {
                    float a = (kk == 0) ? av[r].x : (kk == 1) ? av[r].y
                            : (kk == 2) ? av[r].z : av[r].w;
                    unsigned long long a2 = pk2(a, a);
                    fma2(acc[r][0], a2, b0);
                    fma2(acc[r][1], a2, b1);
                    fma2(acc[r][2], a2, b2);
                    fma2(acc[r][3], a2, b3);
                }
            }
        }
    }
#pragma unroll
    for (int r = 0; r < RPT; r++)
#pragma unroll
        for (int p = 0; p < 4; p++) {
            float lo, hi;
            upk2(acc[r][p], lo, hi);
            int c = c0 + p * 2;
            if (bias) {
                float2 bb = *(const float2*)&bias[c];
                lo += bb.x;
                hi += bb.y;
            }
            if (ACT) { lo = silu_f(lo); hi = silu_f(hi); }
            float2 o; o.x = lo; o.y = hi;
            *(float2*)&out[(r0 + r) * N + c] = o;
        }
    __syncthreads();
}

// ---------------- prep kernels ----------------
__global__ void zero_kernel() {
    int idx = blockIdx.x * 256 + threadIdx.x;
    if (idx < NN * 256) g_mi[idx] = 0.f;
    if (idx < NN * 24) g_shift[idx] = 0.f;
}
__global__ void prep_hc(const float* __restrict__ x, const float* __restrict__ h) {
    int n = blockIdx.x, t = threadIdx.x;
    if (t < 128) g_hc[n * 192 + t] = h[n * 128 + t];
    else {
        int p = t - 128, a = p >> 3, b = p & 7;
        float dx = x[n * 24 + a * 3] - x[n * 24 + b * 3];
        float dy = x[n * 24 + a * 3 + 1] - x[n * 24 + b * 3 + 1];
        float dz = x[n * 24 + a * 3 + 2] - x[n * 24 + b * 3 + 2];
        g_hc[n * 192 + 128 + p] = dx * dx + dy * dy + dz * dz;
    }
}
// transpose + fp16 hi/lo split: g_W*[sel][n*256+k] = split(W[k*256+n])
__global__ void prep_w(const float* __restrict__ We1, const float* __restrict__ Wx0,
                       const float* __restrict__ Wx1) {
    __shared__ float tile[32][33];
    int sel = blockIdx.z;
    const float* W = (sel == 0) ? We1 : (sel == 1) ? Wx0 : Wx1;
    int n0 = blockIdx.x * 32, k0 = blockIdx.y * 32;
    int tx = threadIdx.x, ty = threadIdx.y;
    for (int r = ty; r < 32; r += 8) tile[r][tx] = W[(k0 + r) * 256 + n0 + tx];
    __syncthreads();
    for (int r = ty; r < 32; r += 8) {
        float v = tile[tx][r];
        __half hb = __float2half_rn(v);
        g_Whi[sel][(n0 + r) * 256 + k0 + tx] = hb;
        g_Wlo[sel][(n0 + r) * 256 + k0 + tx] =
            __float2half_rn(v - __half2float(hb));
    }
}
__global__ void __launch_bounds__(256) prep_ab(const float* __restrict__ We0) {
    extern __shared__ float sm[];
    float* sIn = sm;
    float* ws = sm + 64 * 192;
    int r0g = blockIdx.x * 64, t = threadIdx.x;
    for (int idx = t; idx < 64 * 192 / 4; idx += 256)
        *(float4*)&sIn[idx * 4] = *(const float4*)&g_hc[r0g * 192 + idx * 4];
    __syncthreads();
    const float* Wg = We0 + (blockIdx.y == 0 ? 8 : 200) * 256;
    float* outp = (blockIdx.y == 0 ? g_A : g_B) + r0g * 256;
    gemm64<256, false>(sIn, 192, Wg, nullptr, outp, ws);
}

// ---------------- edge kernel ----------------
// smem byte offsets
#define OFF_A_HI 0       // 33792  (64 rows x 264 halves)
#define OFF_A_LO 33792   // 33792
#define OFF_W 67584      // 131072 (2 bufs x (hi 32768 + lo 32768))
#define OFF_AUX 198656   // 8192   (We0 rows 0..7 f32; later Wxo [256][8] f32)
#define OFF_XJ 206848    // 6144
#define OFF_SQN 212992   // 2048
#define OFF_BI 215040    // 1024
#define OFF_WINF 216064  // 1024
#define OFF_BIAS 217088  // 3072
#define OFF_PE 220160    // 256
#define OFF_E 220416     // 256
#define OFF_PX 220672    // 2048
#define OFF_XI 222720    // 96
#define OFF_SH 222816    // 96
#define EDGE_SMEM 222912

__global__ void __launch_bounds__(256, 1) edge_kernel(
    const float* __restrict__ x, const float* __restrict__ We0,
    const float* __restrict__ be0, const float* __restrict__ be1,
    const float* __restrict__ Winf, const float* __restrict__ binf,
    const float* __restrict__ bx0, const float* __restrict__ bx1,
    const float* __restrict__ bxo, const float* __restrict__ Wxo) {
    extern __shared__ char smc[];
    const unsigned sb = smem_u32(smc);
    const int t = threadIdx.x;
    const int lane = t & 31, w = t >> 5;
    const int band = w >> 1, ng = w & 1;
    const int r0 = band * 16 + (lane >> 2);
    const int k4 = lane & 3;
    const unsigned bswz = (unsigned)((lane >> 2) << 4);
    const int i = blockIdx.y, j0 = blockIdx.x * 64;

    float* sAux = (float*)(smc + OFF_AUX);
    float* sXj = (float*)(smc + OFF_XJ);
    float* sSqn = (float*)(smc + OFF_SQN);
    float* sBi = (float*)(smc + OFF_BI);
    float* sWinf = (float*)(smc + OFF_WINF);
    float* sBias = (float*)(smc + OFF_BIAS);
    float* sPE = (float*)(smc + OFF_PE);
    float* sE = (float*)(smc + OFF_E);
    float* sPx = (float*)(smc + OFF_PX);
    float* sXi = (float*)(smc + OFF_XI);
    float* sSh = (float*)(smc + OFF_SH);

    // prologue staging
    for (int idx = t; idx < 2048; idx += 256) sAux[idx] = We0[idx];
    for (int idx = t; idx < 1536; idx += 256) sXj[idx] = x[j0 * 24 + idx];
    sBi[t] = g_B[i * 256 + t] + be0[t];
    sWinf[t] = Winf[t];
    sBias[t] = be1[t];
    sBias[256 + t] = bx0[t];
    sBias[512 + t] = bx1[t];
    if (t < 64) sPE[t] = 0.f;
    for (int p = t; p < 512; p += 256) sPx[p] = 0.f;
    if (t < 24) { sXi[t] = x[i * 24 + t]; sSh[t] = 0.f; }
    __syncthreads();

    // sqn
    for (int p = t; p < 512; p += 256) {
        int j = p >> 3, hh = p & 7;
        float dx = sXj[j * 24 + hh * 3] - sXi[hh * 3];
        float dy = sXj[j * 24 + hh * 3 + 1] - sXi[hh * 3 + 1];
        float dz = sXj[j * 24 + hh * 3 + 2] - sXi[hh * 3 + 2];
        sSqn[p] = dx * dx + dy * dy + dz * dz;
    }
    __syncthreads();

    // T0 = silu(A[j] + (B[i]+be0) + sqn@We0[0:8]) -> split planes
    for (int it = 0; it < 16; ++it) {
        int idx = it * 256 + t;
        int j = idx >> 6, c = (idx & 63) * 4;
        float4 v = *(const float4*)&g_A[(j0 + j) * 256 + c];
        v.x += sBi[c]; v.y += sBi[c + 1]; v.z += sBi[c + 2]; v.w += sBi[c + 3];
#pragma unroll
        for (int q = 0; q < 8; q++) {
            float s = sSqn[j * 8 + q];
            float4 ww = *(const float4*)&sAux[q * 256 + c];
            v.x += s * ww.x; v.y += s * ww.y; v.z += s * ww.z; v.w += s * ww.w;
        }
        v.x = silu_f(v.x); v.y = silu_f(v.y); v.z = silu_f(v.z); v.w = silu_f(v.w);
        unsigned hp0, lp0, hp1, lp1;
        hsplit2(v.x, v.y, hp0, lp0);
        hsplit2(v.z, v.w, hp1, lp1);
        unsigned off = (unsigned)(j * 528 + c * 2);
        sts32(sb + OFF_A_HI + off, hp0);
        sts32(sb + OFF_A_HI + off + 4, hp1);
        sts32(sb + OFF_A_LO + off, lp0);
        sts32(sb + OFF_A_LO + off + 4, lp1);
    }

    // stage chunk 0
    {
        const __half* gh = g_Whi[0];
        const __half* gl = g_Wlo[0];
        for (int it = 0; it < 16; ++it) {
            int idx = it * 256 + t;
            int plane = idx >> 11, rem = idx & 2047, n = rem >> 3, u = rem & 7;
            const __half* src = (plane ? gl : gh) + n * 256 + u * 8;
            unsigned dst = sb + OFF_W + (unsigned)(plane * 32768 + n * 128 +
                                                   ((u * 16) ^ ((n & 7) << 4)));
            cp16(dst, src);
        }
        asm volatile("cp.async.commit_group;" ::: "memory");
    }

    const float binf0 = binf[0];

    for (int l = 0; l < 3; ++l) {
        float acc[16][4];
#pragma unroll
        for (int s2 = 0; s2 < 16; ++s2)
#pragma unroll
            for (int q = 0; q < 4; ++q) acc[s2][q] = 0.f;

        for (int c = 0; c < 4; ++c) {
            int g = l * 4 + c;
            if (g + 1 < 12) {
                int gl_ = (g + 1) >> 2, gc = (g + 1) & 3, gb = (g + 1) & 1;
                const __half* gh = g_Whi[gl_];
                const __half* glo = g_Wlo[gl_];
                for (int it = 0; it < 16; ++it) {
                    int idx = it * 256 + t;
                    int plane = idx >> 11, rem = idx & 2047, n = rem >> 3, u = rem & 7;
                    const __half* src = (plane ? glo : gh) + n * 256 + gc * 64 + u * 8;
                    unsigned dst =
                        sb + OFF_W + (unsigned)(gb * 65536 + plane * 32768 + n * 128 +
                                                ((u * 16) ^ ((n & 7) << 4)));
                    cp16(dst, src);
                }
                asm volatile("cp.async.commit_group;" ::: "memory");
                asm volatile("cp.async.wait_group 1;" ::: "memory");
            } else {
                asm volatile("cp.async.wait_group 0;" ::: "memory");
            }
            __syncthreads();
            const unsigned wb = sb + OFF_W + (unsigned)((g & 1) * 65536);
#pragma unroll
            for (int ks = 0; ks < 4; ++ks) {
                const int khb = c * 128 + ks * 32;
                unsigned ah[4], al[4];
                unsigned a0 = sb + OFF_A_HI + (unsigned)(r0 * 528 + khb + k4 * 4);
                ah[0] = lds32(a0);
                ah[1] = lds32(a0 + 8 * 528);
                ah[2] = lds32(a0 + 16);
                ah[3] = lds32(a0 + 8 * 528 + 16);
                unsigned a1 = a0 + (OFF_A_LO - OFF_A_HI);
                al[0] = lds32(a1);
                al[1] = lds32(a1 + 8 * 528);
                al[2] = lds32(a1 + 16);
                al[3] = lds32(a1 + 8 * 528 + 16);
#pragma unroll
                for (int sub = 0; sub < 16; ++sub) {
                    unsigned nrow = (unsigned)(ng * 128 + sub * 8 + (lane >> 2));
                    unsigned rb = wb + nrow * 128;
                    unsigned o0 = ((unsigned)(ks * 32 + k4 * 4)) ^ bswz;
                    unsigned o1 = ((unsigned)(ks * 32 + k4 * 4 + 16)) ^ bswz;
                    unsigned bh0 = lds32(rb + o0), bh1 = lds32(rb + o1);
                    unsigned bl0 = lds32(rb + 32768 + o0), bl1 = lds32(rb + 32768 + o1);
                    mma16816(acc[sub], ah, bh0, bh1);
                    mma16816(acc[sub], ah, bl0, bl1);
                    mma16816(acc[sub], al, bh0, bh1);
                }
            }
            __syncthreads();
        }

        // ---------------- epilogues ----------------
        if (l < 2) {
            float pe0 = 0.f, pe1 = 0.f;
#pragma unroll
            for (int sub = 0; sub < 16; ++sub) {
                int col = ng * 128 + sub * 8 + k4 * 2;
                float v0 = silu_f(acc[sub][0] + sBias[l * 256 + col]);
                float v1 = silu_f(acc[sub][1] + sBias[l * 256 + col + 1]);
                float v2 = silu_f(acc[sub][2] + sBias[l * 256 + col]);
                float v3 = silu_f(acc[sub][3] + sBias[l * 256 + col + 1]);
                if (l == 0) {
                    pe0 += v0 * sWinf[col] + v1 * sWinf[col + 1];
                    pe1 += v2 * sWinf[col] + v3 * sWinf[col + 1];
                }
                unsigned hp, lp;
                hsplit2(v0, v1, hp, lp);
                unsigned off = (unsigned)(r0 * 528 + col * 2);
                sts32(sb + OFF_A_HI + off, hp);
                sts32(sb + OFF_A_LO + off, lp);
                hsplit2(v2, v3, hp, lp);
                off += 8 * 528;
                sts32(sb + OFF_A_HI + off, hp);
                sts32(sb + OFF_A_LO + off, lp);
            }
            if (l == 0) {
                pe0 += __shfl_xor_sync(0xffffffffu, pe0, 1);
                pe0 += __shfl_xor_sync(0xffffffffu, pe0, 2);
                pe1 += __shfl_xor_sync(0xffffffffu, pe1, 1);
                pe1 += __shfl_xor_sync(0xffffffffu, pe1, 2);
                if (k4 == 0) {
                    atomicAdd(&sPE[r0], pe0);
                    atomicAdd(&sPE[r0 + 8], pe1);
                }
                __syncthreads();
                if (t < 64) {
                    float z = sPE[t] + binf0;
                    float e = 1.0f / (1.0f + __expf(-z));
                    if (j0 + t == i) e = 0.f;
                    sE[t] = e;
                }
                // stage Wxo into sAux (We0 no longer needed)
                for (int idx = t; idx < 2048; idx += 256) sAux[idx] = Wxo[idx];
                __syncthreads();
                // m_i column sums
                {
                    const __half* mh = (const __half*)(smc + OFF_A_HI);
                    const __half* ml = (const __half*)(smc + OFF_A_LO);
                    float a_ = 0.f;
#pragma unroll 4
                    for (int j = 0; j < 64; ++j)
                        a_ += (__half2float(mh[j * 264 + t]) +
                               __half2float(ml[j * 264 + t])) * sE[j];
                    atomicAdd(&g_mi[i * 256 + t], a_);
                }
            }
        } else {
            float pxa0[8], pxa1[8];
#pragma unroll
            for (int hh = 0; hh < 8; ++hh) { pxa0[hh] = 0.f; pxa1[hh] = 0.f; }
#pragma unroll
            for (int sub = 0; sub < 16; ++sub) {
                int col = ng * 128 + sub * 8 + k4 * 2;
                float v0 = silu_f(acc[sub][0] + sBias[512 + col]);
                float v1 = silu_f(acc[sub][1] + sBias[512 + col + 1]);
                float v2 = silu_f(acc[sub][2] + sBias[512 + col]);
                float v3 = silu_f(acc[sub][3] + sBias[512 + col + 1]);
                const float* w0 = &sAux[col * 8];
                const float* w1 = &sAux[(col + 1) * 8];
#pragma unroll
                for (int hh = 0; hh < 8; ++hh) {
                    pxa0[hh] += v0 * w0[hh] + v1 * w1[hh];
                    pxa1[hh] += v2 * w0[hh] + v3 * w1[hh];
                }
            }
#pragma unroll
            for (int hh = 0; hh < 8; ++hh) {
                pxa0[hh] += __shfl_xor_sync(0xffffffffu, pxa0[hh], 1);
                pxa0[hh] += __shfl_xor_sync(0xffffffffu, pxa0[hh], 2);
                pxa1[hh] += __shfl_xor_sync(0xffffffffu, pxa1[hh], 1);
                pxa1[hh] += __shfl_xor_sync(0xffffffffu, pxa1[hh], 2);
            }
            if (k4 == 0) {
#pragma unroll
                for (int hh = 0; hh < 8; ++hh) {
                    atomicAdd(&sPx[r0 * 8 + hh], pxa0[hh]);
                    atomicAdd(&sPx[(r0 + 8) * 8 + hh], pxa1[hh]);
                }
            }
            __syncthreads();
            for (int p = t; p < 512; p += 256) {
                int j = p >> 3, hh = p & 7;
                float px = sPx[p] + bxo[hh];
                if (j0 + j == i) px = 0.f;
                float nrm = sqrtf(sSqn[p] + 1e-8f) + 1.0f;
                float wgt = px / nrm;
#pragma unroll
                for (int d = 0; d < 3; ++d)
                    atomicAdd(&sSh[hh * 3 + d],
                              wgt * (sXj[j * 24 + hh * 3 + d] - sXi[hh * 3 + d]));
            }
            __syncthreads();
            if (t < 24) atomicAdd(&g_shift[i * 24 + t], sSh[t]);
        }
    }
}

// ---------------- node kernels ----------------
__global__ void __launch_bounds__(256) hnew_kernel(
    const float* __restrict__ h, const float* __restrict__ Wh0,
    const float* __restrict__ bh0, const float* __restrict__ Wh1,
    const float* __restrict__ bh1, const float* __restrict__ Who,
    const float* __restrict__ bho, float* __restrict__ out) {
    extern __shared__ float sm[];
    float* buf0 = sm;                 // 64*384
    float* buf1 = buf0 + 64 * 384;    // 64*256
    float* ws = buf1 + 64 * 256;      // 32*256
    int r0g = blockIdx.x * 64, t = threadIdx.x;
    for (int idx = t; idx < 64 * 384; idx += 256) {
        int row = idx / 384, c = idx - row * 384;
        buf0[idx] = (c < 256) ? g_mi[(r0g + row) * 256 + c]
                              : h[(r0g + row) * 128 + (c - 256)];
    }
    __syncthreads();
    gemm64<256, true>(buf0, 384, Wh0, bh0, buf1, ws);
    gemm64<256, true>(buf1, 256, Wh1, bh1, buf0, ws);
    gemm64<128, false>(buf0, 256, Who, bho, buf1, ws);
    for (int idx = t; idx < 64 * 128; idx += 256)
        out[r0g * 128 + idx] = buf1[idx] + h[r0g * 128 + idx];
}
__global__ void xnew_kernel(const float* __restrict__ x, float* __restrict__ out) {
    int idx = blockIdx.x * 256 + threadIdx.x;
    if (idx < NN * 24) out[idx] = x[idx] + g_shift[idx] * (1.0f / 511.0f);
}

// ---------------- launch ----------------
extern "C" void kernel_launch(void* const* d_in, const int* in_sizes, int n_in,
                              void* d_out, int out_size) {
    const float* x = (const float*)d_in[0];
    const float* h = (const float*)d_in[1];
    const float* We0 = (const float*)d_in[2];
    const float* be0 = (const float*)d_in[3];
    const float* We1 = (const float*)d_in[4];
    const float* be1 = (const float*)d_in[5];
    const float* Winf = (const float*)d_in[6];
    const float* binf = (const float*)d_in[7];
    const float* Wx0 = (const float*)d_in[8];
    const float* bx0 = (const float*)d_in[9];
    const float* Wx1 = (const float*)d_in[10];
    const float* bx1 = (const float*)d_in[11];
    const float* Wxo = (const float*)d_in[12];
    const float* bxo = (const float*)d_in[13];
    const float* Wh0 = (const float*)d_in[14];
    const float* bh0 = (const float*)d_in[15];
    const float* Wh1 = (const float*)d_in[16];
    const float* bh1 = (const float*)d_in[17];
    const float* Who = (const float*)d_in[18];
    const float* bho = (const float*)d_in[19];
    float* out = (float*)d_out;  // [x_new (512*24) | h_new (512*128)]

    const int AB_SMEM = (64 * 192 + 32 * 256) * 4;
    const int HNEW_SMEM = (64 * 384 + 64 * 256 + 32 * 256) * 4;
    cudaFuncSetAttribute(edge_kernel, cudaFuncAttributeMaxDynamicSharedMemorySize,
                         EDGE_SMEM);
    cudaFuncSetAttribute(prep_ab, cudaFuncAttributeMaxDynamicSharedMemorySize, AB_SMEM);
    cudaFuncSetAttribute(hnew_kernel, cudaFuncAttributeMaxDynamicSharedMemorySize,
                         HNEW_SMEM);

    zero_kernel<<<512, 256>>>();
    prep_hc<<<NN, 192>>>(x, h);
    prep_w<<<dim3(8, 8, 3), dim3(32, 8)>>>(We1, Wx0, Wx1);
    prep_ab<<<dim3(8, 2), 256, AB_SMEM>>>(We0);
    edge_kernel<<<dim3(8, NN), 256, EDGE_SMEM>>>(x, We0, be0, be1, Winf, binf, bx0,
                                                 bx1, bxo, Wxo);
    hnew_kernel<<<8, 256, HNEW_SMEM>>>(h, Wh0, bh0, Wh1, bh1, Who, bho, out + NN * 24);
    xnew_kernel<<<48, 256>>>(x, out);
}

// round 6
// speedup vs baseline: 2.2139x; 1.1129x over previous
#include <cuda_runtime.h>
#include <cuda_fp16.h>

// EGCL_Multi via mma.sync.m16n8k16 fp16 split hi/lo (3-product) — sm_103.
// R5: weight staging via single cp.async.bulk per 64KB chunk (prestaged,
// pre-swizzled global image) instead of 4096 cp.async.ca instructions.
#define NN 512

__device__ __align__(16) float g_hc[NN * 192];
__device__ __align__(16) float g_A[NN * 256];
__device__ __align__(16) float g_B[NN * 256];
__device__ __align__(16) float g_mi[NN * 256];
__device__ __align__(16) float g_shift[NN * 24];
// 12 chunks x 64KB: [sel(3)][chunk(4)][hi 32KB | lo 32KB], smem-image layout
__device__ __align__(128) char g_Wstage[786432];

// ---------------- small helpers ----------------
__device__ __forceinline__ float silu_f(float v) {
    return v * (1.0f / (1.0f + __expf(-v)));
}
__device__ __forceinline__ unsigned smem_u32(const void* p) {
    unsigned a;
    asm("{ .reg .u64 t; cvta.to.shared.u64 t, %1; cvt.u32.u64 %0, t; }"
        : "=r"(a) : "l"(p));
    return a;
}
__device__ __forceinline__ unsigned lds32(unsigned addr) {
    unsigned v;
    asm volatile("ld.shared.b32 %0, [%1];" : "=r"(v) : "r"(addr));
    return v;
}
__device__ __forceinline__ void sts32(unsigned addr, unsigned v) {
    asm volatile("st.shared.b32 [%0], %1;" :: "r"(addr), "r"(v) : "memory");
}
#define MBAR_INIT(mb, n) \
    asm volatile("mbarrier.init.shared.b64 [%0], %1;" :: "r"(mb), "r"(n) : "memory")
#define EXPECT_TX(mb, n) \
    asm volatile("mbarrier.arrive.expect_tx.shared.b64 _, [%0], %1;" \
                 :: "r"(mb), "r"(n) : "memory")
__device__ __forceinline__ void mbar_wait(unsigned mb, unsigned par) {
    asm volatile(
        "{\n\t.reg .pred P;\n"
        "WL_%=:\n\t"
        "mbarrier.try_wait.parity.acquire.cta.shared::cta.b64 P, [%0], %1, 0x989680;\n\t"
        "@P bra.uni WD_%=;\n\tbra.uni WL_%=;\nWD_%=:\n\t}"
        :: "r"(mb), "r"(par) : "memory");
}
__device__ __forceinline__ void bulk_cp(unsigned dst, const void* src, unsigned mbar) {
    asm volatile(
        "cp.async.bulk.shared::cluster.global.mbarrier::complete_tx::bytes "
        "[%0], [%1], %2, [%3];"
        :: "r"(dst), "l"(src), "r"(65536u), "r"(mbar) : "memory");
}
__device__ __forceinline__ void hsplit2(float a, float b, unsigned& hp, unsigned& lp) {
    __half2 h = __floats2half2_rn(a, b);
    float2 r = __half22float2(h);
    __half2 l = __floats2half2_rn(a - r.x, b - r.y);
    hp = *(unsigned*)&h;
    lp = *(unsigned*)&l;
}
__device__ __forceinline__ void mma16816(float* d, const unsigned* a, unsigned b0,
                                         unsigned b1) {
    asm volatile(
        "mma.sync.aligned.m16n8k16.row.col.f32.f16.f16.f32 "
        "{%0,%1,%2,%3}, {%4,%5,%6,%7}, {%8,%9}, {%0,%1,%2,%3};"
        : "+f"(d[0]), "+f"(d[1]), "+f"(d[2]), "+f"(d[3])
        : "r"(a[0]), "r"(a[1]), "r"(a[2]), "r"(a[3]), "r"(b0), "r"(b1));
}

// ---------------- f32x2 SIMT gemm (node-side) ----------------
__device__ __forceinline__ unsigned long long pk2(float lo, float hi) {
    unsigned long long r;
    asm("mov.b64 %0, {%1, %2};" : "=l"(r) : "f"(lo), "f"(hi));
    return r;
}
__device__ __forceinline__ void upk2(unsigned long long v, float& lo, float& hi) {
    asm("mov.b64 {%0, %1}, %2;" : "=f"(lo), "=f"(hi) : "l"(v));
}
__device__ __forceinline__ void fma2(unsigned long long& d, unsigned long long a,
                                     unsigned long long b) {
    asm("fma.rn.f32x2 %0, %1, %2, %0;" : "+l"(d) : "l"(a), "l"(b));
}
template <int N, bool ACT>
__device__ __forceinline__ void gemm64(const float* sIn, int K,
                                       const float* __restrict__ Wg,
                                       const float* __restrict__ bias, float* out,
                                       float* ws) {
    constexpr int COLG = N / 8;
    constexpr int RPT = COLG / 4;
    const int t = threadIdx.x;
    const int nc = t % COLG, mr = t / COLG;
    const int r0 = mr * RPT, c0 = nc * 8;
    unsigned long long acc[RPT][4];
#pragma unroll
    for (int r = 0; r < RPT; r++)
#pragma unroll
        for (int p = 0; p < 4; p++) acc[r][p] = 0ULL;
    for (int kt = 0; kt < K; kt += 32) {
        __syncthreads();
        for (int idx = t; idx < 32 * N / 4; idx += 256) {
            int wr = idx / (N / 4), wc = (idx - wr * (N / 4)) * 4;
            *(float4*)&ws[wr * N + wc] = *(const float4*)&Wg[(kt + wr) * N + wc];
        }
        __syncthreads();
#pragma unroll
        for (int k4 = 0; k4 < 8; k4++) {
            float4 av[RPT];
#pragma unroll
            for (int r = 0; r < RPT; r++)
                av[r] = *(const float4*)&sIn[(r0 + r) * K + kt + k4 * 4];
#pragma unroll
            for (int kk = 0; kk < 4; kk++) {
                const float* wr_ = &ws[(k4 * 4 + kk) * N + c0];
                float4 w0 = *(const float4*)&wr_[0];
                float4 w1 = *(const float4*)&wr_[4];
                unsigned long long b0 = pk2(w0.x, w0.y), b1 = pk2(w0.z, w0.w);
                unsigned long long b2 = pk2(w1.x, w1.y), b3 = pk2(w1.z, w1.w);
#pragma unroll
                for (int r = 0; r < RPT; r++) {
                    float a = (kk == 0) ? av[r].x : (kk == 1) ? av[r].y
                            : (kk == 2) ? av[r].z : av[r].w;
                    unsigned long long a2 = pk2(a, a);
                    fma2(acc[r][0], a2, b0);
                    fma2(acc[r][1], a2, b1);
                    fma2(acc[r][2], a2, b2);
                    fma2(acc[r][3], a2, b3);
                }
            }
        }
    }
#pragma unroll
    for (int r = 0; r < RPT; r++)
#pragma unroll
        for (int p = 0; p < 4; p++) {
            float lo, hi;
            upk2(acc[r][p], lo, hi);
            int c = c0 + p * 2;
            if (bias) {
                float2 bb = *(const float2*)&bias[c];
                lo += bb.x;
                hi += bb.y;
            }
            if (ACT) { lo = silu_f(lo); hi = silu_f(hi); }
            float2 o; o.x = lo; o.y = hi;
            *(float2*)&out[(r0 + r) * N + c] = o;
        }
    __syncthreads();
}

// ---------------- prep kernels ----------------
__global__ void zero_kernel() {
    int idx = blockIdx.x * 256 + threadIdx.x;
    if (idx < NN * 256) g_mi[idx] = 0.f;
    if (idx < NN * 24) g_shift[idx] = 0.f;
}
__global__ void prep_hc(const float* __restrict__ x, const float* __restrict__ h) {
    int n = blockIdx.x, t = threadIdx.x;
    if (t < 128) g_hc[n * 192 + t] = h[n * 128 + t];
    else {
        int p = t - 128, a = p >> 3, b = p & 7;
        float dx = x[n * 24 + a * 3] - x[n * 24 + b * 3];
        float dy = x[n * 24 + a * 3 + 1] - x[n * 24 + b * 3 + 1];
        float dz = x[n * 24 + a * 3 + 2] - x[n * 24 + b * 3 + 2];
        g_hc[n * 192 + 128 + p] = dx * dx + dy * dy + dz * dz;
    }
}
// transpose + fp16 hi/lo split into the pre-swizzled smem-image layout
__global__ void prep_w(const float* __restrict__ We1, const float* __restrict__ Wx0,
                       const float* __restrict__ Wx1) {
    __shared__ float tile[32][33];
    int sel = blockIdx.z;
    const float* W = (sel == 0) ? We1 : (sel == 1) ? Wx0 : Wx1;
    int n0 = blockIdx.x * 32, k0 = blockIdx.y * 32;
    int tx = threadIdx.x, ty = threadIdx.y;
    for (int r = ty; r < 32; r += 8) tile[r][tx] = W[(k0 + r) * 256 + n0 + tx];
    __syncthreads();
    for (int r = ty; r < 32; r += 8) {
        float v = tile[tx][r];  // = W[k0+tx][n0+r]
        int n = n0 + r, k = k0 + tx;
        __half hb = __float2half_rn(v);
        __half lb = __float2half_rn(v - __half2float(hb));
        int chunk = k >> 6, kin = k & 63;
        unsigned off = (unsigned)(sel * 262144 + chunk * 65536 + n * 128 +
                                  (((kin >> 3) * 16) ^ ((n & 7) * 16)) + (kin & 7) * 2);
        *(__half*)(g_Wstage + off) = hb;
        *(__half*)(g_Wstage + 32768 + off) = lb;
    }
}
__global__ void __launch_bounds__(256) prep_ab(const float* __restrict__ We0) {
    extern __shared__ float sm[];
    float* sIn = sm;
    float* ws = sm + 64 * 192;
    int r0g = blockIdx.x * 64, t = threadIdx.x;
    for (int idx = t; idx < 64 * 192 / 4; idx += 256)
        *(float4*)&sIn[idx * 4] = *(const float4*)&g_hc[r0g * 192 + idx * 4];
    __syncthreads();
    const float* Wg = We0 + (blockIdx.y == 0 ? 8 : 200) * 256;
    float* outp = (blockIdx.y == 0 ? g_A : g_B) + r0g * 256;
    gemm64<256, false>(sIn, 192, Wg, nullptr, outp, ws);
}

// ---------------- edge kernel ----------------
// smem byte offsets
#define OFF_A_HI 0       // 33792  (64 rows x 264 halves)
#define OFF_A_LO 33792   // 33792
#define OFF_W 67584      // 131072 (2 bufs x (hi 32768 + lo 32768))
#define OFF_AUX 198656   // 8192   (We0 rows 0..7 f32; later Wxo [256][8] f32)
#define OFF_XJ 206848    // 6144
#define OFF_SQN 212992   // 2048
#define OFF_BI 215040    // 1024
#define OFF_WINF 216064  // 1024
#define OFF_BIAS 217088  // 3072
#define OFF_PE 220160    // 256
#define OFF_E 220416     // 256
#define OFF_PX 220672    // 2048
#define OFF_XI 222720    // 96
#define OFF_SH 222816    // 96
#define OFF_MB 222912    // 16 (two mbarriers)
#define EDGE_SMEM 222928

__global__ void __launch_bounds__(256, 1) edge_kernel(
    const float* __restrict__ x, const float* __restrict__ We0,
    const float* __restrict__ be0, const float* __restrict__ be1,
    const float* __restrict__ Winf, const float* __restrict__ binf,
    const float* __restrict__ bx0, const float* __restrict__ bx1,
    const float* __restrict__ bxo, const float* __restrict__ Wxo) {
    extern __shared__ char smc[];
    const unsigned sb = smem_u32(smc);
    const int t = threadIdx.x;
    const int lane = t & 31, w = t >> 5;
    const int band = w >> 1, ng = w & 1;
    const int r0 = band * 16 + (lane >> 2);
    const int k4 = lane & 3;
    const unsigned bswz = (unsigned)((lane >> 2) << 4);
    const int i = blockIdx.y, j0 = blockIdx.x * 64;

    float* sAux = (float*)(smc + OFF_AUX);
    float* sXj = (float*)(smc + OFF_XJ);
    float* sSqn = (float*)(smc + OFF_SQN);
    float* sBi = (float*)(smc + OFF_BI);
    float* sWinf = (float*)(smc + OFF_WINF);
    float* sBias = (float*)(smc + OFF_BIAS);
    float* sPE = (float*)(smc + OFF_PE);
    float* sE = (float*)(smc + OFF_E);
    float* sPx = (float*)(smc + OFF_PX);
    float* sXi = (float*)(smc + OFF_XI);
    float* sSh = (float*)(smc + OFF_SH);
    const unsigned mb0 = sb + OFF_MB, mb1 = sb + OFF_MB + 8;

    // prologue staging
    if (t == 0) { MBAR_INIT(mb0, 1); MBAR_INIT(mb1, 1); }
    for (int idx = t; idx < 2048; idx += 256) sAux[idx] = We0[idx];
    for (int idx = t; idx < 1536; idx += 256) sXj[idx] = x[j0 * 24 + idx];
    sBi[t] = g_B[i * 256 + t] + be0[t];
    sWinf[t] = Winf[t];
    sBias[t] = be1[t];
    sBias[256 + t] = bx0[t];
    sBias[512 + t] = bx1[t];
    if (t < 64) sPE[t] = 0.f;
    for (int p = t; p < 512; p += 256) sPx[p] = 0.f;
    if (t < 24) { sXi[t] = x[i * 24 + t]; sSh[t] = 0.f; }
    __syncthreads();

    // kick chunk 0 bulk copy (one thread, ~0 issue cost)
    if (t == 0) {
        EXPECT_TX(mb0, 65536u);
        bulk_cp(sb + OFF_W, g_Wstage, mb0);
    }

    // sqn
    for (int p = t; p < 512; p += 256) {
        int j = p >> 3, hh = p & 7;
        float dx = sXj[j * 24 + hh * 3] - sXi[hh * 3];
        float dy = sXj[j * 24 + hh * 3 + 1] - sXi[hh * 3 + 1];
        float dz = sXj[j * 24 + hh * 3 + 2] - sXi[hh * 3 + 2];
        sSqn[p] = dx * dx + dy * dy + dz * dz;
    }
    __syncthreads();

    // T0 = silu(A[j] + (B[i]+be0) + sqn@We0[0:8]) -> split planes
    for (int it = 0; it < 16; ++it) {
        int idx = it * 256 + t;
        int j = idx >> 6, c = (idx & 63) * 4;
        float4 v = *(const float4*)&g_A[(j0 + j) * 256 + c];
        v.x += sBi[c]; v.y += sBi[c + 1]; v.z += sBi[c + 2]; v.w += sBi[c + 3];
#pragma unroll
        for (int q = 0; q < 8; q++) {
            float s = sSqn[j * 8 + q];
            float4 ww = *(const float4*)&sAux[q * 256 + c];
            v.x += s * ww.x; v.y += s * ww.y; v.z += s * ww.z; v.w += s * ww.w;
        }
        v.x = silu_f(v.x); v.y = silu_f(v.y); v.z = silu_f(v.z); v.w = silu_f(v.w);
        unsigned hp0, lp0, hp1, lp1;
        hsplit2(v.x, v.y, hp0, lp0);
        hsplit2(v.z, v.w, hp1, lp1);
        unsigned off = (unsigned)(j * 528 + c * 2);
        sts32(sb + OFF_A_HI + off, hp0);
        sts32(sb + OFF_A_HI + off + 4, hp1);
        sts32(sb + OFF_A_LO + off, lp0);
        sts32(sb + OFF_A_LO + off + 4, lp1);
    }
    __syncthreads();  // T0 planes complete before first MMA

    const float binf0 = binf[0];

    for (int l = 0; l < 3; ++l) {
        float acc[16][4];
#pragma unroll
        for (int s2 = 0; s2 < 16; ++s2)
#pragma unroll
            for (int q = 0; q < 4; ++q) acc[s2][q] = 0.f;

        for (int c = 0; c < 4; ++c) {
            int g = l * 4 + c;
            if (g + 1 < 12 && t == 0) {
                unsigned mb = ((g + 1) & 1) ? mb1 : mb0;
                EXPECT_TX(mb, 65536u);
                bulk_cp(sb + OFF_W + (unsigned)(((g + 1) & 1) * 65536),
                        g_Wstage + (g + 1) * 65536, mb);
            }
            mbar_wait((g & 1) ? mb1 : mb0, (g >> 1) & 1);
            const unsigned wb = sb + OFF_W + (unsigned)((g & 1) * 65536);
#pragma unroll
            for (int ks = 0; ks < 4; ++ks) {
                const int khb = c * 128 + ks * 32;
                unsigned ah[4], al[4];
                unsigned a0 = sb + OFF_A_HI + (unsigned)(r0 * 528 + khb + k4 * 4);
                ah[0] = lds32(a0);
                ah[1] = lds32(a0 + 8 * 528);
                ah[2] = lds32(a0 + 16);
                ah[3] = lds32(a0 + 8 * 528 + 16);
                unsigned a1 = a0 + (OFF_A_LO - OFF_A_HI);
                al[0] = lds32(a1);
                al[1] = lds32(a1 + 8 * 528);
                al[2] = lds32(a1 + 16);
                al[3] = lds32(a1 + 8 * 528 + 16);
#pragma unroll
                for (int sub = 0; sub < 16; ++sub) {
                    unsigned nrow = (unsigned)(ng * 128 + sub * 8 + (lane >> 2));
                    unsigned rb = wb + nrow * 128;
                    unsigned o0 = ((unsigned)(ks * 32 + k4 * 4)) ^ bswz;
                    unsigned o1 = ((unsigned)(ks * 32 + k4 * 4 + 16)) ^ bswz;
                    unsigned bh0 = lds32(rb + o0), bh1 = lds32(rb + o1);
                    unsigned bl0 = lds32(rb + 32768 + o0), bl1 = lds32(rb + 32768 + o1);
                    mma16816(acc[sub], ah, bh0, bh1);
                    mma16816(acc[sub], ah, bl0, bl1);
                    mma16816(acc[sub], al, bh0, bh1);
                }
            }
            __syncthreads();  // MMA reads done before buffer reuse
        }

        // ---------------- epilogues ----------------
        if (l < 2) {
            float pe0 = 0.f, pe1 = 0.f;
#pragma unroll
            for (int sub = 0; sub < 16; ++sub) {
                int col = ng * 128 + sub * 8 + k4 * 2;
                float v0 = silu_f(acc[sub][0] + sBias[l * 256 + col]);
                float v1 = silu_f(acc[sub][1] + sBias[l * 256 + col + 1]);
                float v2 = silu_f(acc[sub][2] + sBias[l * 256 + col]);
                float v3 = silu_f(acc[sub][3] + sBias[l * 256 + col + 1]);
                if (l == 0) {
                    pe0 += v0 * sWinf[col] + v1 * sWinf[col + 1];
                    pe1 += v2 * sWinf[col] + v3 * sWinf[col + 1];
                }
                unsigned hp, lp;
                hsplit2(v0, v1, hp, lp);
                unsigned off = (unsigned)(r0 * 528 + col * 2);
                sts32(sb + OFF_A_HI + off, hp);
                sts32(sb + OFF_A_LO + off, lp);
                hsplit2(v2, v3, hp, lp);
                off += 8 * 528;
                sts32(sb + OFF_A_HI + off, hp);
                sts32(sb + OFF_A_LO + off, lp);
            }
            if (l == 0) {
                pe0 += __shfl_xor_sync(0xffffffffu, pe0, 1);
                pe0 += __shfl_xor_sync(0xffffffffu, pe0, 2);
                pe1 += __shfl_xor_sync(0xffffffffu, pe1, 1);
                pe1 += __shfl_xor_sync(0xffffffffu, pe1, 2);
                if (k4 == 0) {
                    atomicAdd(&sPE[r0], pe0);
                    atomicAdd(&sPE[r0 + 8], pe1);
                }
                __syncthreads();
                if (t < 64) {
                    float z = sPE[t] + binf0;
                    float e = 1.0f / (1.0f + __expf(-z));
                    if (j0 + t == i) e = 0.f;
                    sE[t] = e;
                }
                // stage Wxo into sAux (We0 no longer needed)
                for (int idx = t; idx < 2048; idx += 256) sAux[idx] = Wxo[idx];
                __syncthreads();
                // m_i column sums
                {
                    const __half* mh = (const __half*)(smc + OFF_A_HI);
                    const __half* ml = (const __half*)(smc + OFF_A_LO);
                    float a_ = 0.f;
#pragma unroll 4
                    for (int j = 0; j < 64; ++j)
                        a_ += (__half2float(mh[j * 264 + t]) +
                               __half2float(ml[j * 264 + t])) * sE[j];
                    atomicAdd(&g_mi[i * 256 + t], a_);
                }
            }
        } else {
            float pxa0[8], pxa1[8];
#pragma unroll
            for (int hh = 0; hh < 8; ++hh) { pxa0[hh] = 0.f; pxa1[hh] = 0.f; }
#pragma unroll
            for (int sub = 0; sub < 16; ++sub) {
                int col = ng * 128 + sub * 8 + k4 * 2;
                float v0 = silu_f(acc[sub][0] + sBias[512 + col]);
                float v1 = silu_f(acc[sub][1] + sBias[512 + col + 1]);
                float v2 = silu_f(acc[sub][2] + sBias[512 + col]);
                float v3 = silu_f(acc[sub][3] + sBias[512 + col + 1]);
                const float* w0 = &sAux[col * 8];
                const float* w1 = &sAux[(col + 1) * 8];
#pragma unroll
                for (int hh = 0; hh < 8; ++hh) {
                    pxa0[hh] += v0 * w0[hh] + v1 * w1[hh];
                    pxa1[hh] += v2 * w0[hh] + v3 * w1[hh];
                }
            }
#pragma unroll
            for (int hh = 0; hh < 8; ++hh) {
                pxa0[hh] += __shfl_xor_sync(0xffffffffu, pxa0[hh], 1);
                pxa0[hh] += __shfl_xor_sync(0xffffffffu, pxa0[hh], 2);
                pxa1[hh] += __shfl_xor_sync(0xffffffffu, pxa1[hh], 1);
                pxa1[hh] += __shfl_xor_sync(0xffffffffu, pxa1[hh], 2);
            }
            if (k4 == 0) {
#pragma unroll
                for (int hh = 0; hh < 8; ++hh) {
                    atomicAdd(&sPx[r0 * 8 + hh], pxa0[hh]);
                    atomicAdd(&sPx[(r0 + 8) * 8 + hh], pxa1[hh]);
                }
            }
            __syncthreads();
            for (int p = t; p < 512; p += 256) {
                int j = p >> 3, hh = p & 7;
                float px = sPx[p] + bxo[hh];
                if (j0 + j == i) px = 0.f;
                float nrm = sqrtf(sSqn[p] + 1e-8f) + 1.0f;
                float wgt = px / nrm;
#pragma unroll
                for (int d = 0; d < 3; ++d)
                    atomicAdd(&sSh[hh * 3 + d],
                              wgt * (sXj[j * 24 + hh * 3 + d] - sXi[hh * 3 + d]));
            }
            __syncthreads();
            if (t < 24) atomicAdd(&g_shift[i * 24 + t], sSh[t]);
        }
        __syncthreads();  // epilogue A-plane writes visible to next layer MMA
    }
}

// ---------------- node kernels ----------------
__global__ void __launch_bounds__(256) hnew_kernel(
    const float* __restrict__ h, const float* __restrict__ Wh0,
    const float* __restrict__ bh0, const float* __restrict__ Wh1,
    const float* __restrict__ bh1, const float* __restrict__ Who,
    const float* __restrict__ bho, float* __restrict__ out) {
    extern __shared__ float sm[];
    float* buf0 = sm;                 // 64*384
    float* buf1 = buf0 + 64 * 384;    // 64*256
    float* ws = buf1 + 64 * 256;      // 32*256
    int r0g = blockIdx.x * 64, t = threadIdx.x;
    for (int idx = t; idx < 64 * 384; idx += 256) {
        int row = idx / 384, c = idx - row * 384;
        buf0[idx] = (c < 256) ? g_mi[(r0g + row) * 256 + c]
                              : h[(r0g + row) * 128 + (c - 256)];
    }
    __syncthreads();
    gemm64<256, true>(buf0, 384, Wh0, bh0, buf1, ws);
    gemm64<256, true>(buf1, 256, Wh1, bh1, buf0, ws);
    gemm64<128, false>(buf0, 256, Who, bho, buf1, ws);
    for (int idx = t; idx < 64 * 128; idx += 256)
        out[r0g * 128 + idx] = buf1[idx] + h[r0g * 128 + idx];
}
__global__ void xnew_kernel(const float* __restrict__ x, float* __restrict__ out) {
    int idx = blockIdx.x * 256 + threadIdx.x;
    if (idx < NN * 24) out[idx] = x[idx] + g_shift[idx] * (1.0f / 511.0f);
}

// ---------------- launch ----------------
extern "C" void kernel_launch(void* const* d_in, const int* in_sizes, int n_in,
                              void* d_out, int out_size) {
    const float* x = (const float*)d_in[0];
    const float* h = (const float*)d_in[1];
    const float* We0 = (const float*)d_in[2];
    const float* be0 = (const float*)d_in[3];
    const float* We1 = (const float*)d_in[4];
    const float* be1 = (const float*)d_in[5];
    const float* Winf = (const float*)d_in[6];
    const float* binf = (const float*)d_in[7];
    const float* Wx0 = (const float*)d_in[8];
    const float* bx0 = (const float*)d_in[9];
    const float* Wx1 = (const float*)d_in[10];
    const float* bx1 = (const float*)d_in[11];
    const float* Wxo = (const float*)d_in[12];
    const float* bxo = (const float*)d_in[13];
    const float* Wh0 = (const float*)d_in[14];
    const float* bh0 = (const float*)d_in[15];
    const float* Wh1 = (const float*)d_in[16];
    const float* bh1 = (const float*)d_in[17];
    const float* Who = (const float*)d_in[18];
    const float* bho = (const float*)d_in[19];
    float* out = (float*)d_out;  // [x_new (512*24) | h_new (512*128)]

    const int AB_SMEM = (64 * 192 + 32 * 256) * 4;
    const int HNEW_SMEM = (64 * 384 + 64 * 256 + 32 * 256) * 4;
    cudaFuncSetAttribute(edge_kernel, cudaFuncAttributeMaxDynamicSharedMemorySize,
                         EDGE_SMEM);
    cudaFuncSetAttribute(prep_ab, cudaFuncAttributeMaxDynamicSharedMemorySize, AB_SMEM);
    cudaFuncSetAttribute(hnew_kernel, cudaFuncAttributeMaxDynamicSharedMemorySize,
                         HNEW_SMEM);

    zero_kernel<<<512, 256>>>();
    prep_hc<<<NN, 192>>>(x, h);
    prep_w<<<dim3(8, 8, 3), dim3(32, 8)>>>(We1, Wx0, Wx1);
    prep_ab<<<dim3(8, 2), 256, AB_SMEM>>>(We0);
    edge_kernel<<<dim3(8, NN), 256, EDGE_SMEM>>>(x, We0, be0, be1, Winf, binf, bx0,
                                                 bx1, bxo, Wxo);
    hnew_kernel<<<8, 256, HNEW_SMEM>>>(h, Wh0, bh0, Wh1, bh1, Who, bho, out + NN * 24);
    xnew_kernel<<<48, 256>>>(x, out);
}

// round 7
// speedup vs baseline: 2.5404x; 1.1475x over previous
#include <cuda_runtime.h>
#include <cuda_fp16.h>

// EGCL_Multi via mma.sync.m16n8k16 fp16 — sm_103.
// R6: precision-tiered products. Layer 1 (We1): split hi/lo 3-product
// (full accuracy for m -> gate/m_i/h_new). Layers 2-3 (Wx0,Wx1): plain fp16
// single product (px feeds shift which is << x; error is diluted).
// Cuts HMMA work 9 -> 5 units per edge and layer-2/3 weight traffic in half.
#define NN 512

__device__ __align__(16) float g_hc[NN * 192];
__device__ __align__(16) float g_A[NN * 256];
__device__ __align__(16) float g_B[NN * 256];
__device__ __align__(16) float g_mi[NN * 256];
__device__ __align__(16) float g_shift[NN * 24];
// 12 chunks x 64KB: [sel(3)][chunk(4)][hi 32KB | lo 32KB], smem-image layout
__device__ __align__(128) char g_Wstage[786432];

// ---------------- small helpers ----------------
__device__ __forceinline__ float silu_f(float v) {
    return v * (1.0f / (1.0f + __expf(-v)));
}
__device__ __forceinline__ unsigned smem_u32(const void* p) {
    unsigned a;
    asm("{ .reg .u64 t; cvta.to.shared.u64 t, %1; cvt.u32.u64 %0, t; }"
        : "=r"(a) : "l"(p));
    return a;
}
__device__ __forceinline__ unsigned lds32(unsigned addr) {
    unsigned v;
    asm volatile("ld.shared.b32 %0, [%1];" : "=r"(v) : "r"(addr));
    return v;
}
__device__ __forceinline__ void sts32(unsigned addr, unsigned v) {
    asm volatile("st.shared.b32 [%0], %1;" :: "r"(addr), "r"(v) : "memory");
}
#define MBAR_INIT(mb, n) \
    asm volatile("mbarrier.init.shared.b64 [%0], %1;" :: "r"(mb), "r"(n) : "memory")
#define EXPECT_TX(mb, n) \
    asm volatile("mbarrier.arrive.expect_tx.shared.b64 _, [%0], %1;" \
                 :: "r"(mb), "r"(n) : "memory")
__device__ __forceinline__ void mbar_wait(unsigned mb, unsigned par) {
    asm volatile(
        "{\n\t.reg .pred P;\n"
        "WL_%=:\n\t"
        "mbarrier.try_wait.parity.acquire.cta.shared::cta.b64 P, [%0], %1, 0x989680;\n\t"
        "@P bra.uni WD_%=;\n\tbra.uni WL_%=;\nWD_%=:\n\t}"
        :: "r"(mb), "r"(par) : "memory");
}
__device__ __forceinline__ void bulk_cp(unsigned dst, const void* src, unsigned bytes,
                                        unsigned mbar) {
    asm volatile(
        "cp.async.bulk.shared::cluster.global.mbarrier::complete_tx::bytes "
        "[%0], [%1], %2, [%3];"
        :: "r"(dst), "l"(src), "r"(bytes), "r"(mbar) : "memory");
}
__device__ __forceinline__ void hsplit2(float a, float b, unsigned& hp, unsigned& lp) {
    __half2 h = __floats2half2_rn(a, b);
    float2 r = __half22float2(h);
    __half2 l = __floats2half2_rn(a - r.x, b - r.y);
    hp = *(unsigned*)&h;
    lp = *(unsigned*)&l;
}
__device__ __forceinline__ unsigned hpack2(float a, float b) {
    __half2 h = __floats2half2_rn(a, b);
    return *(unsigned*)&h;
}
__device__ __forceinline__ void mma16816(float* d, const unsigned* a, unsigned b0,
                                         unsigned b1) {
    asm volatile(
        "mma.sync.aligned.m16n8k16.row.col.f32.f16.f16.f32 "
        "{%0,%1,%2,%3}, {%4,%5,%6,%7}, {%8,%9}, {%0,%1,%2,%3};"
        : "+f"(d[0]), "+f"(d[1]), "+f"(d[2]), "+f"(d[3])
        : "r"(a[0]), "r"(a[1]), "r"(a[2]), "r"(a[3]), "r"(b0), "r"(b1));
}

// ---------------- f32x2 SIMT gemm (node-side) ----------------
__device__ __forceinline__ unsigned long long pk2(float lo, float hi) {
    unsigned long long r;
    asm("mov.b64 %0, {%1, %2};" : "=l"(r) : "f"(lo), "f"(hi));
    return r;
}
__device__ __forceinline__ void upk2(unsigned long long v, float& lo, float& hi) {
    asm("mov.b64 {%0, %1}, %2;" : "=f"(lo), "=f"(hi) : "l"(v));
}
__device__ __forceinline__ void fma2(unsigned long long& d, unsigned long long a,
                                     unsigned long long b) {
    asm("fma.rn.f32x2 %0, %1, %2, %0;" : "+l"(d) : "l"(a), "l"(b));
}
template <int N, bool ACT>
__device__ __forceinline__ void gemm64(const float* sIn, int K,
                                       const float* __restrict__ Wg,
                                       const float* __restrict__ bias, float* out,
                                       float* ws) {
    constexpr int COLG = N / 8;
    constexpr int RPT = COLG / 4;
    const int t = threadIdx.x;
    const int nc = t % COLG, mr = t / COLG;
    const int r0 = mr * RPT, c0 = nc * 8;
    unsigned long long acc[RPT][4];
#pragma unroll
    for (int r = 0; r < RPT; r++)
#pragma unroll
        for (int p = 0; p < 4; p++) acc[r][p] = 0ULL;
    for (int kt = 0; kt < K; kt += 32) {
        __syncthreads();
        for (int idx = t; idx < 32 * N / 4; idx += 256) {
            int wr = idx / (N / 4), wc = (idx - wr * (N / 4)) * 4;
            *(float4*)&ws[wr * N + wc] = *(const float4*)&Wg[(kt + wr) * N + wc];
        }
        __syncthreads();
#pragma unroll
        for (int k4 = 0; k4 < 8; k4++) {
            float4 av[RPT];
#pragma unroll
            for (int r = 0; r < RPT; r++)
                av[r] = *(const float4*)&sIn[(r0 + r) * K + kt + k4 * 4];
#pragma unroll
            for (int kk = 0; kk < 4; kk++) {
                const float* wr_ = &ws[(k4 * 4 + kk) * N + c0];
                float4 w0 = *(const float4*)&wr_[0];
                float4 w1 = *(const float4*)&wr_[4];
                unsigned long long b0 = pk2(w0.x, w0.y), b1 = pk2(w0.z, w0.w);
                unsigned long long b2 = pk2(w1.x, w1.y), b3 = pk2(w1.z, w1.w);
#pragma unroll
                for (int r = 0; r < RPT; r++) {
                    float a = (kk == 0) ? av[r].x : (kk == 1) ? av[r].y
                            : (kk == 2) ? av[r].z : av[r].w;
                    unsigned long long a2 = pk2(a, a);
                    fma2(acc[r][0], a2, b0);
                    fma2(acc[r][1], a2, b1);
                    fma2(acc[r][2], a2, b2);
                    fma2(acc[r][3], a2, b3);
                }
            }
        }
    }
#pragma unroll
    for (int r = 0; r < RPT; r++)
#pragma unroll
        for (int p = 0; p < 4; p++) {
            float lo, hi;
            upk2(acc[r][p], lo, hi);
            int c = c0 + p * 2;
            if (bias) {
                float2 bb = *(const float2*)&bias[c];
                lo += bb.x;
                hi += bb.y;
            }
            if (ACT) { lo = silu_f(lo); hi = silu_f(hi); }
            float2 o; o.x = lo; o.y = hi;
            *(float2*)&out[(r0 + r) * N + c] = o;
        }
    __syncthreads();
}

// ---------------- prep kernels ----------------
__global__ void zero_kernel() {
    int idx = blockIdx.x * 256 + threadIdx.x;
    if (idx < NN * 256) g_mi[idx] = 0.f;
    if (idx < NN * 24) g_shift[idx] = 0.f;
}
__global__ void prep_hc(const float* __restrict__ x, const float* __restrict__ h) {
    int n = blockIdx.x, t = threadIdx.x;
    if (t < 128) g_hc[n * 192 + t] = h[n * 128 + t];
    else {
        int p = t - 128, a = p >> 3, b = p & 7;
        float dx = x[n * 24 + a * 3] - x[n * 24 + b * 3];
        float dy = x[n * 24 + a * 3 + 1] - x[n * 24 + b * 3 + 1];
        float dz = x[n * 24 + a * 3 + 2] - x[n * 24 + b * 3 + 2];
        g_hc[n * 192 + 128 + p] = dx * dx + dy * dy + dz * dz;
    }
}
// transpose + fp16 hi/lo split into the pre-swizzled smem-image layout
__global__ void prep_w(const float* __restrict__ We1, const float* __restrict__ Wx0,
                       const float* __restrict__ Wx1) {
    __shared__ float tile[32][33];
    int sel = blockIdx.z;
    const float* W = (sel == 0) ? We1 : (sel == 1) ? Wx0 : Wx1;
    int n0 = blockIdx.x * 32, k0 = blockIdx.y * 32;
    int tx = threadIdx.x, ty = threadIdx.y;
    for (int r = ty; r < 32; r += 8) tile[r][tx] = W[(k0 + r) * 256 + n0 + tx];
    __syncthreads();
    for (int r = ty; r < 32; r += 8) {
        float v = tile[tx][r];  // = W[k0+tx][n0+r]
        int n = n0 + r, k = k0 + tx;
        __half hb = __float2half_rn(v);
        __half lb = __float2half_rn(v - __half2float(hb));
        int chunk = k >> 6, kin = k & 63;
        unsigned off = (unsigned)(sel * 262144 + chunk * 65536 + n * 128 +
                                  (((kin >> 3) * 16) ^ ((n & 7) * 16)) + (kin & 7) * 2);
        *(__half*)(g_Wstage + off) = hb;
        *(__half*)(g_Wstage + 32768 + off) = lb;
    }
}
__global__ void __launch_bounds__(256) prep_ab(const float* __restrict__ We0) {
    extern __shared__ float sm[];
    float* sIn = sm;
    float* ws = sm + 64 * 192;
    int r0g = blockIdx.x * 64, t = threadIdx.x;
    for (int idx = t; idx < 64 * 192 / 4; idx += 256)
        *(float4*)&sIn[idx * 4] = *(const float4*)&g_hc[r0g * 192 + idx * 4];
    __syncthreads();
    const float* Wg = We0 + (blockIdx.y == 0 ? 8 : 200) * 256;
    float* outp = (blockIdx.y == 0 ? g_A : g_B) + r0g * 256;
    gemm64<256, false>(sIn, 192, Wg, nullptr, outp, ws);
}

// ---------------- edge kernel ----------------
// smem byte offsets
#define OFF_A_HI 0       // 33792  (64 rows x 264 halves)
#define OFF_A_LO 33792   // 33792
#define OFF_W 67584      // 131072 (2 bufs x (hi 32768 + lo 32768))
#define OFF_AUX 198656   // 8192   (We0 rows 0..7 f32; later Wxo [256][8] f32)
#define OFF_XJ 206848    // 6144
#define OFF_SQN 212992   // 2048
#define OFF_BI 215040    // 1024
#define OFF_WINF 216064  // 1024
#define OFF_BIAS 217088  // 3072
#define OFF_PE 220160    // 256
#define OFF_E 220416     // 256
#define OFF_PX 220672    // 2048
#define OFF_XI 222720    // 96
#define OFF_SH 222816    // 96
#define OFF_MB 222912    // 16 (two mbarriers)
#define EDGE_SMEM 222928

__global__ void __launch_bounds__(256, 1) edge_kernel(
    const float* __restrict__ x, const float* __restrict__ We0,
    const float* __restrict__ be0, const float* __restrict__ be1,
    const float* __restrict__ Winf, const float* __restrict__ binf,
    const float* __restrict__ bx0, const float* __restrict__ bx1,
    const float* __restrict__ bxo, const float* __restrict__ Wxo) {
    extern __shared__ char smc[];
    const unsigned sb = smem_u32(smc);
    const int t = threadIdx.x;
    const int lane = t & 31, w = t >> 5;
    const int band = w >> 1, ng = w & 1;
    const int r0 = band * 16 + (lane >> 2);
    const int k4 = lane & 3;
    const unsigned bswz = (unsigned)((lane >> 2) << 4);
    const int i = blockIdx.y, j0 = blockIdx.x * 64;

    float* sAux = (float*)(smc + OFF_AUX);
    float* sXj = (float*)(smc + OFF_XJ);
    float* sSqn = (float*)(smc + OFF_SQN);
    float* sBi = (float*)(smc + OFF_BI);
    float* sWinf = (float*)(smc + OFF_WINF);
    float* sBias = (float*)(smc + OFF_BIAS);
    float* sPE = (float*)(smc + OFF_PE);
    float* sE = (float*)(smc + OFF_E);
    float* sPx = (float*)(smc + OFF_PX);
    float* sXi = (float*)(smc + OFF_XI);
    float* sSh = (float*)(smc + OFF_SH);
    const unsigned mb0 = sb + OFF_MB, mb1 = sb + OFF_MB + 8;

    // prologue staging
    if (t == 0) { MBAR_INIT(mb0, 1); MBAR_INIT(mb1, 1); }
    for (int idx = t; idx < 2048; idx += 256) sAux[idx] = We0[idx];
    for (int idx = t; idx < 1536; idx += 256) sXj[idx] = x[j0 * 24 + idx];
    sBi[t] = g_B[i * 256 + t] + be0[t];
    sWinf[t] = Winf[t];
    sBias[t] = be1[t];
    sBias[256 + t] = bx0[t];
    sBias[512 + t] = bx1[t];
    if (t < 64) sPE[t] = 0.f;
    for (int p = t; p < 512; p += 256) sPx[p] = 0.f;
    if (t < 24) { sXi[t] = x[i * 24 + t]; sSh[t] = 0.f; }
    __syncthreads();

    // kick chunk 0 bulk copy (one thread, ~0 issue cost)
    if (t == 0) {
        EXPECT_TX(mb0, 65536u);
        bulk_cp(sb + OFF_W, g_Wstage, 65536u, mb0);
    }

    // sqn
    for (int p = t; p < 512; p += 256) {
        int j = p >> 3, hh = p & 7;
        float dx = sXj[j * 24 + hh * 3] - sXi[hh * 3];
        float dy = sXj[j * 24 + hh * 3 + 1] - sXi[hh * 3 + 1];
        float dz = sXj[j * 24 + hh * 3 + 2] - sXi[hh * 3 + 2];
        sSqn[p] = dx * dx + dy * dy + dz * dz;
    }
    __syncthreads();

    // T0 = silu(A[j] + (B[i]+be0) + sqn@We0[0:8]) -> split planes
    for (int it = 0; it < 16; ++it) {
        int idx = it * 256 + t;
        int j = idx >> 6, c = (idx & 63) * 4;
        float4 v = *(const float4*)&g_A[(j0 + j) * 256 + c];
        v.x += sBi[c]; v.y += sBi[c + 1]; v.z += sBi[c + 2]; v.w += sBi[c + 3];
#pragma unroll
        for (int q = 0; q < 8; q++) {
            float s = sSqn[j * 8 + q];
            float4 ww = *(const float4*)&sAux[q * 256 + c];
            v.x += s * ww.x; v.y += s * ww.y; v.z += s * ww.z; v.w += s * ww.w;
        }
        v.x = silu_f(v.x); v.y = silu_f(v.y); v.z = silu_f(v.z); v.w = silu_f(v.w);
        unsigned hp0, lp0, hp1, lp1;
        hsplit2(v.x, v.y, hp0, lp0);
        hsplit2(v.z, v.w, hp1, lp1);
        unsigned off = (unsigned)(j * 528 + c * 2);
        sts32(sb + OFF_A_HI + off, hp0);
        sts32(sb + OFF_A_HI + off + 4, hp1);
        sts32(sb + OFF_A_LO + off, lp0);
        sts32(sb + OFF_A_LO + off + 4, lp1);
    }
    __syncthreads();  // T0 planes complete before first MMA

    const float binf0 = binf[0];

    for (int l = 0; l < 3; ++l) {
        float acc[16][4];
#pragma unroll
        for (int s2 = 0; s2 < 16; ++s2)
#pragma unroll
            for (int q = 0; q < 4; ++q) acc[s2][q] = 0.f;

        for (int c = 0; c < 4; ++c) {
            int g = l * 4 + c;
            if (g + 1 < 12 && t == 0) {
                unsigned mb = ((g + 1) & 1) ? mb1 : mb0;
                unsigned nb = (g + 1 < 4) ? 65536u : 32768u;  // hi-only for l>=1
                EXPECT_TX(mb, nb);
                bulk_cp(sb + OFF_W + (unsigned)(((g + 1) & 1) * 65536),
                        g_Wstage + (g + 1) * 65536, nb, mb);
            }
            mbar_wait((g & 1) ? mb1 : mb0, (g >> 1) & 1);
            const unsigned wb = sb + OFF_W + (unsigned)((g & 1) * 65536);
            if (l == 0) {
                // split 3-product (full accuracy for m)
#pragma unroll
                for (int ks = 0; ks < 4; ++ks) {
                    const int khb = c * 128 + ks * 32;
                    unsigned ah[4], al[4];
                    unsigned a0 = sb + OFF_A_HI + (unsigned)(r0 * 528 + khb + k4 * 4);
                    ah[0] = lds32(a0);
                    ah[1] = lds32(a0 + 8 * 528);
                    ah[2] = lds32(a0 + 16);
                    ah[3] = lds32(a0 + 8 * 528 + 16);
                    unsigned a1 = a0 + (OFF_A_LO - OFF_A_HI);
                    al[0] = lds32(a1);
                    al[1] = lds32(a1 + 8 * 528);
                    al[2] = lds32(a1 + 16);
                    al[3] = lds32(a1 + 8 * 528 + 16);
#pragma unroll
                    for (int sub = 0; sub < 16; ++sub) {
                        unsigned nrow = (unsigned)(ng * 128 + sub * 8 + (lane >> 2));
                        unsigned rb = wb + nrow * 128;
                        unsigned o0 = ((unsigned)(ks * 32 + k4 * 4)) ^ bswz;
                        unsigned o1 = ((unsigned)(ks * 32 + k4 * 4 + 16)) ^ bswz;
                        unsigned bh0 = lds32(rb + o0), bh1 = lds32(rb + o1);
                        unsigned bl0 = lds32(rb + 32768 + o0),
                                 bl1 = lds32(rb + 32768 + o1);
                        mma16816(acc[sub], ah, bh0, bh1);
                        mma16816(acc[sub], ah, bl0, bl1);
                        mma16816(acc[sub], al, bh0, bh1);
                    }
                }
            } else {
                // plain fp16 single product (px path; error diluted in shift)
#pragma unroll
                for (int ks = 0; ks < 4; ++ks) {
                    const int khb = c * 128 + ks * 32;
                    unsigned ah[4];
                    unsigned a0 = sb + OFF_A_HI + (unsigned)(r0 * 528 + khb + k4 * 4);
                    ah[0] = lds32(a0);
                    ah[1] = lds32(a0 + 8 * 528);
                    ah[2] = lds32(a0 + 16);
                    ah[3] = lds32(a0 + 8 * 528 + 16);
#pragma unroll
                    for (int sub = 0; sub < 16; ++sub) {
                        unsigned nrow = (unsigned)(ng * 128 + sub * 8 + (lane >> 2));
                        unsigned rb = wb + nrow * 128;
                        unsigned o0 = ((unsigned)(ks * 32 + k4 * 4)) ^ bswz;
                        unsigned o1 = ((unsigned)(ks * 32 + k4 * 4 + 16)) ^ bswz;
                        unsigned bh0 = lds32(rb + o0), bh1 = lds32(rb + o1);
                        mma16816(acc[sub], ah, bh0, bh1);
                    }
                }
            }
            __syncthreads();  // MMA reads done before buffer reuse
        }

        // ---------------- epilogues ----------------
        if (l < 2) {
            float pe0 = 0.f, pe1 = 0.f;
#pragma unroll
            for (int sub = 0; sub < 16; ++sub) {
                int col = ng * 128 + sub * 8 + k4 * 2;
                float v0 = silu_f(acc[sub][0] + sBias[l * 256 + col]);
                float v1 = silu_f(acc[sub][1] + sBias[l * 256 + col + 1]);
                float v2 = silu_f(acc[sub][2] + sBias[l * 256 + col]);
                float v3 = silu_f(acc[sub][3] + sBias[l * 256 + col + 1]);
                if (l == 0) {
                    pe0 += v0 * sWinf[col] + v1 * sWinf[col + 1];
                    pe1 += v2 * sWinf[col] + v3 * sWinf[col + 1];
                }
                unsigned off = (unsigned)(r0 * 528 + col * 2);
                if (l == 0) {
                    unsigned hp, lp;
                    hsplit2(v0, v1, hp, lp);
                    sts32(sb + OFF_A_HI + off, hp);
                    sts32(sb + OFF_A_LO + off, lp);
                    hsplit2(v2, v3, hp, lp);
                    sts32(sb + OFF_A_HI + off + 8 * 528, hp);
                    sts32(sb + OFF_A_LO + off + 8 * 528, lp);
                } else {
                    sts32(sb + OFF_A_HI + off, hpack2(v0, v1));
                    sts32(sb + OFF_A_HI + off + 8 * 528, hpack2(v2, v3));
                }
            }
            if (l == 0) {
                pe0 += __shfl_xor_sync(0xffffffffu, pe0, 1);
                pe0 += __shfl_xor_sync(0xffffffffu, pe0, 2);
                pe1 += __shfl_xor_sync(0xffffffffu, pe1, 1);
                pe1 += __shfl_xor_sync(0xffffffffu, pe1, 2);
                if (k4 == 0) {
                    atomicAdd(&sPE[r0], pe0);
                    atomicAdd(&sPE[r0 + 8], pe1);
                }
                __syncthreads();
                if (t < 64) {
                    float z = sPE[t] + binf0;
                    float e = 1.0f / (1.0f + __expf(-z));
                    if (j0 + t == i) e = 0.f;
                    sE[t] = e;
                }
                // stage Wxo into sAux (We0 no longer needed)
                for (int idx = t; idx < 2048; idx += 256) sAux[idx] = Wxo[idx];
                __syncthreads();
                // m_i column sums
                {
                    const __half* mh = (const __half*)(smc + OFF_A_HI);
                    const __half* ml = (const __half*)(smc + OFF_A_LO);
                    float a_ = 0.f;
#pragma unroll 4
                    for (int j = 0; j < 64; ++j)
                        a_ += (__half2float(mh[j * 264 + t]) +
                               __half2float(ml[j * 264 + t])) * sE[j];
                    atomicAdd(&g_mi[i * 256 + t], a_);
                }
            }
        } else {
            float pxa0[8], pxa1[8];
#pragma unroll
            for (int hh = 0; hh < 8; ++hh) { pxa0[hh] = 0.f; pxa1[hh] = 0.f; }
#pragma unroll
            for (int sub = 0; sub < 16; ++sub) {
                int col = ng * 128 + sub * 8 + k4 * 2;
                float v0 = silu_f(acc[sub][0] + sBias[512 + col]);
                float v1 = silu_f(acc[sub][1] + sBias[512 + col + 1]);
                float v2 = silu_f(acc[sub][2] + sBias[512 + col]);
                float v3 = silu_f(acc[sub][3] + sBias[512 + col + 1]);
                const float* w0 = &sAux[col * 8];
                const float* w1 = &sAux[(col + 1) * 8];
#pragma unroll
                for (int hh = 0; hh < 8; ++hh) {
                    pxa0[hh] += v0 * w0[hh] + v1 * w1[hh];
                    pxa1[hh] += v2 * w0[hh] + v3 * w1[hh];
                }
            }
#pragma unroll
            for (int hh = 0; hh < 8; ++hh) {
                pxa0[hh] += __shfl_xor_sync(0xffffffffu, pxa0[hh], 1);
                pxa0[hh] += __shfl_xor_sync(0xffffffffu, pxa0[hh], 2);
                pxa1[hh] += __shfl_xor_sync(0xffffffffu, pxa1[hh], 1);
                pxa1[hh] += __shfl_xor_sync(0xffffffffu, pxa1[hh], 2);
            }
            if (k4 == 0) {
#pragma unroll
                for (int hh = 0; hh < 8; ++hh) {
                    atomicAdd(&sPx[r0 * 8 + hh], pxa0[hh]);
                    atomicAdd(&sPx[(r0 + 8) * 8 + hh], pxa1[hh]);
                }
            }
            __syncthreads();
            for (int p = t; p < 512; p += 256) {
                int j = p >> 3, hh = p & 7;
                float px = sPx[p] + bxo[hh];
                if (j0 + j == i) px = 0.f;
                float nrm = sqrtf(sSqn[p] + 1e-8f) + 1.0f;
                float wgt = px / nrm;
#pragma unroll
                for (int d = 0; d < 3; ++d)
                    atomicAdd(&sSh[hh * 3 + d],
                              wgt * (sXj[j * 24 + hh * 3 + d] - sXi[hh * 3 + d]));
            }
            __syncthreads();
            if (t < 24) atomicAdd(&g_shift[i * 24 + t], sSh[t]);
        }
        __syncthreads();  // epilogue A-plane writes visible to next layer MMA
    }
}

// ---------------- node kernels ----------------
__global__ void __launch_bounds__(256) hnew_kernel(
    const float* __restrict__ h, const float* __restrict__ Wh0,
    const float* __restrict__ bh0, const float* __restrict__ Wh1,
    const float* __restrict__ bh1, const float* __restrict__ Who,
    const float* __restrict__ bho, float* __restrict__ out) {
    extern __shared__ float sm[];
    float* buf0 = sm;                 // 64*384
    float* buf1 = buf0 + 64 * 384;    // 64*256
    float* ws = buf1 + 64 * 256;      // 32*256
    int r0g = blockIdx.x * 64, t = threadIdx.x;
    for (int idx = t; idx < 64 * 384; idx += 256) {
        int row = idx / 384, c = idx - row * 384;
        buf0[idx] = (c < 256) ? g_mi[(r0g + row) * 256 + c]
                              : h[(r0g + row) * 128 + (c - 256)];
    }
    __syncthreads();
    gemm64<256, true>(buf0, 384, Wh0, bh0, buf1, ws);
    gemm64<256, true>(buf1, 256, Wh1, bh1, buf0, ws);
    gemm64<128, false>(buf0, 256, Who, bho, buf1, ws);
    for (int idx = t; idx < 64 * 128; idx += 256)
        out[r0g * 128 + idx] = buf1[idx] + h[r0g * 128 + idx];
}
__global__ void xnew_kernel(const float* __restrict__ x, float* __restrict__ out) {
    int idx = blockIdx.x * 256 + threadIdx.x;
    if (idx < NN * 24) out[idx] = x[idx] + g_shift[idx] * (1.0f / 511.0f);
}

// ---------------- launch ----------------
extern "C" void kernel_launch(void* const* d_in, const int* in_sizes, int n_in,
                              void* d_out, int out_size) {
    const float* x = (const float*)d_in[0];
    const float* h = (const float*)d_in[1];
    const float* We0 = (const float*)d_in[2];
    const float* be0 = (const float*)d_in[3];
    const float* We1 = (const float*)d_in[4];
    const float* be1 = (const float*)d_in[5];
    const float* Winf = (const float*)d_in[6];
    const float* binf = (const float*)d_in[7];
    const float* Wx0 = (const float*)d_in[8];
    const float* bx0 = (const float*)d_in[9];
    const float* Wx1 = (const float*)d_in[10];
    const float* bx1 = (const float*)d_in[11];
    const float* Wxo = (const float*)d_in[12];
    const float* bxo = (const float*)d_in[13];
    const float* Wh0 = (const float*)d_in[14];
    const float* bh0 = (const float*)d_in[15];
    const float* Wh1 = (const float*)d_in[16];
    const float* bh1 = (const float*)d_in[17];
    const float* Who = (const float*)d_in[18];
    const float* bho = (const float*)d_in[19];
    float* out = (float*)d_out;  // [x_new (512*24) | h_new (512*128)]

    const int AB_SMEM = (64 * 192 + 32 * 256) * 4;
    const int HNEW_SMEM = (64 * 384 + 64 * 256 + 32 * 256) * 4;
    cudaFuncSetAttribute(edge_kernel, cudaFuncAttributeMaxDynamicSharedMemorySize,
                         EDGE_SMEM);
    cudaFuncSetAttribute(prep_ab, cudaFuncAttributeMaxDynamicSharedMemorySize, AB_SMEM);
    cudaFuncSetAttribute(hnew_kernel, cudaFuncAttributeMaxDynamicSharedMemorySize,
                         HNEW_SMEM);

    zero_kernel<<<512, 256>>>();
    prep_hc<<<NN, 192>>>(x, h);
    prep_w<<<dim3(8, 8, 3), dim3(32, 8)>>>(We1, Wx0, Wx1);
    prep_ab<<<dim3(8, 2), 256, AB_SMEM>>>(We0);
    edge_kernel<<<dim3(8, NN), 256, EDGE_SMEM>>>(x, We0, be0, be1, Winf, binf, bx0,
                                                 bx1, bxo, Wxo);
    hnew_kernel<<<8, 256, HNEW_SMEM>>>(h, Wh0, bh0, Wh1, bh1, Who, bho, out + NN * 24);
    xnew_kernel<<<48, 256>>>(x, out);
}

// round 8
// speedup vs baseline: 3.9842x; 1.5683x over previous
#include <cuda_runtime.h>
#include <cuda_fp16.h>

// EGCL_Multi via mma.sync.m16n8k16 fp16 — sm_103.
// R7: plain fp16 single product on ALL layers; smem cut to 113KB so the
// edge kernel runs 2 CTAs/SM (latency hiding was the R6 bottleneck).
#define NN 512

__device__ __align__(16) float g_hc[NN * 192];
__device__ __align__(16) float g_A[NN * 256];
__device__ __align__(16) float g_B[NN * 256];
__device__ __align__(16) float g_mi[NN * 256];
__device__ __align__(16) float g_shift[NN * 24];
// 12 chunks x 32KB (hi plane only), smem-image layout
__device__ __align__(128) char g_Wstage[393216];

// ---------------- small helpers ----------------
__device__ __forceinline__ float silu_f(float v) {
    return v * (1.0f / (1.0f + __expf(-v)));
}
__device__ __forceinline__ unsigned smem_u32(const void* p) {
    unsigned a;
    asm("{ .reg .u64 t; cvta.to.shared.u64 t, %1; cvt.u32.u64 %0, t; }"
        : "=r"(a) : "l"(p));
    return a;
}
__device__ __forceinline__ unsigned lds32(unsigned addr) {
    unsigned v;
    asm volatile("ld.shared.b32 %0, [%1];" : "=r"(v) : "r"(addr));
    return v;
}
__device__ __forceinline__ void sts32(unsigned addr, unsigned v) {
    asm volatile("st.shared.b32 [%0], %1;" :: "r"(addr), "r"(v) : "memory");
}
#define MBAR_INIT(mb, n) \
    asm volatile("mbarrier.init.shared.b64 [%0], %1;" :: "r"(mb), "r"(n) : "memory")
#define EXPECT_TX(mb, n) \
    asm volatile("mbarrier.arrive.expect_tx.shared.b64 _, [%0], %1;" \
                 :: "r"(mb), "r"(n) : "memory")
__device__ __forceinline__ void mbar_wait(unsigned mb, unsigned par) {
    asm volatile(
        "{\n\t.reg .pred P;\n"
        "WL_%=:\n\t"
        "mbarrier.try_wait.parity.acquire.cta.shared::cta.b64 P, [%0], %1, 0x989680;\n\t"
        "@P bra.uni WD_%=;\n\tbra.uni WL_%=;\nWD_%=:\n\t}"
        :: "r"(mb), "r"(par) : "memory");
}
__device__ __forceinline__ void bulk_cp(unsigned dst, const void* src, unsigned bytes,
                                        unsigned mbar) {
    asm volatile(
        "cp.async.bulk.shared::cluster.global.mbarrier::complete_tx::bytes "
        "[%0], [%1], %2, [%3];"
        :: "r"(dst), "l"(src), "r"(bytes), "r"(mbar) : "memory");
}
__device__ __forceinline__ unsigned hpack2(float a, float b) {
    __half2 h = __floats2half2_rn(a, b);
    return *(unsigned*)&h;
}
__device__ __forceinline__ void mma16816(float* d, const unsigned* a, unsigned b0,
                                         unsigned b1) {
    asm volatile(
        "mma.sync.aligned.m16n8k16.row.col.f32.f16.f16.f32 "
        "{%0,%1,%2,%3}, {%4,%5,%6,%7}, {%8,%9}, {%0,%1,%2,%3};"
        : "+f"(d[0]), "+f"(d[1]), "+f"(d[2]), "+f"(d[3])
        : "r"(a[0]), "r"(a[1]), "r"(a[2]), "r"(a[3]), "r"(b0), "r"(b1));
}

// ---------------- f32x2 SIMT gemm (node-side) ----------------
__device__ __forceinline__ unsigned long long pk2(float lo, float hi) {
    unsigned long long r;
    asm("mov.b64 %0, {%1, %2};" : "=l"(r) : "f"(lo), "f"(hi));
    return r;
}
__device__ __forceinline__ void upk2(unsigned long long v, float& lo, float& hi) {
    asm("mov.b64 {%0, %1}, %2;" : "=f"(lo), "=f"(hi) : "l"(v));
}
__device__ __forceinline__ void fma2(unsigned long long& d, unsigned long long a,
                                     unsigned long long b) {
    asm("fma.rn.f32x2 %0, %1, %2, %0;" : "+l"(d) : "l"(a), "l"(b));
}
template <int N, bool ACT>
__device__ __forceinline__ void gemm64(const float* sIn, int K,
                                       const float* __restrict__ Wg,
                                       const float* __restrict__ bias, float* out,
                                       float* ws) {
    constexpr int COLG = N / 8;
    constexpr int RPT = COLG / 4;
    const int t = threadIdx.x;
    const int nc = t % COLG, mr = t / COLG;
    const int r0 = mr * RPT, c0 = nc * 8;
    unsigned long long acc[RPT][4];
#pragma unroll
    for (int r = 0; r < RPT; r++)
#pragma unroll
        for (int p = 0; p < 4; p++) acc[r][p] = 0ULL;
    for (int kt = 0; kt < K; kt += 32) {
        __syncthreads();
        for (int idx = t; idx < 32 * N / 4; idx += 256) {
            int wr = idx / (N / 4), wc = (idx - wr * (N / 4)) * 4;
            *(float4*)&ws[wr * N + wc] = *(const float4*)&Wg[(kt + wr) * N + wc];
        }
        __syncthreads();
#pragma unroll
        for (int k4 = 0; k4 < 8; k4++) {
            float4 av[RPT];
#pragma unroll
            for (int r = 0; r < RPT; r++)
                av[r] = *(const float4*)&sIn[(r0 + r) * K + kt + k4 * 4];
#pragma unroll
            for (int kk = 0; kk < 4; kk++) {
                const float* wr_ = &ws[(k4 * 4 + kk) * N + c0];
                float4 w0 = *(const float4*)&wr_[0];
                float4 w1 = *(const float4*)&wr_[4];
                unsigned long long b0 = pk2(w0.x, w0.y), b1 = pk2(w0.z, w0.w);
                unsigned long long b2 = pk2(w1.x, w1.y), b3 = pk2(w1.z, w1.w);
#pragma unroll
                for (int r = 0; r < RPT; r++) {
                    float a = (kk == 0) ? av[r].x : (kk == 1) ? av[r].y
                            : (kk == 2) ? av[r].z : av[r].w;
                    unsigned long long a2 = pk2(a, a);
                    fma2(acc[r][0], a2, b0);
                    fma2(acc[r][1], a2, b1);
                    fma2(acc[r][2], a2, b2);
                    fma2(acc[r][3], a2, b3);
                }
            }
        }
    }
#pragma unroll
    for (int r = 0; r < RPT; r++)
#pragma unroll
        for (int p = 0; p < 4; p++) {
            float lo, hi;
            upk2(acc[r][p], lo, hi);
            int c = c0 + p * 2;
            if (bias) {
                float2 bb = *(const float2*)&bias[c];
                lo += bb.x;
                hi += bb.y;
            }
            if (ACT) { lo = silu_f(lo); hi = silu_f(hi); }
            float2 o; o.x = lo; o.y = hi;
            *(float2*)&out[(r0 + r) * N + c] = o;
        }
    __syncthreads();
}

// ---------------- prep kernels ----------------
__global__ void zero_kernel() {
    int idx = blockIdx.x * 256 + threadIdx.x;
    if (idx < NN * 256) g_mi[idx] = 0.f;
    if (idx < NN * 24) g_shift[idx] = 0.f;
}
__global__ void prep_hc(const float* __restrict__ x, const float* __restrict__ h) {
    int n = blockIdx.x, t = threadIdx.x;
    if (t < 128) g_hc[n * 192 + t] = h[n * 128 + t];
    else {
        int p = t - 128, a = p >> 3, b = p & 7;
        float dx = x[n * 24 + a * 3] - x[n * 24 + b * 3];
        float dy = x[n * 24 + a * 3 + 1] - x[n * 24 + b * 3 + 1];
        float dz = x[n * 24 + a * 3 + 2] - x[n * 24 + b * 3 + 2];
        g_hc[n * 192 + 128 + p] = dx * dx + dy * dy + dz * dz;
    }
}
// transpose + fp16 into the pre-swizzled smem-image layout (hi plane only)
__global__ void prep_w(const float* __restrict__ We1, const float* __restrict__ Wx0,
                       const float* __restrict__ Wx1) {
    __shared__ float tile[32][33];
    int sel = blockIdx.z;
    const float* W = (sel == 0) ? We1 : (sel == 1) ? Wx0 : Wx1;
    int n0 = blockIdx.x * 32, k0 = blockIdx.y * 32;
    int tx = threadIdx.x, ty = threadIdx.y;
    for (int r = ty; r < 32; r += 8) tile[r][tx] = W[(k0 + r) * 256 + n0 + tx];
    __syncthreads();
    for (int r = ty; r < 32; r += 8) {
        float v = tile[tx][r];  // = W[k0+tx][n0+r]
        int n = n0 + r, k = k0 + tx;
        int chunk = k >> 6, kin = k & 63;
        unsigned off = (unsigned)((sel * 4 + chunk) * 32768 + n * 128 +
                                  (((kin >> 3) * 16) ^ ((n & 7) * 16)) + (kin & 7) * 2);
        *(__half*)(g_Wstage + off) = __float2half_rn(v);
    }
}
__global__ void __launch_bounds__(256) prep_ab(const float* __restrict__ We0) {
    extern __shared__ float sm[];
    float* sIn = sm;
    float* ws = sm + 64 * 192;
    int r0g = blockIdx.x * 64, t = threadIdx.x;
    for (int idx = t; idx < 64 * 192 / 4; idx += 256)
        *(float4*)&sIn[idx * 4] = *(const float4*)&g_hc[r0g * 192 + idx * 4];
    __syncthreads();
    const float* Wg = We0 + (blockIdx.y == 0 ? 8 : 200) * 256;
    float* outp = (blockIdx.y == 0 ? g_A : g_B) + r0g * 256;
    gemm64<256, false>(sIn, 192, Wg, nullptr, outp, ws);
}

// ---------------- edge kernel ----------------
// smem byte offsets (total 113424 -> 2 CTAs/SM)
#define OFF_A 0          // 33792 (64 rows x 264 halves)
#define OFF_W 33792      // 65536 (2 bufs x 32KB)
#define OFF_XJ 99328     // 6144
#define OFF_SQN 105472   // 2048
#define OFF_BI 107520    // 1024 (T0 only; aliased by PX later)
#define OFF_WINF 108544  // 1024 (l0 only; aliased by PX later)
#define OFF_PX OFF_BI    // 2048 (l2 only)
#define OFF_BIAS 109568  // 3072
#define OFF_PE 112640    // 256
#define OFF_E 112896     // 256
#define OFF_XI 113152    // 128
#define OFF_SH 113280    // 128
#define OFF_MB 113408    // 16
#define EDGE_SMEM 113424

__global__ void __launch_bounds__(256, 2) edge_kernel(
    const float* __restrict__ x, const float* __restrict__ We0,
    const float* __restrict__ be0, const float* __restrict__ be1,
    const float* __restrict__ Winf, const float* __restrict__ binf,
    const float* __restrict__ bx0, const float* __restrict__ bx1,
    const float* __restrict__ bxo, const float* __restrict__ Wxo) {
    extern __shared__ char smc[];
    const unsigned sb = smem_u32(smc);
    const int t = threadIdx.x;
    const int lane = t & 31, w = t >> 5;
    const int band = w >> 1, ng = w & 1;
    const int r0 = band * 16 + (lane >> 2);
    const int k4 = lane & 3;
    const unsigned bswz = (unsigned)((lane >> 2) << 4);
    const int i = blockIdx.y, j0 = blockIdx.x * 64;

    float* sXj = (float*)(smc + OFF_XJ);
    float* sSqn = (float*)(smc + OFF_SQN);
    float* sBi = (float*)(smc + OFF_BI);
    float* sWinf = (float*)(smc + OFF_WINF);
    float* sBias = (float*)(smc + OFF_BIAS);
    float* sPE = (float*)(smc + OFF_PE);
    float* sE = (float*)(smc + OFF_E);
    float* sPx = (float*)(smc + OFF_PX);
    float* sXi = (float*)(smc + OFF_XI);
    float* sSh = (float*)(smc + OFF_SH);
    const unsigned mb0 = sb + OFF_MB, mb1 = sb + OFF_MB + 8;

    // prologue staging
    if (t == 0) { MBAR_INIT(mb0, 1); MBAR_INIT(mb1, 1); }
    for (int idx = t; idx < 1536; idx += 256) sXj[idx] = x[j0 * 24 + idx];
    sBi[t] = g_B[i * 256 + t] + be0[t];
    sWinf[t] = Winf[t];
    sBias[t] = be1[t];
    sBias[256 + t] = bx0[t];
    sBias[512 + t] = bx1[t];
    if (t < 64) sPE[t] = 0.f;
    if (t < 24) { sXi[t] = x[i * 24 + t]; sSh[t] = 0.f; }
    __syncthreads();

    // kick chunk 0 bulk copy (one thread, ~0 issue cost)
    if (t == 0) {
        EXPECT_TX(mb0, 32768u);
        bulk_cp(sb + OFF_W, g_Wstage, 32768u, mb0);
    }

    // sqn
    for (int p = t; p < 512; p += 256) {
        int j = p >> 3, hh = p & 7;
        float dx = sXj[j * 24 + hh * 3] - sXi[hh * 3];
        float dy = sXj[j * 24 + hh * 3 + 1] - sXi[hh * 3 + 1];
        float dz = sXj[j * 24 + hh * 3 + 2] - sXi[hh * 3 + 2];
        sSqn[p] = dx * dx + dy * dy + dz * dz;
    }
    __syncthreads();

    // T0 = silu(A[j] + (B[i]+be0) + sqn@We0[0:8]) -> fp16 A plane
    for (int it = 0; it < 16; ++it) {
        int idx = it * 256 + t;
        int j = idx >> 6, c = (idx & 63) * 4;
        float4 v = *(const float4*)&g_A[(j0 + j) * 256 + c];
        v.x += sBi[c]; v.y += sBi[c + 1]; v.z += sBi[c + 2]; v.w += sBi[c + 3];
#pragma unroll
        for (int q = 0; q < 8; q++) {
            float s = sSqn[j * 8 + q];
            const float* wr_ = &We0[q * 256 + c];
            v.x += s * __ldg(wr_);
            v.y += s * __ldg(wr_ + 1);
            v.z += s * __ldg(wr_ + 2);
            v.w += s * __ldg(wr_ + 3);
        }
        v.x = silu_f(v.x); v.y = silu_f(v.y); v.z = silu_f(v.z); v.w = silu_f(v.w);
        unsigned off = (unsigned)(j * 528 + c * 2);
        sts32(sb + OFF_A + off, hpack2(v.x, v.y));
        sts32(sb + OFF_A + off + 4, hpack2(v.z, v.w));
    }
    __syncthreads();  // T0 plane complete before first MMA

    const float binf0 = binf[0];

    for (int l = 0; l < 3; ++l) {
        float acc[16][4];
#pragma unroll
        for (int s2 = 0; s2 < 16; ++s2)
#pragma unroll
            for (int q = 0; q < 4; ++q) acc[s2][q] = 0.f;

        for (int c = 0; c < 4; ++c) {
            int g = l * 4 + c;
            if (g + 1 < 12 && t == 0) {
                unsigned mb = ((g + 1) & 1) ? mb1 : mb0;
                EXPECT_TX(mb, 32768u);
                bulk_cp(sb + OFF_W + (unsigned)(((g + 1) & 1) * 32768),
                        g_Wstage + (g + 1) * 32768, 32768u, mb);
            }
            mbar_wait((g & 1) ? mb1 : mb0, (g >> 1) & 1);
            const unsigned wb = sb + OFF_W + (unsigned)((g & 1) * 32768);
#pragma unroll
            for (int ks = 0; ks < 4; ++ks) {
                const int khb = c * 128 + ks * 32;
                unsigned ah[4];
                unsigned a0 = sb + OFF_A + (unsigned)(r0 * 528 + khb + k4 * 4);
                ah[0] = lds32(a0);
                ah[1] = lds32(a0 + 8 * 528);
                ah[2] = lds32(a0 + 16);
                ah[3] = lds32(a0 + 8 * 528 + 16);
#pragma unroll
                for (int sub = 0; sub < 16; ++sub) {
                    unsigned nrow = (unsigned)(ng * 128 + sub * 8 + (lane >> 2));
                    unsigned rb = wb + nrow * 128;
                    unsigned o0 = ((unsigned)(ks * 32 + k4 * 4)) ^ bswz;
                    unsigned o1 = ((unsigned)(ks * 32 + k4 * 4 + 16)) ^ bswz;
                    unsigned bh0 = lds32(rb + o0), bh1 = lds32(rb + o1);
                    mma16816(acc[sub], ah, bh0, bh1);
                }
            }
            __syncthreads();  // MMA reads done before buffer reuse
        }

        // ---------------- epilogues ----------------
        if (l < 2) {
            float pe0 = 0.f, pe1 = 0.f;
#pragma unroll
            for (int sub = 0; sub < 16; ++sub) {
                int col = ng * 128 + sub * 8 + k4 * 2;
                float v0 = silu_f(acc[sub][0] + sBias[l * 256 + col]);
                float v1 = silu_f(acc[sub][1] + sBias[l * 256 + col + 1]);
                float v2 = silu_f(acc[sub][2] + sBias[l * 256 + col]);
                float v3 = silu_f(acc[sub][3] + sBias[l * 256 + col + 1]);
                if (l == 0) {
                    pe0 += v0 * sWinf[col] + v1 * sWinf[col + 1];
                    pe1 += v2 * sWinf[col] + v3 * sWinf[col + 1];
                }
                unsigned off = (unsigned)(r0 * 528 + col * 2);
                sts32(sb + OFF_A + off, hpack2(v0, v1));
                sts32(sb + OFF_A + off + 8 * 528, hpack2(v2, v3));
            }
            if (l == 0) {
                pe0 += __shfl_xor_sync(0xffffffffu, pe0, 1);
                pe0 += __shfl_xor_sync(0xffffffffu, pe0, 2);
                pe1 += __shfl_xor_sync(0xffffffffu, pe1, 1);
                pe1 += __shfl_xor_sync(0xffffffffu, pe1, 2);
                if (k4 == 0) {
                    atomicAdd(&sPE[r0], pe0);
                    atomicAdd(&sPE[r0 + 8], pe1);
                }
                __syncthreads();
                if (t < 64) {
                    float z = sPE[t] + binf0;
                    float e = 1.0f / (1.0f + __expf(-z));
                    if (j0 + t == i) e = 0.f;
                    sE[t] = e;
                }
                __syncthreads();
                // m_i column sums (m is fp16 in the A plane)
                {
                    const __half* mh = (const __half*)(smc + OFF_A);
                    float a_ = 0.f;
#pragma unroll 4
                    for (int j = 0; j < 64; ++j)
                        a_ += __half2float(mh[j * 264 + t]) * sE[j];
                    atomicAdd(&g_mi[i * 256 + t], a_);
                }
            } else {
                // zero px accumulators (aliases BI/WINF, both now dead)
                for (int p = t; p < 512; p += 256) sPx[p] = 0.f;
            }
        } else {
            // l==2: px + shift. Stage Wxo into the (now-final) A-plane area?
            // A plane still holds u2 inputs? No: acc already holds the GEMM
            // result; A plane is dead. Reuse it for a Wxo stage.
            float* sWxo = (float*)(smc + OFF_A);
            for (int idx = t; idx < 2048; idx += 256) sWxo[idx] = Wxo[idx];
            __syncthreads();
            float pxa0[8], pxa1[8];
#pragma unroll
            for (int hh = 0; hh < 8; ++hh) { pxa0[hh] = 0.f; pxa1[hh] = 0.f; }
#pragma unroll
            for (int sub = 0; sub < 16; ++sub) {
                int col = ng * 128 + sub * 8 + k4 * 2;
                float v0 = silu_f(acc[sub][0] + sBias[512 + col]);
                float v1 = silu_f(acc[sub][1] + sBias[512 + col + 1]);
                float v2 = silu_f(acc[sub][2] + sBias[512 + col]);
                float v3 = silu_f(acc[sub][3] + sBias[512 + col + 1]);
                const float* w0 = &sWxo[col * 8];
                const float* w1 = &sWxo[(col + 1) * 8];
#pragma unroll
                for (int hh = 0; hh < 8; ++hh) {
                    pxa0[hh] += v0 * w0[hh] + v1 * w1[hh];
                    pxa1[hh] += v2 * w0[hh] + v3 * w1[hh];
                }
            }
#pragma unroll
            for (int hh = 0; hh < 8; ++hh) {
                pxa0[hh] += __shfl_xor_sync(0xffffffffu, pxa0[hh], 1);
                pxa0[hh] += __shfl_xor_sync(0xffffffffu, pxa0[hh], 2);
                pxa1[hh] += __shfl_xor_sync(0xffffffffu, pxa1[hh], 1);
                pxa1[hh] += __shfl_xor_sync(0xffffffffu, pxa1[hh], 2);
            }
            if (k4 == 0) {
#pragma unroll
                for (int hh = 0; hh < 8; ++hh) {
                    atomicAdd(&sPx[r0 * 8 + hh], pxa0[hh]);
                    atomicAdd(&sPx[(r0 + 8) * 8 + hh], pxa1[hh]);
                }
            }
            __syncthreads();
            for (int p = t; p < 512; p += 256) {
                int j = p >> 3, hh = p & 7;
                float px = sPx[p] + bxo[hh];
                if (j0 + j == i) px = 0.f;
                float nrm = sqrtf(sSqn[p] + 1e-8f) + 1.0f;
                float wgt = px / nrm;
#pragma unroll
                for (int d = 0; d < 3; ++d)
                    atomicAdd(&sSh[hh * 3 + d],
                              wgt * (sXj[j * 24 + hh * 3 + d] - sXi[hh * 3 + d]));
            }
            __syncthreads();
            if (t < 24) atomicAdd(&g_shift[i * 24 + t], sSh[t]);
        }
        __syncthreads();  // epilogue A-plane writes visible to next layer MMA
    }
}

// ---------------- node kernels ----------------
__global__ void __launch_bounds__(256) hnew_kernel(
    const float* __restrict__ h, const float* __restrict__ Wh0,
    const float* __restrict__ bh0, const float* __restrict__ Wh1,
    const float* __restrict__ bh1, const float* __restrict__ Who,
    const float* __restrict__ bho, float* __restrict__ out) {
    extern __shared__ float sm[];
    float* buf0 = sm;                 // 64*384
    float* buf1 = buf0 + 64 * 384;    // 64*256
    float* ws = buf1 + 64 * 256;      // 32*256
    int r0g = blockIdx.x * 64, t = threadIdx.x;
    for (int idx = t; idx < 64 * 384; idx += 256) {
        int row = idx / 384, c = idx - row * 384;
        buf0[idx] = (c < 256) ? g_mi[(r0g + row) * 256 + c]
                              : h[(r0g + row) * 128 + (c - 256)];
    }
    __syncthreads();
    gemm64<256, true>(buf0, 384, Wh0, bh0, buf1, ws);
    gemm64<256, true>(buf1, 256, Wh1, bh1, buf0, ws);
    gemm64<128, false>(buf0, 256, Who, bho, buf1, ws);
    for (int idx = t; idx < 64 * 128; idx += 256)
        out[r0g * 128 + idx] = buf1[idx] + h[r0g * 128 + idx];
}
__global__ void xnew_kernel(const float* __restrict__ x, float* __restrict__ out) {
    int idx = blockIdx.x * 256 + threadIdx.x;
    if (idx < NN * 24) out[idx] = x[idx] + g_shift[idx] * (1.0f / 511.0f);
}

// ---------------- launch ----------------
extern "C" void kernel_launch(void* const* d_in, const int* in_sizes, int n_in,
                              void* d_out, int out_size) {
    const float* x = (const float*)d_in[0];
    const float* h = (const float*)d_in[1];
    const float* We0 = (const float*)d_in[2];
    const float* be0 = (const float*)d_in[3];
    const float* We1 = (const float*)d_in[4];
    const float* be1 = (const float*)d_in[5];
    const float* Winf = (const float*)d_in[6];
    const float* binf = (const float*)d_in[7];
    const float* Wx0 = (const float*)d_in[8];
    const float* bx0 = (const float*)d_in[9];
    const float* Wx1 = (const float*)d_in[10];
    const float* bx1 = (const float*)d_in[11];
    const float* Wxo = (const float*)d_in[12];
    const float* bxo = (const float*)d_in[13];
    const float* Wh0 = (const float*)d_in[14];
    const float* bh0 = (const float*)d_in[15];
    const float* Wh1 = (const float*)d_in[16];
    const float* bh1 = (const float*)d_in[17];
    const float* Who = (const float*)d_in[18];
    const float* bho = (const float*)d_in[19];
    float* out = (float*)d_out;  // [x_new (512*24) | h_new (512*128)]

    const int AB_SMEM = (64 * 192 + 32 * 256) * 4;
    const int HNEW_SMEM = (64 * 384 + 64 * 256 + 32 * 256) * 4;
    cudaFuncSetAttribute(edge_kernel, cudaFuncAttributeMaxDynamicSharedMemorySize,
                         EDGE_SMEM);
    cudaFuncSetAttribute(prep_ab, cudaFuncAttributeMaxDynamicSharedMemorySize, AB_SMEM);
    cudaFuncSetAttribute(hnew_kernel, cudaFuncAttributeMaxDynamicSharedMemorySize,
                         HNEW_SMEM);

    zero_kernel<<<512, 256>>>();
    prep_hc<<<NN, 192>>>(x, h);
    prep_w<<<dim3(8, 8, 3), dim3(32, 8)>>>(We1, Wx0, Wx1);
    prep_ab<<<dim3(8, 2), 256, AB_SMEM>>>(We0);
    edge_kernel<<<dim3(8, NN), 256, EDGE_SMEM>>>(x, We0, be0, be1, Winf, binf, bx0,
                                                 bx1, bxo, Wxo);
    hnew_kernel<<<8, 256, HNEW_SMEM>>>(h, Wh0, bh0, Wh1, bh1, Who, bho, out + NN * 24);
    xnew_kernel<<<48, 256>>>(x, out);
}

// round 9
// speedup vs baseline: 3.9949x; 1.0027x over previous
#include <cuda_runtime.h>
#include <cuda_fp16.h>

// EGCL_Multi via mma.sync.m16n8k16 fp16 — sm_103.
// R8: f16 accumulators on phi_x layers (l>=1), f32 acc kept on the m layer;
// prep_ab/hnew re-tiled to 16-row tiles (4x more CTAs); float4 We0 loads.
#define NN 512

__device__ __align__(16) float g_hc[NN * 192];
__device__ __align__(16) float g_A[NN * 256];
__device__ __align__(16) float g_B[NN * 256];
__device__ __align__(16) float g_mi[NN * 256];
__device__ __align__(16) float g_shift[NN * 24];
// 12 chunks x 32KB, smem-image layout
__device__ __align__(128) char g_Wstage[393216];

// ---------------- small helpers ----------------
__device__ __forceinline__ float silu_f(float v) {
    return v * (1.0f / (1.0f + __expf(-v)));
}
__device__ __forceinline__ unsigned smem_u32(const void* p) {
    unsigned a;
    asm("{ .reg .u64 t; cvta.to.shared.u64 t, %1; cvt.u32.u64 %0, t; }"
        : "=r"(a) : "l"(p));
    return a;
}
__device__ __forceinline__ unsigned lds32(unsigned addr) {
    unsigned v;
    asm volatile("ld.shared.b32 %0, [%1];" : "=r"(v) : "r"(addr));
    return v;
}
__device__ __forceinline__ void sts32(unsigned addr, unsigned v) {
    asm volatile("st.shared.b32 [%0], %1;" :: "r"(addr), "r"(v) : "memory");
}
#define MBAR_INIT(mb, n) \
    asm volatile("mbarrier.init.shared.b64 [%0], %1;" :: "r"(mb), "r"(n) : "memory")
#define EXPECT_TX(mb, n) \
    asm volatile("mbarrier.arrive.expect_tx.shared.b64 _, [%0], %1;" \
                 :: "r"(mb), "r"(n) : "memory")
__device__ __forceinline__ void mbar_wait(unsigned mb, unsigned par) {
    asm volatile(
        "{\n\t.reg .pred P;\n"
        "WL_%=:\n\t"
        "mbarrier.try_wait.parity.acquire.cta.shared::cta.b64 P, [%0], %1, 0x989680;\n\t"
        "@P bra.uni WD_%=;\n\tbra.uni WL_%=;\nWD_%=:\n\t}"
        :: "r"(mb), "r"(par) : "memory");
}
__device__ __forceinline__ void bulk_cp(unsigned dst, const void* src, unsigned bytes,
                                        unsigned mbar) {
    asm volatile(
        "cp.async.bulk.shared::cluster.global.mbarrier::complete_tx::bytes "
        "[%0], [%1], %2, [%3];"
        :: "r"(dst), "l"(src), "r"(bytes), "r"(mbar) : "memory");
}
__device__ __forceinline__ unsigned hpack2(float a, float b) {
    __half2 h = __floats2half2_rn(a, b);
    return *(unsigned*)&h;
}
__device__ __forceinline__ void mma16816(float* d, const unsigned* a, unsigned b0,
                                         unsigned b1) {
    asm volatile(
        "mma.sync.aligned.m16n8k16.row.col.f32.f16.f16.f32 "
        "{%0,%1,%2,%3}, {%4,%5,%6,%7}, {%8,%9}, {%0,%1,%2,%3};"
        : "+f"(d[0]), "+f"(d[1]), "+f"(d[2]), "+f"(d[3])
        : "r"(a[0]), "r"(a[1]), "r"(a[2]), "r"(a[3]), "r"(b0), "r"(b1));
}
__device__ __forceinline__ void mma16816h(unsigned* d, const unsigned* a, unsigned b0,
                                          unsigned b1) {
    asm volatile(
        "mma.sync.aligned.m16n8k16.row.col.f16.f16.f16.f16 "
        "{%0,%1}, {%2,%3,%4,%5}, {%6,%7}, {%0,%1};"
        : "+r"(d[0]), "+r"(d[1])
        : "r"(a[0]), "r"(a[1]), "r"(a[2]), "r"(a[3]), "r"(b0), "r"(b1));
}

// ---------------- f32x2 SIMT gemm (node-side) ----------------
__device__ __forceinline__ unsigned long long pk2(float lo, float hi) {
    unsigned long long r;
    asm("mov.b64 %0, {%1, %2};" : "=l"(r) : "f"(lo), "f"(hi));
    return r;
}
__device__ __forceinline__ void upk2(unsigned long long v, float& lo, float& hi) {
    asm("mov.b64 {%0, %1}, %2;" : "=f"(lo), "=f"(hi) : "l"(v));
}
__device__ __forceinline__ void fma2(unsigned long long& d, unsigned long long a,
                                     unsigned long long b) {
    asm("fma.rn.f32x2 %0, %1, %2, %0;" : "+l"(d) : "l"(a), "l"(b));
}
template <int ROWS, int N, bool ACT>
__device__ __forceinline__ void gemmR(const float* sIn, int K,
                                      const float* __restrict__ Wg,
                                      const float* __restrict__ bias, float* out,
                                      float* ws) {
    constexpr int COLG = N / 8;
    constexpr int RPT = ROWS * COLG / 256;
    const int t = threadIdx.x;
    const int nc = t % COLG, mr = t / COLG;
    const int r0 = mr * RPT, c0 = nc * 8;
    unsigned long long acc[RPT][4];
#pragma unroll
    for (int r = 0; r < RPT; r++)
#pragma unroll
        for (int p = 0; p < 4; p++) acc[r][p] = 0ULL;
    for (int kt = 0; kt < K; kt += 32) {
        __syncthreads();
        for (int idx = t; idx < 32 * N / 4; idx += 256) {
            int wr = idx / (N / 4), wc = (idx - wr * (N / 4)) * 4;
            *(float4*)&ws[wr * N + wc] = *(const float4*)&Wg[(kt + wr) * N + wc];
        }
        __syncthreads();
#pragma unroll
        for (int k4 = 0; k4 < 8; k4++) {
            float4 av[RPT];
#pragma unroll
            for (int r = 0; r < RPT; r++)
                av[r] = *(const float4*)&sIn[(r0 + r) * K + kt + k4 * 4];
#pragma unroll
            for (int kk = 0; kk < 4; kk++) {
                const float* wr_ = &ws[(k4 * 4 + kk) * N + c0];
                float4 w0 = *(const float4*)&wr_[0];
                float4 w1 = *(const float4*)&wr_[4];
                unsigned long long b0 = pk2(w0.x, w0.y), b1 = pk2(w0.z, w0.w);
                unsigned long long b2 = pk2(w1.x, w1.y), b3 = pk2(w1.z, w1.w);
#pragma unroll
                for (int r = 0; r < RPT; r++) {
                    float a = (kk == 0) ? av[r].x : (kk == 1) ? av[r].y
                            : (kk == 2) ? av[r].z : av[r].w;
                    unsigned long long a2 = pk2(a, a);
                    fma2(acc[r][0], a2, b0);
                    fma2(acc[r][1], a2, b1);
                    fma2(acc[r][2], a2, b2);
                    fma2(acc[r][3], a2, b3);
                }
            }
        }
    }
#pragma unroll
    for (int r = 0; r < RPT; r++)
#pragma unroll
        for (int p = 0; p < 4; p++) {
            float lo, hi;
            upk2(acc[r][p], lo, hi);
            int c = c0 + p * 2;
            if (bias) {
                float2 bb = *(const float2*)&bias[c];
                lo += bb.x;
                hi += bb.y;
            }
            if (ACT) { lo = silu_f(lo); hi = silu_f(hi); }
            float2 o; o.x = lo; o.y = hi;
            *(float2*)&out[(r0 + r) * N + c] = o;
        }
    __syncthreads();
}

// ---------------- prep kernels ----------------
__global__ void zero_kernel() {
    int idx = blockIdx.x * 256 + threadIdx.x;
    if (idx < NN * 256) g_mi[idx] = 0.f;
    if (idx < NN * 24) g_shift[idx] = 0.f;
}
__global__ void prep_hc(const float* __restrict__ x, const float* __restrict__ h) {
    int n = blockIdx.x, t = threadIdx.x;
    if (t < 128) g_hc[n * 192 + t] = h[n * 128 + t];
    else {
        int p = t - 128, a = p >> 3, b = p & 7;
        float dx = x[n * 24 + a * 3] - x[n * 24 + b * 3];
        float dy = x[n * 24 + a * 3 + 1] - x[n * 24 + b * 3 + 1];
        float dz = x[n * 24 + a * 3 + 2] - x[n * 24 + b * 3 + 2];
        g_hc[n * 192 + 128 + p] = dx * dx + dy * dy + dz * dz;
    }
}
// transpose + fp16 into the pre-swizzled smem-image layout
__global__ void prep_w(const float* __restrict__ We1, const float* __restrict__ Wx0,
                       const float* __restrict__ Wx1) {
    __shared__ float tile[32][33];
    int sel = blockIdx.z;
    const float* W = (sel == 0) ? We1 : (sel == 1) ? Wx0 : Wx1;
    int n0 = blockIdx.x * 32, k0 = blockIdx.y * 32;
    int tx = threadIdx.x, ty = threadIdx.y;
    for (int r = ty; r < 32; r += 8) tile[r][tx] = W[(k0 + r) * 256 + n0 + tx];
    __syncthreads();
    for (int r = ty; r < 32; r += 8) {
        float v = tile[tx][r];  // = W[k0+tx][n0+r]
        int n = n0 + r, k = k0 + tx;
        int chunk = k >> 6, kin = k & 63;
        unsigned off = (unsigned)((sel * 4 + chunk) * 32768 + n * 128 +
                                  (((kin >> 3) * 16) ^ ((n & 7) * 16)) + (kin & 7) * 2);
        *(__half*)(g_Wstage + off) = __float2half_rn(v);
    }
}
__global__ void __launch_bounds__(256) prep_ab(const float* __restrict__ We0) {
    extern __shared__ float sm[];
    float* sIn = sm;              // 16*192
    float* ws = sm + 16 * 192;    // 32*256
    int r0g = blockIdx.x * 16, t = threadIdx.x;
    for (int idx = t; idx < 16 * 192 / 4; idx += 256)
        *(float4*)&sIn[idx * 4] = *(const float4*)&g_hc[r0g * 192 + idx * 4];
    __syncthreads();
    const float* Wg = We0 + (blockIdx.y == 0 ? 8 : 200) * 256;
    float* outp = (blockIdx.y == 0 ? g_A : g_B) + r0g * 256;
    gemmR<16, 256, false>(sIn, 192, Wg, nullptr, outp, ws);
}

// ---------------- edge kernel ----------------
// smem byte offsets (total 113424 -> 2 CTAs/SM)
#define OFF_A 0          // 33792 (64 rows x 264 halves)
#define OFF_W 33792      // 65536 (2 bufs x 32KB)
#define OFF_XJ 99328     // 6144
#define OFF_SQN 105472   // 2048
#define OFF_BI 107520    // 1024 (T0 only; aliased by PX later)
#define OFF_WINF 108544  // 1024 (l0 only; aliased by PX later)
#define OFF_PX OFF_BI    // 2048 (l2 only)
#define OFF_BIAS 109568  // 3072
#define OFF_PE 112640    // 256
#define OFF_E 112896     // 256
#define OFF_XI 113152    // 128
#define OFF_SH 113280    // 128
#define OFF_MB 113408    // 16
#define EDGE_SMEM 113424

__global__ void __launch_bounds__(256, 2) edge_kernel(
    const float* __restrict__ x, const float* __restrict__ We0,
    const float* __restrict__ be0, const float* __restrict__ be1,
    const float* __restrict__ Winf, const float* __restrict__ binf,
    const float* __restrict__ bx0, const float* __restrict__ bx1,
    const float* __restrict__ bxo, const float* __restrict__ Wxo) {
    extern __shared__ char smc[];
    const unsigned sb = smem_u32(smc);
    const int t = threadIdx.x;
    const int lane = t & 31, w = t >> 5;
    const int band = w >> 1, ng = w & 1;
    const int r0 = band * 16 + (lane >> 2);
    const int k4 = lane & 3;
    const unsigned bswz = (unsigned)((lane >> 2) << 4);
    const int i = blockIdx.y, j0 = blockIdx.x * 64;

    float* sXj = (float*)(smc + OFF_XJ);
    float* sSqn = (float*)(smc + OFF_SQN);
    float* sBi = (float*)(smc + OFF_BI);
    float* sWinf = (float*)(smc + OFF_WINF);
    float* sBias = (float*)(smc + OFF_BIAS);
    float* sPE = (float*)(smc + OFF_PE);
    float* sE = (float*)(smc + OFF_E);
    float* sPx = (float*)(smc + OFF_PX);
    float* sXi = (float*)(smc + OFF_XI);
    float* sSh = (float*)(smc + OFF_SH);
    const unsigned mb0 = sb + OFF_MB, mb1 = sb + OFF_MB + 8;

    // prologue staging
    if (t == 0) { MBAR_INIT(mb0, 1); MBAR_INIT(mb1, 1); }
    for (int idx = t; idx < 1536; idx += 256) sXj[idx] = x[j0 * 24 + idx];
    sBi[t] = g_B[i * 256 + t] + be0[t];
    sWinf[t] = Winf[t];
    sBias[t] = be1[t];
    sBias[256 + t] = bx0[t];
    sBias[512 + t] = bx1[t];
    if (t < 64) sPE[t] = 0.f;
    if (t < 24) { sXi[t] = x[i * 24 + t]; sSh[t] = 0.f; }
    __syncthreads();

    // kick chunk 0 bulk copy (one thread, ~0 issue cost)
    if (t == 0) {
        EXPECT_TX(mb0, 32768u);
        bulk_cp(sb + OFF_W, g_Wstage, 32768u, mb0);
    }

    // sqn
    for (int p = t; p < 512; p += 256) {
        int j = p >> 3, hh = p & 7;
        float dx = sXj[j * 24 + hh * 3] - sXi[hh * 3];
        float dy = sXj[j * 24 + hh * 3 + 1] - sXi[hh * 3 + 1];
        float dz = sXj[j * 24 + hh * 3 + 2] - sXi[hh * 3 + 2];
        sSqn[p] = dx * dx + dy * dy + dz * dz;
    }
    __syncthreads();

    // T0 = silu(A[j] + (B[i]+be0) + sqn@We0[0:8]) -> fp16 A plane
    for (int it = 0; it < 16; ++it) {
        int idx = it * 256 + t;
        int j = idx >> 6, c = (idx & 63) * 4;
        float4 v = *(const float4*)&g_A[(j0 + j) * 256 + c];
        v.x += sBi[c]; v.y += sBi[c + 1]; v.z += sBi[c + 2]; v.w += sBi[c + 3];
#pragma unroll
        for (int q = 0; q < 8; q++) {
            float s = sSqn[j * 8 + q];
            float4 w4 = __ldg((const float4*)&We0[q * 256 + c]);
            v.x += s * w4.x; v.y += s * w4.y; v.z += s * w4.z; v.w += s * w4.w;
        }
        v.x = silu_f(v.x); v.y = silu_f(v.y); v.z = silu_f(v.z); v.w = silu_f(v.w);
        unsigned off = (unsigned)(j * 528 + c * 2);
        sts32(sb + OFF_A + off, hpack2(v.x, v.y));
        sts32(sb + OFF_A + off + 4, hpack2(v.z, v.w));
    }
    __syncthreads();  // T0 plane complete before first MMA

    const float binf0 = binf[0];

    for (int l = 0; l < 3; ++l) {
        float accf[16][4];
        unsigned acch[16][2];
        if (l == 0) {
#pragma unroll
            for (int s2 = 0; s2 < 16; ++s2)
#pragma unroll
                for (int q = 0; q < 4; ++q) accf[s2][q] = 0.f;
        } else {
#pragma unroll
            for (int s2 = 0; s2 < 16; ++s2) { acch[s2][0] = 0u; acch[s2][1] = 0u; }
        }

        for (int c = 0; c < 4; ++c) {
            int g = l * 4 + c;
            if (g + 1 < 12 && t == 0) {
                unsigned mb = ((g + 1) & 1) ? mb1 : mb0;
                EXPECT_TX(mb, 32768u);
                bulk_cp(sb + OFF_W + (unsigned)(((g + 1) & 1) * 32768),
                        g_Wstage + (g + 1) * 32768, 32768u, mb);
            }
            mbar_wait((g & 1) ? mb1 : mb0, (g >> 1) & 1);
            const unsigned wb = sb + OFF_W + (unsigned)((g & 1) * 32768);
#pragma unroll
            for (int ks = 0; ks < 4; ++ks) {
                const int khb = c * 128 + ks * 32;
                unsigned ah[4];
                unsigned a0 = sb + OFF_A + (unsigned)(r0 * 528 + khb + k4 * 4);
                ah[0] = lds32(a0);
                ah[1] = lds32(a0 + 8 * 528);
                ah[2] = lds32(a0 + 16);
                ah[3] = lds32(a0 + 8 * 528 + 16);
#pragma unroll
                for (int sub = 0; sub < 16; ++sub) {
                    unsigned nrow = (unsigned)(ng * 128 + sub * 8 + (lane >> 2));
                    unsigned rb = wb + nrow * 128;
                    unsigned o0 = ((unsigned)(ks * 32 + k4 * 4)) ^ bswz;
                    unsigned o1 = ((unsigned)(ks * 32 + k4 * 4 + 16)) ^ bswz;
                    unsigned bh0 = lds32(rb + o0), bh1 = lds32(rb + o1);
                    if (l == 0) mma16816(accf[sub], ah, bh0, bh1);
                    else mma16816h(acch[sub], ah, bh0, bh1);
                }
            }
            __syncthreads();  // MMA reads done before buffer reuse
        }

        // ---------------- epilogues ----------------
        if (l == 0) {
            float pe0 = 0.f, pe1 = 0.f;
#pragma unroll
            for (int sub = 0; sub < 16; ++sub) {
                int col = ng * 128 + sub * 8 + k4 * 2;
                float v0 = silu_f(accf[sub][0] + sBias[col]);
                float v1 = silu_f(accf[sub][1] + sBias[col + 1]);
                float v2 = silu_f(accf[sub][2] + sBias[col]);
                float v3 = silu_f(accf[sub][3] + sBias[col + 1]);
                pe0 += v0 * sWinf[col] + v1 * sWinf[col + 1];
                pe1 += v2 * sWinf[col] + v3 * sWinf[col + 1];
                unsigned off = (unsigned)(r0 * 528 + col * 2);
                sts32(sb + OFF_A + off, hpack2(v0, v1));
                sts32(sb + OFF_A + off + 8 * 528, hpack2(v2, v3));
            }
            pe0 += __shfl_xor_sync(0xffffffffu, pe0, 1);
            pe0 += __shfl_xor_sync(0xffffffffu, pe0, 2);
            pe1 += __shfl_xor_sync(0xffffffffu, pe1, 1);
            pe1 += __shfl_xor_sync(0xffffffffu, pe1, 2);
            if (k4 == 0) {
                atomicAdd(&sPE[r0], pe0);
                atomicAdd(&sPE[r0 + 8], pe1);
            }
            __syncthreads();
            if (t < 64) {
                float z = sPE[t] + binf0;
                float e = 1.0f / (1.0f + __expf(-z));
                if (j0 + t == i) e = 0.f;
                sE[t] = e;
            }
            __syncthreads();
            // m_i column sums (m is fp16 in the A plane)
            {
                const __half* mh = (const __half*)(smc + OFF_A);
                float a_ = 0.f;
#pragma unroll 4
                for (int j = 0; j < 64; ++j)
                    a_ += __half2float(mh[j * 264 + t]) * sE[j];
                atomicAdd(&g_mi[i * 256 + t], a_);
            }
        } else if (l == 1) {
#pragma unroll
            for (int sub = 0; sub < 16; ++sub) {
                int col = ng * 128 + sub * 8 + k4 * 2;
                __half2 p0 = *(__half2*)&acch[sub][0];
                __half2 p1 = *(__half2*)&acch[sub][1];
                float v0 = silu_f(__low2float(p0) + sBias[256 + col]);
                float v1 = silu_f(__high2float(p0) + sBias[256 + col + 1]);
                float v2 = silu_f(__low2float(p1) + sBias[256 + col]);
                float v3 = silu_f(__high2float(p1) + sBias[256 + col + 1]);
                unsigned off = (unsigned)(r0 * 528 + col * 2);
                sts32(sb + OFF_A + off, hpack2(v0, v1));
                sts32(sb + OFF_A + off + 8 * 528, hpack2(v2, v3));
            }
            // zero px accumulators (aliases BI/WINF, both now dead)
            for (int p = t; p < 512; p += 256) sPx[p] = 0.f;
        } else {
            // l==2: px + shift. A plane is dead -> stage Wxo there.
            float* sWxo = (float*)(smc + OFF_A);
            for (int idx = t; idx < 2048; idx += 256) sWxo[idx] = Wxo[idx];
            __syncthreads();
            float pxa0[8], pxa1[8];
#pragma unroll
            for (int hh = 0; hh < 8; ++hh) { pxa0[hh] = 0.f; pxa1[hh] = 0.f; }
#pragma unroll
            for (int sub = 0; sub < 16; ++sub) {
                int col = ng * 128 + sub * 8 + k4 * 2;
                __half2 p0 = *(__half2*)&acch[sub][0];
                __half2 p1 = *(__half2*)&acch[sub][1];
                float v0 = silu_f(__low2float(p0) + sBias[512 + col]);
                float v1 = silu_f(__high2float(p0) + sBias[512 + col + 1]);
                float v2 = silu_f(__low2float(p1) + sBias[512 + col]);
                float v3 = silu_f(__high2float(p1) + sBias[512 + col + 1]);
                const float* w0 = &sWxo[col * 8];
                const float* w1 = &sWxo[(col + 1) * 8];
#pragma unroll
                for (int hh = 0; hh < 8; ++hh) {
                    pxa0[hh] += v0 * w0[hh] + v1 * w1[hh];
                    pxa1[hh] += v2 * w0[hh] + v3 * w1[hh];
                }
            }
#pragma unroll
            for (int hh = 0; hh < 8; ++hh) {
                pxa0[hh] += __shfl_xor_sync(0xffffffffu, pxa0[hh], 1);
                pxa0[hh] += __shfl_xor_sync(0xffffffffu, pxa0[hh], 2);
                pxa1[hh] += __shfl_xor_sync(0xffffffffu, pxa1[hh], 1);
                pxa1[hh] += __shfl_xor_sync(0xffffffffu, pxa1[hh], 2);
            }
            if (k4 == 0) {
#pragma unroll
                for (int hh = 0; hh < 8; ++hh) {
                    atomicAdd(&sPx[r0 * 8 + hh], pxa0[hh]);
                    atomicAdd(&sPx[(r0 + 8) * 8 + hh], pxa1[hh]);
                }
            }
            __syncthreads();
            for (int p = t; p < 512; p += 256) {
                int j = p >> 3, hh = p & 7;
                float px = sPx[p] + bxo[hh];
                if (j0 + j == i) px = 0.f;
                float nrm = sqrtf(sSqn[p] + 1e-8f) + 1.0f;
                float wgt = px / nrm;
#pragma unroll
                for (int d = 0; d < 3; ++d)
                    atomicAdd(&sSh[hh * 3 + d],
                              wgt * (sXj[j * 24 + hh * 3 + d] - sXi[hh * 3 + d]));
            }
            __syncthreads();
            if (t < 24) atomicAdd(&g_shift[i * 24 + t], sSh[t]);
        }
        __syncthreads();  // epilogue A-plane writes visible to next layer MMA
    }
}

// ---------------- node kernels ----------------
__global__ void __launch_bounds__(256) hnew_kernel(
    const float* __restrict__ h, const float* __restrict__ Wh0,
    const float* __restrict__ bh0, const float* __restrict__ Wh1,
    const float* __restrict__ bh1, const float* __restrict__ Who,
    const float* __restrict__ bho, float* __restrict__ out) {
    extern __shared__ float sm[];
    float* buf0 = sm;                 // 16*384
    float* buf1 = buf0 + 16 * 384;    // 16*256
    float* ws = buf1 + 16 * 256;      // 32*256
    int r0g = blockIdx.x * 16, t = threadIdx.x;
    for (int idx = t; idx < 16 * 384; idx += 256) {
        int row = idx / 384, c = idx - row * 384;
        buf0[idx] = (c < 256) ? g_mi[(r0g + row) * 256 + c]
                              : h[(r0g + row) * 128 + (c - 256)];
    }
    __syncthreads();
    gemmR<16, 256, true>(buf0, 384, Wh0, bh0, buf1, ws);
    gemmR<16, 256, true>(buf1, 256, Wh1, bh1, buf0, ws);
    gemmR<16, 128, false>(buf0, 256, Who, bho, buf1, ws);
    for (int idx = t; idx < 16 * 128; idx += 256)
        out[r0g * 128 + idx] = buf1[idx] + h[r0g * 128 + idx];
}
__global__ void xnew_kernel(const float* __restrict__ x, float* __restrict__ out) {
    int idx = blockIdx.x * 256 + threadIdx.x;
    if (idx < NN * 24) out[idx] = x[idx] + g_shift[idx] * (1.0f / 511.0f);
}

// ---------------- launch ----------------
extern "C" void kernel_launch(void* const* d_in, const int* in_sizes, int n_in,
                              void* d_out, int out_size) {
    const float* x = (const float*)d_in[0];
    const float* h = (const float*)d_in[1];
    const float* We0 = (const float*)d_in[2];
    const float* be0 = (const float*)d_in[3];
    const float* We1 = (const float*)d_in[4];
    const float* be1 = (const float*)d_in[5];
    const float* Winf = (const float*)d_in[6];
    const float* binf = (const float*)d_in[7];
    const float* Wx0 = (const float*)d_in[8];
    const float* bx0 = (const float*)d_in[9];
    const float* Wx1 = (const float*)d_in[10];
    const float* bx1 = (const float*)d_in[11];
    const float* Wxo = (const float*)d_in[12];
    const float* bxo = (const float*)d_in[13];
    const float* Wh0 = (const float*)d_in[14];
    const float* bh0 = (const float*)d_in[15];
    const float* Wh1 = (const float*)d_in[16];
    const float* bh1 = (const float*)d_in[17];
    const float* Who = (const float*)d_in[18];
    const float* bho = (const float*)d_in[19];
    float* out = (float*)d_out;  // [x_new (512*24) | h_new (512*128)]

    const int AB_SMEM = (16 * 192 + 32 * 256) * 4;
    const int HNEW_SMEM = (16 * 384 + 16 * 256 + 32 * 256) * 4;
    cudaFuncSetAttribute(edge_kernel, cudaFuncAttributeMaxDynamicSharedMemorySize,
                         EDGE_SMEM);
    cudaFuncSetAttribute(prep_ab, cudaFuncAttributeMaxDynamicSharedMemorySize, AB_SMEM);
    cudaFuncSetAttribute(hnew_kernel, cudaFuncAttributeMaxDynamicSharedMemorySize,
                         HNEW_SMEM);

    zero_kernel<<<512, 256>>>();
    prep_hc<<<NN, 192>>>(x, h);
    prep_w<<<dim3(8, 8, 3), dim3(32, 8)>>>(We1, Wx0, Wx1);
    prep_ab<<<dim3(32, 2), 256, AB_SMEM>>>(We0);
    edge_kernel<<<dim3(8, NN), 256, EDGE_SMEM>>>(x, We0, be0, be1, Winf, binf, bx0,
                                                 bx1, bxo, Wxo);
    hnew_kernel<<<32, 256, HNEW_SMEM>>>(h, Wh0, bh0, Wh1, bh1, Who, bho, out + NN * 24);
    xnew_kernel<<<48, 256>>>(x, out);
}

// round 11
// speedup vs baseline: 4.4850x; 1.1227x over previous
#include <cuda_runtime.h>
#include <cuda_fp16.h>

// EGCL_Multi — sm_103. R10: layer0 (m) fp16 m16n8k16 f32acc; layers 1-2
// (phi_x) fp8 e4m3 m16n8k32 (half the MMA instrs + half the weight bytes).
// Fix vs R9: e4m3x2 cvt destination is .b16 ("=h"), not .b32.
#define NN 512

__device__ __align__(16) float g_hc[NN * 192];
__device__ __align__(16) float g_A[NN * 256];
__device__ __align__(16) float g_B[NN * 256];
__device__ __align__(16) float g_mi[NN * 256];
__device__ __align__(16) float g_shift[NN * 24];
// chunks 0-3: fp16 We1 32KB each (offset 0); chunks 4-11: fp8 Wx0/Wx1 16KB each
// (offset 131072)
__device__ __align__(128) char g_Wstage[262144];

// ---------------- small helpers ----------------
__device__ __forceinline__ float silu_f(float v) {
    return v * (1.0f / (1.0f + __expf(-v)));
}
__device__ __forceinline__ unsigned smem_u32(const void* p) {
    unsigned a;
    asm("{ .reg .u64 t; cvta.to.shared.u64 t, %1; cvt.u32.u64 %0, t; }"
        : "=r"(a) : "l"(p));
    return a;
}
__device__ __forceinline__ unsigned lds32(unsigned addr) {
    unsigned v;
    asm volatile("ld.shared.b32 %0, [%1];" : "=r"(v) : "r"(addr));
    return v;
}
__device__ __forceinline__ void sts32(unsigned addr, unsigned v) {
    asm volatile("st.shared.b32 [%0], %1;" :: "r"(addr), "r"(v) : "memory");
}
__device__ __forceinline__ void sts16(unsigned addr, unsigned short v) {
    asm volatile("st.shared.u16 [%0], %1;" :: "r"(addr), "h"(v) : "memory");
}
#define MBAR_INIT(mb, n) \
    asm volatile("mbarrier.init.shared.b64 [%0], %1;" :: "r"(mb), "r"(n) : "memory")
#define EXPECT_TX(mb, n) \
    asm volatile("mbarrier.arrive.expect_tx.shared.b64 _, [%0], %1;" \
                 :: "r"(mb), "r"(n) : "memory")
__device__ __forceinline__ void mbar_wait(unsigned mb, unsigned par) {
    asm volatile(
        "{\n\t.reg .pred P;\n"
        "WL_%=:\n\t"
        "mbarrier.try_wait.parity.acquire.cta.shared::cta.b64 P, [%0], %1, 0x989680;\n\t"
        "@P bra.uni WD_%=;\n\tbra.uni WL_%=;\nWD_%=:\n\t}"
        :: "r"(mb), "r"(par) : "memory");
}
__device__ __forceinline__ void bulk_cp(unsigned dst, const void* src, unsigned bytes,
                                        unsigned mbar) {
    asm volatile(
        "cp.async.bulk.shared::cluster.global.mbarrier::complete_tx::bytes "
        "[%0], [%1], %2, [%3];"
        :: "r"(dst), "l"(src), "r"(bytes), "r"(mbar) : "memory");
}
__device__ __forceinline__ unsigned hpack2(float a, float b) {
    __half2 h = __floats2half2_rn(a, b);
    return *(unsigned*)&h;
}
// pack (lo, hi) floats -> e4m3x2 in a .b16 (lo in byte0)
__device__ __forceinline__ unsigned short f8pack2(float lo, float hi) {
    unsigned short q;
    asm("cvt.rn.satfinite.e4m3x2.f32 %0, %1, %2;" : "=h"(q) : "f"(hi), "f"(lo));
    return q;
}
__device__ __forceinline__ void mma16816(float* d, const unsigned* a, unsigned b0,
                                         unsigned b1) {
    asm volatile(
        "mma.sync.aligned.m16n8k16.row.col.f32.f16.f16.f32 "
        "{%0,%1,%2,%3}, {%4,%5,%6,%7}, {%8,%9}, {%0,%1,%2,%3};"
        : "+f"(d[0]), "+f"(d[1]), "+f"(d[2]), "+f"(d[3])
        : "r"(a[0]), "r"(a[1]), "r"(a[2]), "r"(a[3]), "r"(b0), "r"(b1));
}
__device__ __forceinline__ void mma16832f8(float* d, const unsigned* a, unsigned b0,
                                           unsigned b1) {
    asm volatile(
        "mma.sync.aligned.m16n8k32.row.col.f32.e4m3.e4m3.f32 "
        "{%0,%1,%2,%3}, {%4,%5,%6,%7}, {%8,%9}, {%0,%1,%2,%3};"
        : "+f"(d[0]), "+f"(d[1]), "+f"(d[2]), "+f"(d[3])
        : "r"(a[0]), "r"(a[1]), "r"(a[2]), "r"(a[3]), "r"(b0), "r"(b1));
}

// ---------------- f32x2 SIMT gemm (node-side) ----------------
__device__ __forceinline__ unsigned long long pk2(float lo, float hi) {
    unsigned long long r;
    asm("mov.b64 %0, {%1, %2};" : "=l"(r) : "f"(lo), "f"(hi));
    return r;
}
__device__ __forceinline__ void upk2(unsigned long long v, float& lo, float& hi) {
    asm("mov.b64 {%0, %1}, %2;" : "=f"(lo), "=f"(hi) : "l"(v));
}
__device__ __forceinline__ void fma2(unsigned long long& d, unsigned long long a,
                                     unsigned long long b) {
    asm("fma.rn.f32x2 %0, %1, %2, %0;" : "+l"(d) : "l"(a), "l"(b));
}
template <int ROWS, int N, bool ACT>
__device__ __forceinline__ void gemmR(const float* sIn, int K,
                                      const float* __restrict__ Wg,
                                      const float* __restrict__ bias, float* out,
                                      float* ws) {
    constexpr int COLG = N / 8;
    constexpr int RPT = ROWS * COLG / 256;
    const int t = threadIdx.x;
    const int nc = t % COLG, mr = t / COLG;
    const int r0 = mr * RPT, c0 = nc * 8;
    unsigned long long acc[RPT][4];
#pragma unroll
    for (int r = 0; r < RPT; r++)
#pragma unroll
        for (int p = 0; p < 4; p++) acc[r][p] = 0ULL;
    for (int kt = 0; kt < K; kt += 32) {
        __syncthreads();
        for (int idx = t; idx < 32 * N / 4; idx += 256) {
            int wr = idx / (N / 4), wc = (idx - wr * (N / 4)) * 4;
            *(float4*)&ws[wr * N + wc] = *(const float4*)&Wg[(kt + wr) * N + wc];
        }
        __syncthreads();
#pragma unroll
        for (int k4 = 0; k4 < 8; k4++) {
            float4 av[RPT];
#pragma unroll
            for (int r = 0; r < RPT; r++)
                av[r] = *(const float4*)&sIn[(r0 + r) * K + kt + k4 * 4];
#pragma unroll
            for (int kk = 0; kk < 4; kk++) {
                const float* wr_ = &ws[(k4 * 4 + kk) * N + c0];
                float4 w0 = *(const float4*)&wr_[0];
                float4 w1 = *(const float4*)&wr_[4];
                unsigned long long b0 = pk2(w0.x, w0.y), b1 = pk2(w0.z, w0.w);
                unsigned long long b2 = pk2(w1.x, w1.y), b3 = pk2(w1.z, w1.w);
#pragma unroll
                for (int r = 0; r < RPT; r++) {
                    float a = (kk == 0) ? av[r].x : (kk == 1) ? av[r].y
                            : (kk == 2) ? av[r].z : av[r].w;
                    unsigned long long a2 = pk2(a, a);
                    fma2(acc[r][0], a2, b0);
                    fma2(acc[r][1], a2, b1);
                    fma2(acc[r][2], a2, b2);
                    fma2(acc[r][3], a2, b3);
                }
            }
        }
    }
#pragma unroll
    for (int r = 0; r < RPT; r++)
#pragma unroll
        for (int p = 0; p < 4; p++) {
            float lo, hi;
            upk2(acc[r][p], lo, hi);
            int c = c0 + p * 2;
            if (bias) {
                float2 bb = *(const float2*)&bias[c];
                lo += bb.x;
                hi += bb.y;
            }
            if (ACT) { lo = silu_f(lo); hi = silu_f(hi); }
            float2 o; o.x = lo; o.y = hi;
            *(float2*)&out[(r0 + r) * N + c] = o;
        }
    __syncthreads();
}

// ---------------- prep kernels ----------------
__global__ void zero_kernel() {
    int idx = blockIdx.x * 256 + threadIdx.x;
    if (idx < NN * 256) g_mi[idx] = 0.f;
    if (idx < NN * 24) g_shift[idx] = 0.f;
}
__global__ void prep_hc(const float* __restrict__ x, const float* __restrict__ h) {
    int n = blockIdx.x, t = threadIdx.x;
    if (t < 128) g_hc[n * 192 + t] = h[n * 128 + t];
    else {
        int p = t - 128, a = p >> 3, b = p & 7;
        float dx = x[n * 24 + a * 3] - x[n * 24 + b * 3];
        float dy = x[n * 24 + a * 3 + 1] - x[n * 24 + b * 3 + 1];
        float dz = x[n * 24 + a * 3 + 2] - x[n * 24 + b * 3 + 2];
        g_hc[n * 192 + 128 + p] = dx * dx + dy * dy + dz * dz;
    }
}
// transpose + stage: sel0 -> fp16 swizzled image, sel1/2 -> fp8 e4m3 image
__global__ void prep_w(const float* __restrict__ We1, const float* __restrict__ Wx0,
                       const float* __restrict__ Wx1) {
    __shared__ float tile[32][33];
    int sel = blockIdx.z;
    const float* W = (sel == 0) ? We1 : (sel == 1) ? Wx0 : Wx1;
    int n0 = blockIdx.x * 32, k0 = blockIdx.y * 32;
    int tx = threadIdx.x, ty = threadIdx.y;
    for (int r = ty; r < 32; r += 8) tile[r][tx] = W[(k0 + r) * 256 + n0 + tx];
    __syncthreads();
    for (int r = ty; r < 32; r += 8) {
        float v = tile[tx][r];  // = W[k0+tx][n0+r]
        int n = n0 + r, k = k0 + tx;
        int chunk = k >> 6, kin = k & 63;
        if (sel == 0) {
            unsigned off = (unsigned)(chunk * 32768 + n * 128 +
                                      (((kin >> 3) * 16) ^ ((n & 7) * 16)) +
                                      (kin & 7) * 2);
            *(__half*)(g_Wstage + off) = __float2half_rn(v);
        } else {
            unsigned u = (unsigned)((kin >> 4) ^ ((n >> 1) & 3));
            unsigned off = (unsigned)(131072 + ((sel - 1) * 4 + chunk) * 16384 +
                                      n * 64 + u * 16 + (kin & 15));
            g_Wstage[off] = (char)(f8pack2(v, 0.f) & 0xff);
        }
    }
}
__global__ void __launch_bounds__(256) prep_ab(const float* __restrict__ We0) {
    extern __shared__ float sm[];
    float* sIn = sm;              // 16*192
    float* ws = sm + 16 * 192;    // 32*256
    int r0g = blockIdx.x * 16, t = threadIdx.x;
    for (int idx = t; idx < 16 * 192 / 4; idx += 256)
        *(float4*)&sIn[idx * 4] = *(const float4*)&g_hc[r0g * 192 + idx * 4];
    __syncthreads();
    const float* Wg = We0 + (blockIdx.y == 0 ? 8 : 200) * 256;
    float* outp = (blockIdx.y == 0 ? g_A : g_B) + r0g * 256;
    gemmR<16, 256, false>(sIn, 192, Wg, nullptr, outp, ws);
}

// ---------------- edge kernel ----------------
// smem byte offsets (total 113424 -> 2 CTAs/SM)
#define OFF_A 0          // 33792 (fp16 plane: 64 rows x 264 halves)
#define OFF_W 33792      // l0: 2x32KB fp16 bufs; l>=1: 2x16KB fp8 bufs
#define OFF_A8 66560     // 17408 (fp8 act plane: 64 rows x 272B) inside W region
#define OFF_XJ 99328     // 6144
#define OFF_SQN 105472   // 2048
#define OFF_BI 107520    // 1024 (T0 only; aliased by PX later)
#define OFF_WINF 108544  // 1024 (l0 only; aliased by PX later)
#define OFF_PX OFF_BI    // 2048 (l2 only)
#define OFF_BIAS 109568  // 3072
#define OFF_PE 112640    // 256
#define OFF_E 112896     // 256
#define OFF_XI 113152    // 128
#define OFF_SH 113280    // 128
#define OFF_MB 113408    // 16
#define EDGE_SMEM 113424

__global__ void __launch_bounds__(256, 2) edge_kernel(
    const float* __restrict__ x, const float* __restrict__ We0,
    const float* __restrict__ be0, const float* __restrict__ be1,
    const float* __restrict__ Winf, const float* __restrict__ binf,
    const float* __restrict__ bx0, const float* __restrict__ bx1,
    const float* __restrict__ bxo, const float* __restrict__ Wxo) {
    extern __shared__ char smc[];
    const unsigned sb = smem_u32(smc);
    const int t = threadIdx.x;
    const int lane = t & 31, w = t >> 5;
    const int band = w >> 1, ng = w & 1;
    const int r0 = band * 16 + (lane >> 2);
    const int k4 = lane & 3;
    const unsigned bswz = (unsigned)((lane >> 2) << 4);
    const int i = blockIdx.y, j0 = blockIdx.x * 64;

    float* sXj = (float*)(smc + OFF_XJ);
    float* sSqn = (float*)(smc + OFF_SQN);
    float* sBi = (float*)(smc + OFF_BI);
    float* sWinf = (float*)(smc + OFF_WINF);
    float* sBias = (float*)(smc + OFF_BIAS);
    float* sPE = (float*)(smc + OFF_PE);
    float* sE = (float*)(smc + OFF_E);
    float* sPx = (float*)(smc + OFF_PX);
    float* sXi = (float*)(smc + OFF_XI);
    float* sSh = (float*)(smc + OFF_SH);
    const unsigned mb0 = sb + OFF_MB, mb1 = sb + OFF_MB + 8;

    // prologue staging
    if (t == 0) { MBAR_INIT(mb0, 1); MBAR_INIT(mb1, 1); }
    for (int idx = t; idx < 1536; idx += 256) sXj[idx] = x[j0 * 24 + idx];
    sBi[t] = g_B[i * 256 + t] + be0[t];
    sWinf[t] = Winf[t];
    sBias[t] = be1[t];
    sBias[256 + t] = bx0[t];
    sBias[512 + t] = bx1[t];
    if (t < 64) sPE[t] = 0.f;
    if (t < 24) { sXi[t] = x[i * 24 + t]; sSh[t] = 0.f; }
    __syncthreads();

    // kick chunk 0 bulk copy
    if (t == 0) {
        EXPECT_TX(mb0, 32768u);
        bulk_cp(sb + OFF_W, g_Wstage, 32768u, mb0);
    }

    // sqn
    for (int p = t; p < 512; p += 256) {
        int j = p >> 3, hh = p & 7;
        float dx = sXj[j * 24 + hh * 3] - sXi[hh * 3];
        float dy = sXj[j * 24 + hh * 3 + 1] - sXi[hh * 3 + 1];
        float dz = sXj[j * 24 + hh * 3 + 2] - sXi[hh * 3 + 2];
        sSqn[p] = dx * dx + dy * dy + dz * dz;
    }
    __syncthreads();

    // T0 = silu(A[j] + (B[i]+be0) + sqn@We0[0:8]) -> fp16 A plane
    for (int it = 0; it < 16; ++it) {
        int idx = it * 256 + t;
        int j = idx >> 6, c = (idx & 63) * 4;
        float4 v = *(const float4*)&g_A[(j0 + j) * 256 + c];
        v.x += sBi[c]; v.y += sBi[c + 1]; v.z += sBi[c + 2]; v.w += sBi[c + 3];
#pragma unroll
        for (int q = 0; q < 8; q++) {
            float s = sSqn[j * 8 + q];
            float4 w4 = __ldg((const float4*)&We0[q * 256 + c]);
            v.x += s * w4.x; v.y += s * w4.y; v.z += s * w4.z; v.w += s * w4.w;
        }
        v.x = silu_f(v.x); v.y = silu_f(v.y); v.z = silu_f(v.z); v.w = silu_f(v.w);
        unsigned off = (unsigned)(j * 528 + c * 2);
        sts32(sb + OFF_A + off, hpack2(v.x, v.y));
        sts32(sb + OFF_A + off + 4, hpack2(v.z, v.w));
    }
    __syncthreads();  // T0 plane complete before first MMA

    const float binf0 = binf[0];

    for (int l = 0; l < 3; ++l) {
        float accf[16][4];
#pragma unroll
        for (int s2 = 0; s2 < 16; ++s2)
#pragma unroll
            for (int q = 0; q < 4; ++q) accf[s2][q] = 0.f;

        for (int c = 0; c < 4; ++c) {
            int g = l * 4 + c;
            int gn = g + 1;
            if (gn < 12 && t == 0) {
                unsigned mb = (gn & 1) ? mb1 : mb0;
                if (gn < 4) {
                    EXPECT_TX(mb, 32768u);
                    bulk_cp(sb + OFF_W + (unsigned)((gn & 1) * 32768),
                            g_Wstage + gn * 32768, 32768u, mb);
                } else {
                    EXPECT_TX(mb, 16384u);
                    bulk_cp(sb + OFF_W + (unsigned)((gn & 1) * 16384),
                            g_Wstage + 131072 + (gn - 4) * 16384, 16384u, mb);
                }
            }
            mbar_wait((g & 1) ? mb1 : mb0, (g >> 1) & 1);
            if (l == 0) {
                const unsigned wb = sb + OFF_W + (unsigned)((g & 1) * 32768);
#pragma unroll
                for (int ks = 0; ks < 4; ++ks) {
                    const int khb = c * 128 + ks * 32;
                    unsigned ah[4];
                    unsigned a0 = sb + OFF_A + (unsigned)(r0 * 528 + khb + k4 * 4);
                    ah[0] = lds32(a0);
                    ah[1] = lds32(a0 + 8 * 528);
                    ah[2] = lds32(a0 + 16);
                    ah[3] = lds32(a0 + 8 * 528 + 16);
#pragma unroll
                    for (int sub = 0; sub < 16; ++sub) {
                        unsigned nrow = (unsigned)(ng * 128 + sub * 8 + (lane >> 2));
                        unsigned rb = wb + nrow * 128;
                        unsigned o0 = ((unsigned)(ks * 32 + k4 * 4)) ^ bswz;
                        unsigned o1 = ((unsigned)(ks * 32 + k4 * 4 + 16)) ^ bswz;
                        mma16816(accf[sub], ah, lds32(rb + o0), lds32(rb + o1));
                    }
                }
            } else {
                const unsigned wb = sb + OFF_W + (unsigned)((g & 1) * 16384);
#pragma unroll
                for (int ks = 0; ks < 2; ++ks) {
                    unsigned ah[4];
                    unsigned a0 = sb + OFF_A8 +
                                  (unsigned)(r0 * 272 + c * 64 + ks * 32 + k4 * 4);
                    ah[0] = lds32(a0);
                    ah[1] = lds32(a0 + 8 * 272);
                    ah[2] = lds32(a0 + 16);
                    ah[3] = lds32(a0 + 8 * 272 + 16);
#pragma unroll
                    for (int sub = 0; sub < 16; ++sub) {
                        unsigned nrow = (unsigned)(ng * 128 + sub * 8 + (lane >> 2));
                        unsigned rb = wb + nrow * 64;
                        unsigned s_ = (nrow >> 1) & 3u;
                        unsigned b0 = lds32(rb + (((unsigned)(ks * 2)) ^ s_) * 16 +
                                            k4 * 4);
                        unsigned b1 = lds32(rb + (((unsigned)(ks * 2 + 1)) ^ s_) * 16 +
                                            k4 * 4);
                        mma16832f8(accf[sub], ah, b0, b1);
                    }
                }
            }
            __syncthreads();  // MMA reads done before buffer reuse
        }

        // ---------------- epilogues ----------------
        if (l == 0) {
            float pe0 = 0.f, pe1 = 0.f;
#pragma unroll
            for (int sub = 0; sub < 16; ++sub) {
                int col = ng * 128 + sub * 8 + k4 * 2;
                float v0 = silu_f(accf[sub][0] + sBias[col]);
                float v1 = silu_f(accf[sub][1] + sBias[col + 1]);
                float v2 = silu_f(accf[sub][2] + sBias[col]);
                float v3 = silu_f(accf[sub][3] + sBias[col + 1]);
                pe0 += v0 * sWinf[col] + v1 * sWinf[col + 1];
                pe1 += v2 * sWinf[col] + v3 * sWinf[col + 1];
                unsigned off = (unsigned)(r0 * 528 + col * 2);
                sts32(sb + OFF_A + off, hpack2(v0, v1));
                sts32(sb + OFF_A + off + 8 * 528, hpack2(v2, v3));
                unsigned a8 = sb + OFF_A8 + (unsigned)(r0 * 272 + col);
                sts16(a8, f8pack2(v0, v1));
                sts16(a8 + 8 * 272, f8pack2(v2, v3));
            }
            pe0 += __shfl_xor_sync(0xffffffffu, pe0, 1);
            pe0 += __shfl_xor_sync(0xffffffffu, pe0, 2);
            pe1 += __shfl_xor_sync(0xffffffffu, pe1, 1);
            pe1 += __shfl_xor_sync(0xffffffffu, pe1, 2);
            if (k4 == 0) {
                atomicAdd(&sPE[r0], pe0);
                atomicAdd(&sPE[r0 + 8], pe1);
            }
            __syncthreads();
            if (t < 64) {
                float z = sPE[t] + binf0;
                float e = 1.0f / (1.0f + __expf(-z));
                if (j0 + t == i) e = 0.f;
                sE[t] = e;
            }
            __syncthreads();
            // m_i column sums (fp16 plane)
            {
                const __half* mh = (const __half*)(smc + OFF_A);
                float a_ = 0.f;
#pragma unroll 4
                for (int j = 0; j < 64; ++j)
                    a_ += __half2float(mh[j * 264 + t]) * sE[j];
                atomicAdd(&g_mi[i * 256 + t], a_);
            }
        } else if (l == 1) {
#pragma unroll
            for (int sub = 0; sub < 16; ++sub) {
                int col = ng * 128 + sub * 8 + k4 * 2;
                float v0 = silu_f(accf[sub][0] + sBias[256 + col]);
                float v1 = silu_f(accf[sub][1] + sBias[256 + col + 1]);
                float v2 = silu_f(accf[sub][2] + sBias[256 + col]);
                float v3 = silu_f(accf[sub][3] + sBias[256 + col + 1]);
                unsigned a8 = sb + OFF_A8 + (unsigned)(r0 * 272 + col);
                sts16(a8, f8pack2(v0, v1));
                sts16(a8 + 8 * 272, f8pack2(v2, v3));
            }
            // zero px accumulators (aliases BI/WINF, both now dead)
            for (int p = t; p < 512; p += 256) sPx[p] = 0.f;
        } else {
            // l==2: px + shift. fp16 A plane is dead -> stage Wxo there.
            float* sWxo = (float*)(smc + OFF_A);
            for (int idx = t; idx < 2048; idx += 256) sWxo[idx] = Wxo[idx];
            __syncthreads();
            float pxa0[8], pxa1[8];
#pragma unroll
            for (int hh = 0; hh < 8; ++hh) { pxa0[hh] = 0.f; pxa1[hh] = 0.f; }
#pragma unroll
            for (int sub = 0; sub < 16; ++sub) {
                int col = ng * 128 + sub * 8 + k4 * 2;
                float v0 = silu_f(accf[sub][0] + sBias[512 + col]);
                float v1 = silu_f(accf[sub][1] + sBias[512 + col + 1]);
                float v2 = silu_f(accf[sub][2] + sBias[512 + col]);
                float v3 = silu_f(accf[sub][3] + sBias[512 + col + 1]);
                const float* w0 = &sWxo[col * 8];
                const float* w1 = &sWxo[(col + 1) * 8];
#pragma unroll
                for (int hh = 0; hh < 8; ++hh) {
                    pxa0[hh] += v0 * w0[hh] + v1 * w1[hh];
                    pxa1[hh] += v2 * w0[hh] + v3 * w1[hh];
                }
            }
#pragma unroll
            for (int hh = 0; hh < 8; ++hh) {
                pxa0[hh] += __shfl_xor_sync(0xffffffffu, pxa0[hh], 1);
                pxa0[hh] += __shfl_xor_sync(0xffffffffu, pxa0[hh], 2);
                pxa1[hh] += __shfl_xor_sync(0xffffffffu, pxa1[hh], 1);
                pxa1[hh] += __shfl_xor_sync(0xffffffffu, pxa1[hh], 2);
            }
            if (k4 == 0) {
#pragma unroll
                for (int hh = 0; hh < 8; ++hh) {
                    atomicAdd(&sPx[r0 * 8 + hh], pxa0[hh]);
                    atomicAdd(&sPx[(r0 + 8) * 8 + hh], pxa1[hh]);
                }
            }
            __syncthreads();
            for (int p = t; p < 512; p += 256) {
                int j = p >> 3, hh = p & 7;
                float px = sPx[p] + bxo[hh];
                if (j0 + j == i) px = 0.f;
                float nrm = sqrtf(sSqn[p] + 1e-8f) + 1.0f;
                float wgt = px / nrm;
#pragma unroll
                for (int d = 0; d < 3; ++d)
                    atomicAdd(&sSh[hh * 3 + d],
                              wgt * (sXj[j * 24 + hh * 3 + d] - sXi[hh * 3 + d]));
            }
            __syncthreads();
            if (t < 24) atomicAdd(&g_shift[i * 24 + t], sSh[t]);
        }
        __syncthreads();  // epilogue writes visible to next layer MMA
    }
}

// ---------------- node kernels ----------------
__global__ void __launch_bounds__(256) hnew_kernel(
    const float* __restrict__ h, const float* __restrict__ Wh0,
    const float* __restrict__ bh0, const float* __restrict__ Wh1,
    const float* __restrict__ bh1, const float* __restrict__ Who,
    const float* __restrict__ bho, float* __restrict__ out) {
    extern __shared__ float sm[];
    float* buf0 = sm;                 // 16*384
    float* buf1 = buf0 + 16 * 384;    // 16*256
    float* ws = buf1 + 16 * 256;      // 32*256
    int r0g = blockIdx.x * 16, t = threadIdx.x;
    for (int idx = t; idx < 16 * 384; idx += 256) {
        int row = idx / 384, c = idx - row * 384;
        buf0[idx] = (c < 256) ? g_mi[(r0g + row) * 256 + c]
                              : h[(r0g + row) * 128 + (c - 256)];
    }
    __syncthreads();
    gemmR<16, 256, true>(buf0, 384, Wh0, bh0, buf1, ws);
    gemmR<16, 256, true>(buf1, 256, Wh1, bh1, buf0, ws);
    gemmR<16, 128, false>(buf0, 256, Who, bho, buf1, ws);
    for (int idx = t; idx < 16 * 128; idx += 256)
        out[r0g * 128 + idx] = buf1[idx] + h[r0g * 128 + idx];
}
__global__ void xnew_kernel(const float* __restrict__ x, float* __restrict__ out) {
    int idx = blockIdx.x * 256 + threadIdx.x;
    if (idx < NN * 24) out[idx] = x[idx] + g_shift[idx] * (1.0f / 511.0f);
}

// ---------------- launch ----------------
extern "C" void kernel_launch(void* const* d_in, const int* in_sizes, int n_in,
                              void* d_out, int out_size) {
    const float* x = (const float*)d_in[0];
    const float* h = (const float*)d_in[1];
    const float* We0 = (const float*)d_in[2];
    const float* be0 = (const float*)d_in[3];
    const float* We1 = (const float*)d_in[4];
    const float* be1 = (const float*)d_in[5];
    const float* Winf = (const float*)d_in[6];
    const float* binf = (const float*)d_in[7];
    const float* Wx0 = (const float*)d_in[8];
    const float* bx0 = (const float*)d_in[9];
    const float* Wx1 = (const float*)d_in[10];
    const float* bx1 = (const float*)d_in[11];
    const float* Wxo = (const float*)d_in[12];
    const float* bxo = (const float*)d_in[13];
    const float* Wh0 = (const float*)d_in[14];
    const float* bh0 = (const float*)d_in[15];
    const float* Wh1 = (const float*)d_in[16];
    const float* bh1 = (const float*)d_in[17];
    const float* Who = (const float*)d_in[18];
    const float* bho = (const float*)d_in[19];
    float* out = (float*)d_out;  // [x_new (512*24) | h_new (512*128)]

    const int AB_SMEM = (16 * 192 + 32 * 256) * 4;
    const int HNEW_SMEM = (16 * 384 + 16 * 256 + 32 * 256) * 4;
    cudaFuncSetAttribute(edge_kernel, cudaFuncAttributeMaxDynamicSharedMemorySize,
                         EDGE_SMEM);
    cudaFuncSetAttribute(prep_ab, cudaFuncAttributeMaxDynamicSharedMemorySize, AB_SMEM);
    cudaFuncSetAttribute(hnew_kernel, cudaFuncAttributeMaxDynamicSharedMemorySize,
                         HNEW_SMEM);

    zero_kernel<<<512, 256>>>();
    prep_hc<<<NN, 192>>>(x, h);
    prep_w<<<dim3(8, 8, 3), dim3(32, 8)>>>(We1, Wx0, Wx1);
    prep_ab<<<dim3(32, 2), 256, AB_SMEM>>>(We0);
    edge_kernel<<<dim3(8, NN), 256, EDGE_SMEM>>>(x, We0, be0, be1, Winf, binf, bx0,
                                                 bx1, bxo, Wxo);
    hnew_kernel<<<32, 256, HNEW_SMEM>>>(h, Wh0, bh0, Wh1, bh1, Who, bho, out + NN * 24);
    xnew_kernel<<<48, 256>>>(x, out);
}

// round 12
// speedup vs baseline: 4.5611x; 1.0170x over previous
#include <cuda_runtime.h>
#include <cuda_fp16.h>

// EGCL_Multi — sm_103. R11: edge kernel unchanged (at legacy-MMA floor:
// l0 fp16 m16n8k16, l1/l2 fp8 e4m3 m16n8k32). Prep kernels de-latencied:
// gemmR now double-buffers weight staging via cp.async; prep_ab N-split
// (grid x2); zero_kernel folded into prep_hc.
#define NN 512

__device__ __align__(16) float g_hc[NN * 192];
__device__ __align__(16) float g_A[NN * 256];
__device__ __align__(16) float g_B[NN * 256];
__device__ __align__(16) float g_mi[NN * 256];
__device__ __align__(16) float g_shift[NN * 24];
// chunks 0-3: fp16 We1 32KB each (offset 0); chunks 4-11: fp8 Wx0/Wx1 16KB
// each (offset 131072)
__device__ __align__(128) char g_Wstage[262144];

// ---------------- small helpers ----------------
__device__ __forceinline__ float silu_f(float v) {
    return v * (1.0f / (1.0f + __expf(-v)));
}
__device__ __forceinline__ unsigned smem_u32(const void* p) {
    unsigned a;
    asm("{ .reg .u64 t; cvta.to.shared.u64 t, %1; cvt.u32.u64 %0, t; }"
        : "=r"(a) : "l"(p));
    return a;
}
__device__ __forceinline__ unsigned lds32(unsigned addr) {
    unsigned v;
    asm volatile("ld.shared.b32 %0, [%1];" : "=r"(v) : "r"(addr));
    return v;
}
__device__ __forceinline__ void sts32(unsigned addr, unsigned v) {
    asm volatile("st.shared.b32 [%0], %1;" :: "r"(addr), "r"(v) : "memory");
}
__device__ __forceinline__ void sts16(unsigned addr, unsigned short v) {
    asm volatile("st.shared.u16 [%0], %1;" :: "r"(addr), "h"(v) : "memory");
}
__device__ __forceinline__ void cp16(unsigned dst, const void* src) {
    asm volatile("cp.async.ca.shared.global [%0], [%1], 16;"
                 :: "r"(dst), "l"(src) : "memory");
}
#define CP_COMMIT() asm volatile("cp.async.commit_group;" ::: "memory")
#define CP_WAIT1() asm volatile("cp.async.wait_group 1;" ::: "memory")
#define CP_WAIT0() asm volatile("cp.async.wait_group 0;" ::: "memory")
#define MBAR_INIT(mb, n) \
    asm volatile("mbarrier.init.shared.b64 [%0], %1;" :: "r"(mb), "r"(n) : "memory")
#define EXPECT_TX(mb, n) \
    asm volatile("mbarrier.arrive.expect_tx.shared.b64 _, [%0], %1;" \
                 :: "r"(mb), "r"(n) : "memory")
__device__ __forceinline__ void mbar_wait(unsigned mb, unsigned par) {
    asm volatile(
        "{\n\t.reg .pred P;\n"
        "WL_%=:\n\t"
        "mbarrier.try_wait.parity.acquire.cta.shared::cta.b64 P, [%0], %1, 0x989680;\n\t"
        "@P bra.uni WD_%=;\n\tbra.uni WL_%=;\nWD_%=:\n\t}"
        :: "r"(mb), "r"(par) : "memory");
}
__device__ __forceinline__ void bulk_cp(unsigned dst, const void* src, unsigned bytes,
                                        unsigned mbar) {
    asm volatile(
        "cp.async.bulk.shared::cluster.global.mbarrier::complete_tx::bytes "
        "[%0], [%1], %2, [%3];"
        :: "r"(dst), "l"(src), "r"(bytes), "r"(mbar) : "memory");
}
__device__ __forceinline__ unsigned hpack2(float a, float b) {
    __half2 h = __floats2half2_rn(a, b);
    return *(unsigned*)&h;
}
// pack (lo, hi) floats -> e4m3x2 in a .b16 (lo in byte0)
__device__ __forceinline__ unsigned short f8pack2(float lo, float hi) {
    unsigned short q;
    asm("cvt.rn.satfinite.e4m3x2.f32 %0, %1, %2;" : "=h"(q) : "f"(hi), "f"(lo));
    return q;
}
__device__ __forceinline__ void mma16816(float* d, const unsigned* a, unsigned b0,
                                         unsigned b1) {
    asm volatile(
        "mma.sync.aligned.m16n8k16.row.col.f32.f16.f16.f32 "
        "{%0,%1,%2,%3}, {%4,%5,%6,%7}, {%8,%9}, {%0,%1,%2,%3};"
        : "+f"(d[0]), "+f"(d[1]), "+f"(d[2]), "+f"(d[3])
        : "r"(a[0]), "r"(a[1]), "r"(a[2]), "r"(a[3]), "r"(b0), "r"(b1));
}
__device__ __forceinline__ void mma16832f8(float* d, const unsigned* a, unsigned b0,
                                           unsigned b1) {
    asm volatile(
        "mma.sync.aligned.m16n8k32.row.col.f32.e4m3.e4m3.f32 "
        "{%0,%1,%2,%3}, {%4,%5,%6,%7}, {%8,%9}, {%0,%1,%2,%3};"
        : "+f"(d[0]), "+f"(d[1]), "+f"(d[2]), "+f"(d[3])
        : "r"(a[0]), "r"(a[1]), "r"(a[2]), "r"(a[3]), "r"(b0), "r"(b1));
}

// ---------------- f32x2 SIMT gemm (node-side) ----------------
__device__ __forceinline__ unsigned long long pk2(float lo, float hi) {
    unsigned long long r;
    asm("mov.b64 %0, {%1, %2};" : "=l"(r) : "f"(lo), "f"(hi));
    return r;
}
__device__ __forceinline__ void upk2(unsigned long long v, float& lo, float& hi) {
    asm("mov.b64 {%0, %1}, %2;" : "=f"(lo), "=f"(hi) : "l"(v));
}
__device__ __forceinline__ void fma2(unsigned long long& d, unsigned long long a,
                                     unsigned long long b) {
    asm("fma.rn.f32x2 %0, %1, %2, %0;" : "+l"(d) : "l"(a), "l"(b));
}
// C[ROWS,N] = act(In[ROWS,K] @ W[K,:] + bias); W rows have stride wstride,
// output rows stride ostride. Weight staging double-buffered via cp.async.
// ws must hold 2*32*N floats. 256 threads.
template <int ROWS, int N, bool ACT>
__device__ __forceinline__ void gemmR(const float* sIn, int K,
                                      const float* __restrict__ Wg, int wstride,
                                      const float* __restrict__ bias, float* out,
                                      int ostride, float* ws) {
    constexpr int COLG = N / 8;
    constexpr int RPT = ROWS * COLG / 256;
    const int t = threadIdx.x;
    const int nc = t % COLG, mr = t / COLG;
    const int r0 = mr * RPT, c0 = nc * 8;
    const int R = K / 32;
    unsigned long long acc[RPT][4];
#pragma unroll
    for (int r = 0; r < RPT; r++)
#pragma unroll
        for (int p = 0; p < 4; p++) acc[r][p] = 0ULL;

    const unsigned wsb = smem_u32(ws);
    // stage round 0 into buffer 0
    for (int idx = t; idx < 32 * N / 4; idx += 256) {
        int wr = idx / (N / 4), wc = (idx - wr * (N / 4)) * 4;
        cp16(wsb + (unsigned)((wr * N + wc) * 4), &Wg[wr * wstride + wc]);
    }
    CP_COMMIT();

    for (int r = 0; r < R; ++r) {
        if (r + 1 < R) {
            unsigned dstb = wsb + (unsigned)(((r + 1) & 1) * 32 * N * 4);
            const float* src = Wg + (r + 1) * 32 * wstride;
            for (int idx = t; idx < 32 * N / 4; idx += 256) {
                int wr = idx / (N / 4), wc = (idx - wr * (N / 4)) * 4;
                cp16(dstb + (unsigned)((wr * N + wc) * 4), &src[wr * wstride + wc]);
            }
            CP_COMMIT();
            CP_WAIT1();
        } else {
            CP_WAIT0();
        }
        __syncthreads();
        const float* wb = ws + (r & 1) * 32 * N;
        const int kt = r * 32;
#pragma unroll
        for (int k4 = 0; k4 < 8; k4++) {
            float4 av[RPT];
#pragma unroll
            for (int rr = 0; rr < RPT; rr++)
                av[rr] = *(const float4*)&sIn[(r0 + rr) * K + kt + k4 * 4];
#pragma unroll
            for (int kk = 0; kk < 4; kk++) {
                const float* wr_ = &wb[(k4 * 4 + kk) * N + c0];
                float4 w0 = *(const float4*)&wr_[0];
                float4 w1 = *(const float4*)&wr_[4];
                unsigned long long b0 = pk2(w0.x, w0.y), b1 = pk2(w0.z, w0.w);
                unsigned long long b2 = pk2(w1.x, w1.y), b3 = pk2(w1.z, w1.w);
#pragma unroll
                for (int rr = 0; rr < RPT; rr++) {
                    float a = (kk == 0) ? av[rr].x : (kk == 1) ? av[rr].y
                            : (kk == 2) ? av[rr].z : av[rr].w;
                    unsigned long long a2 = pk2(a, a);
                    fma2(acc[rr][0], a2, b0);
                    fma2(acc[rr][1], a2, b1);
                    fma2(acc[rr][2], a2, b2);
                    fma2(acc[rr][3], a2, b3);
                }
            }
        }
        __syncthreads();
    }
#pragma unroll
    for (int rr = 0; rr < RPT; rr++)
#pragma unroll
        for (int p = 0; p < 4; p++) {
            float lo, hi;
            upk2(acc[rr][p], lo, hi);
            int c = c0 + p * 2;
            if (bias) {
                float2 bb = *(const float2*)&bias[c];
                lo += bb.x;
                hi += bb.y;
            }
            if (ACT) { lo = silu_f(lo); hi = silu_f(hi); }
            float2 o; o.x = lo; o.y = hi;
            *(float2*)&out[(r0 + rr) * ostride + c] = o;
        }
    __syncthreads();
}

// ---------------- prep kernels ----------------
// h copy + head-pair sq dists + zero g_mi/g_shift (zero_kernel folded in)
__global__ void prep_hc(const float* __restrict__ x, const float* __restrict__ h) {
    int n = blockIdx.x, t = threadIdx.x;
    if (t < 128) g_hc[n * 192 + t] = h[n * 128 + t];
    else if (t < 192) {
        int p = t - 128, a = p >> 3, b = p & 7;
        float dx = x[n * 24 + a * 3] - x[n * 24 + b * 3];
        float dy = x[n * 24 + a * 3 + 1] - x[n * 24 + b * 3 + 1];
        float dz = x[n * 24 + a * 3 + 2] - x[n * 24 + b * 3 + 2];
        g_hc[n * 192 + 128 + p] = dx * dx + dy * dy + dz * dz;
    }
    g_mi[n * 256 + t] = 0.f;
    if (t < 24) g_shift[n * 24 + t] = 0.f;
}
// transpose + stage: sel0 -> fp16 swizzled image, sel1/2 -> fp8 e4m3 image
__global__ void prep_w(const float* __restrict__ We1, const float* __restrict__ Wx0,
                       const float* __restrict__ Wx1) {
    __shared__ float tile[32][33];
    int sel = blockIdx.z;
    const float* W = (sel == 0) ? We1 : (sel == 1) ? Wx0 : Wx1;
    int n0 = blockIdx.x * 32, k0 = blockIdx.y * 32;
    int tx = threadIdx.x, ty = threadIdx.y;
    for (int r = ty; r < 32; r += 8) tile[r][tx] = W[(k0 + r) * 256 + n0 + tx];
    __syncthreads();
    for (int r = ty; r < 32; r += 8) {
        float v = tile[tx][r];  // = W[k0+tx][n0+r]
        int n = n0 + r, k = k0 + tx;
        int chunk = k >> 6, kin = k & 63;
        if (sel == 0) {
            unsigned off = (unsigned)(chunk * 32768 + n * 128 +
                                      (((kin >> 3) * 16) ^ ((n & 7) * 16)) +
                                      (kin & 7) * 2);
            *(__half*)(g_Wstage + off) = __float2half_rn(v);
        } else {
            unsigned u = (unsigned)((kin >> 4) ^ ((n >> 1) & 3));
            unsigned off = (unsigned)(131072 + ((sel - 1) * 4 + chunk) * 16384 +
                                      n * 64 + u * 16 + (kin & 15));
            g_Wstage[off] = (char)(f8pack2(v, 0.f) & 0xff);
        }
    }
}
// A/B precompute, N-split: grid (row_tiles=32, sel=2, nhalf=2)
__global__ void __launch_bounds__(256) prep_ab(const float* __restrict__ We0) {
    extern __shared__ float sm[];
    float* sIn = sm;              // 16*192
    float* ws = sm + 16 * 192;    // 2*32*128
    int r0g = blockIdx.x * 16, t = threadIdx.x;
    int sel = blockIdx.y, nh = blockIdx.z;
    for (int idx = t; idx < 16 * 192 / 4; idx += 256)
        *(float4*)&sIn[idx * 4] = *(const float4*)&g_hc[r0g * 192 + idx * 4];
    __syncthreads();
    const float* Wg = We0 + (sel == 0 ? 8 : 200) * 256 + nh * 128;
    float* outp = (sel == 0 ? g_A : g_B) + r0g * 256 + nh * 128;
    gemmR<16, 128, false>(sIn, 192, Wg, 256, nullptr, outp, 256, ws);
}

// ---------------- edge kernel (unchanged from R10) ----------------
#define OFF_A 0          // 33792 (fp16 plane: 64 rows x 264 halves)
#define OFF_W 33792      // l0: 2x32KB fp16 bufs; l>=1: 2x16KB fp8 bufs
#define OFF_A8 66560     // 17408 (fp8 act plane: 64 rows x 272B) inside W region
#define OFF_XJ 99328     // 6144
#define OFF_SQN 105472   // 2048
#define OFF_BI 107520    // 1024 (T0 only; aliased by PX later)
#define OFF_WINF 108544  // 1024 (l0 only; aliased by PX later)
#define OFF_PX OFF_BI    // 2048 (l2 only)
#define OFF_BIAS 109568  // 3072
#define OFF_PE 112640    // 256
#define OFF_E 112896     // 256
#define OFF_XI 113152    // 128
#define OFF_SH 113280    // 128
#define OFF_MB 113408    // 16
#define EDGE_SMEM 113424

__global__ void __launch_bounds__(256, 2) edge_kernel(
    const float* __restrict__ x, const float* __restrict__ We0,
    const float* __restrict__ be0, const float* __restrict__ be1,
    const float* __restrict__ Winf, const float* __restrict__ binf,
    const float* __restrict__ bx0, const float* __restrict__ bx1,
    const float* __restrict__ bxo, const float* __restrict__ Wxo) {
    extern __shared__ char smc[];
    const unsigned sb = smem_u32(smc);
    const int t = threadIdx.x;
    const int lane = t & 31, w = t >> 5;
    const int band = w >> 1, ng = w & 1;
    const int r0 = band * 16 + (lane >> 2);
    const int k4 = lane & 3;
    const unsigned bswz = (unsigned)((lane >> 2) << 4);
    const int i = blockIdx.y, j0 = blockIdx.x * 64;

    float* sXj = (float*)(smc + OFF_XJ);
    float* sSqn = (float*)(smc + OFF_SQN);
    float* sBi = (float*)(smc + OFF_BI);
    float* sWinf = (float*)(smc + OFF_WINF);
    float* sBias = (float*)(smc + OFF_BIAS);
    float* sPE = (float*)(smc + OFF_PE);
    float* sE = (float*)(smc + OFF_E);
    float* sPx = (float*)(smc + OFF_PX);
    float* sXi = (float*)(smc + OFF_XI);
    float* sSh = (float*)(smc + OFF_SH);
    const unsigned mb0 = sb + OFF_MB, mb1 = sb + OFF_MB + 8;

    if (t == 0) { MBAR_INIT(mb0, 1); MBAR_INIT(mb1, 1); }
    for (int idx = t; idx < 1536; idx += 256) sXj[idx] = x[j0 * 24 + idx];
    sBi[t] = g_B[i * 256 + t] + be0[t];
    sWinf[t] = Winf[t];
    sBias[t] = be1[t];
    sBias[256 + t] = bx0[t];
    sBias[512 + t] = bx1[t];
    if (t < 64) sPE[t] = 0.f;
    if (t < 24) { sXi[t] = x[i * 24 + t]; sSh[t] = 0.f; }
    __syncthreads();

    if (t == 0) {
        EXPECT_TX(mb0, 32768u);
        bulk_cp(sb + OFF_W, g_Wstage, 32768u, mb0);
    }

    for (int p = t; p < 512; p += 256) {
        int j = p >> 3, hh = p & 7;
        float dx = sXj[j * 24 + hh * 3] - sXi[hh * 3];
        float dy = sXj[j * 24 + hh * 3 + 1] - sXi[hh * 3 + 1];
        float dz = sXj[j * 24 + hh * 3 + 2] - sXi[hh * 3 + 2];
        sSqn[p] = dx * dx + dy * dy + dz * dz;
    }
    __syncthreads();

    // T0 = silu(A[j] + (B[i]+be0) + sqn@We0[0:8]) -> fp16 A plane
    for (int it = 0; it < 16; ++it) {
        int idx = it * 256 + t;
        int j = idx >> 6, c = (idx & 63) * 4;
        float4 v = *(const float4*)&g_A[(j0 + j) * 256 + c];
        v.x += sBi[c]; v.y += sBi[c + 1]; v.z += sBi[c + 2]; v.w += sBi[c + 3];
#pragma unroll
        for (int q = 0; q < 8; q++) {
            float s = sSqn[j * 8 + q];
            float4 w4 = __ldg((const float4*)&We0[q * 256 + c]);
            v.x += s * w4.x; v.y += s * w4.y; v.z += s * w4.z; v.w += s * w4.w;
        }
        v.x = silu_f(v.x); v.y = silu_f(v.y); v.z = silu_f(v.z); v.w = silu_f(v.w);
        unsigned off = (unsigned)(j * 528 + c * 2);
        sts32(sb + OFF_A + off, hpack2(v.x, v.y));
        sts32(sb + OFF_A + off + 4, hpack2(v.z, v.w));
    }
    __syncthreads();

    const float binf0 = binf[0];

    for (int l = 0; l < 3; ++l) {
        float accf[16][4];
#pragma unroll
        for (int s2 = 0; s2 < 16; ++s2)
#pragma unroll
            for (int q = 0; q < 4; ++q) accf[s2][q] = 0.f;

        for (int c = 0; c < 4; ++c) {
            int g = l * 4 + c;
            int gn = g + 1;
            if (gn < 12 && t == 0) {
                unsigned mb = (gn & 1) ? mb1 : mb0;
                if (gn < 4) {
                    EXPECT_TX(mb, 32768u);
                    bulk_cp(sb + OFF_W + (unsigned)((gn & 1) * 32768),
                            g_Wstage + gn * 32768, 32768u, mb);
                } else {
                    EXPECT_TX(mb, 16384u);
                    bulk_cp(sb + OFF_W + (unsigned)((gn & 1) * 16384),
                            g_Wstage + 131072 + (gn - 4) * 16384, 16384u, mb);
                }
            }
            mbar_wait((g & 1) ? mb1 : mb0, (g >> 1) & 1);
            if (l == 0) {
                const unsigned wb = sb + OFF_W + (unsigned)((g & 1) * 32768);
#pragma unroll
                for (int ks = 0; ks < 4; ++ks) {
                    const int khb = c * 128 + ks * 32;
                    unsigned ah[4];
                    unsigned a0 = sb + OFF_A + (unsigned)(r0 * 528 + khb + k4 * 4);
                    ah[0] = lds32(a0);
                    ah[1] = lds32(a0 + 8 * 528);
                    ah[2] = lds32(a0 + 16);
                    ah[3] = lds32(a0 + 8 * 528 + 16);
#pragma unroll
                    for (int sub = 0; sub < 16; ++sub) {
                        unsigned nrow = (unsigned)(ng * 128 + sub * 8 + (lane >> 2));
                        unsigned rb = wb + nrow * 128;
                        unsigned o0 = ((unsigned)(ks * 32 + k4 * 4)) ^ bswz;
                        unsigned o1 = ((unsigned)(ks * 32 + k4 * 4 + 16)) ^ bswz;
                        mma16816(accf[sub], ah, lds32(rb + o0), lds32(rb + o1));
                    }
                }
            } else {
                const unsigned wb = sb + OFF_W + (unsigned)((g & 1) * 16384);
#pragma unroll
                for (int ks = 0; ks < 2; ++ks) {
                    unsigned ah[4];
                    unsigned a0 = sb + OFF_A8 +
                                  (unsigned)(r0 * 272 + c * 64 + ks * 32 + k4 * 4);
                    ah[0] = lds32(a0);
                    ah[1] = lds32(a0 + 8 * 272);
                    ah[2] = lds32(a0 + 16);
                    ah[3] = lds32(a0 + 8 * 272 + 16);
#pragma unroll
                    for (int sub = 0; sub < 16; ++sub) {
                        unsigned nrow = (unsigned)(ng * 128 + sub * 8 + (lane >> 2));
                        unsigned rb = wb + nrow * 64;
                        unsigned s_ = (nrow >> 1) & 3u;
                        unsigned b0 = lds32(rb + (((unsigned)(ks * 2)) ^ s_) * 16 +
                                            k4 * 4);
                        unsigned b1 = lds32(rb + (((unsigned)(ks * 2 + 1)) ^ s_) * 16 +
                                            k4 * 4);
                        mma16832f8(accf[sub], ah, b0, b1);
                    }
                }
            }
            __syncthreads();
        }

        // ---------------- epilogues ----------------
        if (l == 0) {
            float pe0 = 0.f, pe1 = 0.f;
#pragma unroll
            for (int sub = 0; sub < 16; ++sub) {
                int col = ng * 128 + sub * 8 + k4 * 2;
                float v0 = silu_f(accf[sub][0] + sBias[col]);
                float v1 = silu_f(accf[sub][1] + sBias[col + 1]);
                float v2 = silu_f(accf[sub][2] + sBias[col]);
                float v3 = silu_f(accf[sub][3] + sBias[col + 1]);
                pe0 += v0 * sWinf[col] + v1 * sWinf[col + 1];
                pe1 += v2 * sWinf[col] + v3 * sWinf[col + 1];
                unsigned off = (unsigned)(r0 * 528 + col * 2);
                sts32(sb + OFF_A + off, hpack2(v0, v1));
                sts32(sb + OFF_A + off + 8 * 528, hpack2(v2, v3));
                unsigned a8 = sb + OFF_A8 + (unsigned)(r0 * 272 + col);
                sts16(a8, f8pack2(v0, v1));
                sts16(a8 + 8 * 272, f8pack2(v2, v3));
            }
            pe0 += __shfl_xor_sync(0xffffffffu, pe0, 1);
            pe0 += __shfl_xor_sync(0xffffffffu, pe0, 2);
            pe1 += __shfl_xor_sync(0xffffffffu, pe1, 1);
            pe1 += __shfl_xor_sync(0xffffffffu, pe1, 2);
            if (k4 == 0) {
                atomicAdd(&sPE[r0], pe0);
                atomicAdd(&sPE[r0 + 8], pe1);
            }
            __syncthreads();
            if (t < 64) {
                float z = sPE[t] + binf0;
                float e = 1.0f / (1.0f + __expf(-z));
                if (j0 + t == i) e = 0.f;
                sE[t] = e;
            }
            __syncthreads();
            {
                const __half* mh = (const __half*)(smc + OFF_A);
                float a_ = 0.f;
#pragma unroll 4
                for (int j = 0; j < 64; ++j)
                    a_ += __half2float(mh[j * 264 + t]) * sE[j];
                atomicAdd(&g_mi[i * 256 + t], a_);
            }
        } else if (l == 1) {
#pragma unroll
            for (int sub = 0; sub < 16; ++sub) {
                int col = ng * 128 + sub * 8 + k4 * 2;
                float v0 = silu_f(accf[sub][0] + sBias[256 + col]);
                float v1 = silu_f(accf[sub][1] + sBias[256 + col + 1]);
                float v2 = silu_f(accf[sub][2] + sBias[256 + col]);
                float v3 = silu_f(accf[sub][3] + sBias[256 + col + 1]);
                unsigned a8 = sb + OFF_A8 + (unsigned)(r0 * 272 + col);
                sts16(a8, f8pack2(v0, v1));
                sts16(a8 + 8 * 272, f8pack2(v2, v3));
            }
            for (int p = t; p < 512; p += 256) sPx[p] = 0.f;
        } else {
            float* sWxo = (float*)(smc + OFF_A);
            for (int idx = t; idx < 2048; idx += 256) sWxo[idx] = Wxo[idx];
            __syncthreads();
            float pxa0[8], pxa1[8];
#pragma unroll
            for (int hh = 0; hh < 8; ++hh) { pxa0[hh] = 0.f; pxa1[hh] = 0.f; }
#pragma unroll
            for (int sub = 0; sub < 16; ++sub) {
                int col = ng * 128 + sub * 8 + k4 * 2;
                float v0 = silu_f(accf[sub][0] + sBias[512 + col]);
                float v1 = silu_f(accf[sub][1] + sBias[512 + col + 1]);
                float v2 = silu_f(accf[sub][2] + sBias[512 + col]);
                float v3 = silu_f(accf[sub][3] + sBias[512 + col + 1]);
                const float* w0 = &sWxo[col * 8];
                const float* w1 = &sWxo[(col + 1) * 8];
#pragma unroll
                for (int hh = 0; hh < 8; ++hh) {
                    pxa0[hh] += v0 * w0[hh] + v1 * w1[hh];
                    pxa1[hh] += v2 * w0[hh] + v3 * w1[hh];
                }
            }
#pragma unroll
            for (int hh = 0; hh < 8; ++hh) {
                pxa0[hh] += __shfl_xor_sync(0xffffffffu, pxa0[hh], 1);
                pxa0[hh] += __shfl_xor_sync(0xffffffffu, pxa0[hh], 2);
                pxa1[hh] += __shfl_xor_sync(0xffffffffu, pxa1[hh], 1);
                pxa1[hh] += __shfl_xor_sync(0xffffffffu, pxa1[hh], 2);
            }
            if (k4 == 0) {
#pragma unroll
                for (int hh = 0; hh < 8; ++hh) {
                    atomicAdd(&sPx[r0 * 8 + hh], pxa0[hh]);
                    atomicAdd(&sPx[(r0 + 8) * 8 + hh], pxa1[hh]);
                }
            }
            __syncthreads();
            for (int p = t; p < 512; p += 256) {
                int j = p >> 3, hh = p & 7;
                float px = sPx[p] + bxo[hh];
                if (j0 + j == i) px = 0.f;
                float nrm = sqrtf(sSqn[p] + 1e-8f) + 1.0f;
                float wgt = px / nrm;
#pragma unroll
                for (int d = 0; d < 3; ++d)
                    atomicAdd(&sSh[hh * 3 + d],
                              wgt * (sXj[j * 24 + hh * 3 + d] - sXi[hh * 3 + d]));
            }
            __syncthreads();
            if (t < 24) atomicAdd(&g_shift[i * 24 + t], sSh[t]);
        }
        __syncthreads();
    }
}

// ---------------- node kernels ----------------
__global__ void __launch_bounds__(256) hnew_kernel(
    const float* __restrict__ h, const float* __restrict__ Wh0,
    const float* __restrict__ bh0, const float* __restrict__ Wh1,
    const float* __restrict__ bh1, const float* __restrict__ Who,
    const float* __restrict__ bho, float* __restrict__ out) {
    extern __shared__ float sm[];
    float* buf0 = sm;                 // 16*384
    float* buf1 = buf0 + 16 * 384;    // 16*256
    float* ws = buf1 + 16 * 256;      // 2*32*256
    int r0g = blockIdx.x * 16, t = threadIdx.x;
    for (int idx = t; idx < 16 * 384; idx += 256) {
        int row = idx / 384, c = idx - row * 384;
        buf0[idx] = (c < 256) ? g_mi[(r0g + row) * 256 + c]
                              : h[(r0g + row) * 128 + (c - 256)];
    }
    __syncthreads();
    gemmR<16, 256, true>(buf0, 384, Wh0, 256, bh0, buf1, 256, ws);
    gemmR<16, 256, true>(buf1, 256, Wh1, 256, bh1, buf0, 256, ws);
    gemmR<16, 128, false>(buf0, 256, Who, 128, bho, buf1, 128, ws);
    for (int idx = t; idx < 16 * 128; idx += 256)
        out[r0g * 128 + idx] = buf1[idx] + h[r0g * 128 + idx];
}
__global__ void xnew_kernel(const float* __restrict__ x, float* __restrict__ out) {
    int idx = blockIdx.x * 256 + threadIdx.x;
    if (idx < NN * 24) out[idx] = x[idx] + g_shift[idx] * (1.0f / 511.0f);
}

// ---------------- launch ----------------
extern "C" void kernel_launch(void* const* d_in, const int* in_sizes, int n_in,
                              void* d_out, int out_size) {
    const float* x = (const float*)d_in[0];
    const float* h = (const float*)d_in[1];
    const float* We0 = (const float*)d_in[2];
    const float* be0 = (const float*)d_in[3];
    const float* We1 = (const float*)d_in[4];
    const float* be1 = (const float*)d_in[5];
    const float* Winf = (const float*)d_in[6];
    const float* binf = (const float*)d_in[7];
    const float* Wx0 = (const float*)d_in[8];
    const float* bx0 = (const float*)d_in[9];
    const float* Wx1 = (const float*)d_in[10];
    const float* bx1 = (const float*)d_in[11];
    const float* Wxo = (const float*)d_in[12];
    const float* bxo = (const float*)d_in[13];
    const float* Wh0 = (const float*)d_in[14];
    const float* bh0 = (const float*)d_in[15];
    const float* Wh1 = (const float*)d_in[16];
    const float* bh1 = (const float*)d_in[17];
    const float* Who = (const float*)d_in[18];
    const float* bho = (const float*)d_in[19];
    float* out = (float*)d_out;  // [x_new (512*24) | h_new (512*128)]

    const int AB_SMEM = (16 * 192 + 2 * 32 * 128) * 4;
    const int HNEW_SMEM = (16 * 384 + 16 * 256 + 2 * 32 * 256) * 4;
    cudaFuncSetAttribute(edge_kernel, cudaFuncAttributeMaxDynamicSharedMemorySize,
                         EDGE_SMEM);
    cudaFuncSetAttribute(prep_ab, cudaFuncAttributeMaxDynamicSharedMemorySize, AB_SMEM);
    cudaFuncSetAttribute(hnew_kernel, cudaFuncAttributeMaxDynamicSharedMemorySize,
                         HNEW_SMEM);

    prep_hc<<<NN, 256>>>(x, h);
    prep_w<<<dim3(8, 8, 3), dim3(32, 8)>>>(We1, Wx0, Wx1);
    prep_ab<<<dim3(32, 2, 2), 256, AB_SMEM>>>(We0);
    edge_kernel<<<dim3(8, NN), 256, EDGE_SMEM>>>(x, We0, be0, be1, Winf, binf, bx0,
                                                 bx1, bxo, Wxo);
    hnew_kernel<<<32, 256, HNEW_SMEM>>>(h, Wh0, bh0, Wh1, bh1, Who, bho, out + NN * 24);
    xnew_kernel<<<48, 256>>>(x, out);
}

// round 13
// speedup vs baseline: 4.6180x; 1.0125x over previous
#include <cuda_runtime.h>
#include <cuda_fp16.h>

// EGCL_Multi — sm_103. R12: ldmatrix.x4 for all A/B fragment loads in the
// edge kernel (2.2x fewer main-loop instructions; issue-bound per R11 ncu).
// Math identical to R11: l0 fp16 m16n8k16 f32acc, l1/l2 fp8 e4m3 m16n8k32.
#define NN 512

__device__ __align__(16) float g_hc[NN * 192];
__device__ __align__(16) float g_A[NN * 256];
__device__ __align__(16) float g_B[NN * 256];
__device__ __align__(16) float g_mi[NN * 256];
__device__ __align__(16) float g_shift[NN * 24];
// chunks 0-3: fp16 We1 32KB each (offset 0); chunks 4-11: fp8 Wx0/Wx1 16KB
// each (offset 131072)
__device__ __align__(128) char g_Wstage[262144];

// ---------------- small helpers ----------------
__device__ __forceinline__ float silu_f(float v) {
    return v * (1.0f / (1.0f + __expf(-v)));
}
__device__ __forceinline__ unsigned smem_u32(const void* p) {
    unsigned a;
    asm("{ .reg .u64 t; cvta.to.shared.u64 t, %1; cvt.u32.u64 %0, t; }"
        : "=r"(a) : "l"(p));
    return a;
}
__device__ __forceinline__ unsigned lds32(unsigned addr) {
    unsigned v;
    asm volatile("ld.shared.b32 %0, [%1];" : "=r"(v) : "r"(addr));
    return v;
}
__device__ __forceinline__ void sts32(unsigned addr, unsigned v) {
    asm volatile("st.shared.b32 [%0], %1;" :: "r"(addr), "r"(v) : "memory");
}
__device__ __forceinline__ void sts16(unsigned addr, unsigned short v) {
    asm volatile("st.shared.u16 [%0], %1;" :: "r"(addr), "h"(v) : "memory");
}
__device__ __forceinline__ void ldmat4(unsigned* r, unsigned addr) {
    asm volatile(
        "ldmatrix.sync.aligned.m8n8.x4.shared.b16 {%0,%1,%2,%3}, [%4];"
        : "=r"(r[0]), "=r"(r[1]), "=r"(r[2]), "=r"(r[3]) : "r"(addr));
}
__device__ __forceinline__ void cp16(unsigned dst, const void* src) {
    asm volatile("cp.async.ca.shared.global [%0], [%1], 16;"
                 :: "r"(dst), "l"(src) : "memory");
}
#define CP_COMMIT() asm volatile("cp.async.commit_group;" ::: "memory")
#define CP_WAIT1() asm volatile("cp.async.wait_group 1;" ::: "memory")
#define CP_WAIT0() asm volatile("cp.async.wait_group 0;" ::: "memory")
#define MBAR_INIT(mb, n) \
    asm volatile("mbarrier.init.shared.b64 [%0], %1;" :: "r"(mb), "r"(n) : "memory")
#define EXPECT_TX(mb, n) \
    asm volatile("mbarrier.arrive.expect_tx.shared.b64 _, [%0], %1;" \
                 :: "r"(mb), "r"(n) : "memory")
__device__ __forceinline__ void mbar_wait(unsigned mb, unsigned par) {
    asm volatile(
        "{\n\t.reg .pred P;\n"
        "WL_%=:\n\t"
        "mbarrier.try_wait.parity.acquire.cta.shared::cta.b64 P, [%0], %1, 0x989680;\n\t"
        "@P bra.uni WD_%=;\n\tbra.uni WL_%=;\nWD_%=:\n\t}"
        :: "r"(mb), "r"(par) : "memory");
}
__device__ __forceinline__ void bulk_cp(unsigned dst, const void* src, unsigned bytes,
                                        unsigned mbar) {
    asm volatile(
        "cp.async.bulk.shared::cluster.global.mbarrier::complete_tx::bytes "
        "[%0], [%1], %2, [%3];"
        :: "r"(dst), "l"(src), "r"(bytes), "r"(mbar) : "memory");
}
__device__ __forceinline__ unsigned hpack2(float a, float b) {
    __half2 h = __floats2half2_rn(a, b);
    return *(unsigned*)&h;
}
// pack (lo, hi) floats -> e4m3x2 in a .b16 (lo in byte0)
__device__ __forceinline__ unsigned short f8pack2(float lo, float hi) {
    unsigned short q;
    asm("cvt.rn.satfinite.e4m3x2.f32 %0, %1, %2;" : "=h"(q) : "f"(hi), "f"(lo));
    return q;
}
__device__ __forceinline__ void mma16816(float* d, const unsigned* a, unsigned b0,
                                         unsigned b1) {
    asm volatile(
        "mma.sync.aligned.m16n8k16.row.col.f32.f16.f16.f32 "
        "{%0,%1,%2,%3}, {%4,%5,%6,%7}, {%8,%9}, {%0,%1,%2,%3};"
        : "+f"(d[0]), "+f"(d[1]), "+f"(d[2]), "+f"(d[3])
        : "r"(a[0]), "r"(a[1]), "r"(a[2]), "r"(a[3]), "r"(b0), "r"(b1));
}
__device__ __forceinline__ void mma16832f8(float* d, const unsigned* a, unsigned b0,
                                           unsigned b1) {
    asm volatile(
        "mma.sync.aligned.m16n8k32.row.col.f32.e4m3.e4m3.f32 "
        "{%0,%1,%2,%3}, {%4,%5,%6,%7}, {%8,%9}, {%0,%1,%2,%3};"
        : "+f"(d[0]), "+f"(d[1]), "+f"(d[2]), "+f"(d[3])
        : "r"(a[0]), "r"(a[1]), "r"(a[2]), "r"(a[3]), "r"(b0), "r"(b1));
}

// ---------------- f32x2 SIMT gemm (node-side) ----------------
__device__ __forceinline__ unsigned long long pk2(float lo, float hi) {
    unsigned long long r;
    asm("mov.b64 %0, {%1, %2};" : "=l"(r) : "f"(lo), "f"(hi));
    return r;
}
__device__ __forceinline__ void upk2(unsigned long long v, float& lo, float& hi) {
    asm("mov.b64 {%0, %1}, %2;" : "=f"(lo), "=f"(hi) : "l"(v));
}
__device__ __forceinline__ void fma2(unsigned long long& d, unsigned long long a,
                                     unsigned long long b) {
    asm("fma.rn.f32x2 %0, %1, %2, %0;" : "+l"(d) : "l"(a), "l"(b));
}
template <int ROWS, int N, bool ACT>
__device__ __forceinline__ void gemmR(const float* sIn, int K,
                                      const float* __restrict__ Wg, int wstride,
                                      const float* __restrict__ bias, float* out,
                                      int ostride, float* ws) {
    constexpr int COLG = N / 8;
    constexpr int RPT = ROWS * COLG / 256;
    const int t = threadIdx.x;
    const int nc = t % COLG, mr = t / COLG;
    const int r0 = mr * RPT, c0 = nc * 8;
    const int R = K / 32;
    unsigned long long acc[RPT][4];
#pragma unroll
    for (int r = 0; r < RPT; r++)
#pragma unroll
        for (int p = 0; p < 4; p++) acc[r][p] = 0ULL;

    const unsigned wsb = smem_u32(ws);
    for (int idx = t; idx < 32 * N / 4; idx += 256) {
        int wr = idx / (N / 4), wc = (idx - wr * (N / 4)) * 4;
        cp16(wsb + (unsigned)((wr * N + wc) * 4), &Wg[wr * wstride + wc]);
    }
    CP_COMMIT();

    for (int r = 0; r < R; ++r) {
        if (r + 1 < R) {
            unsigned dstb = wsb + (unsigned)(((r + 1) & 1) * 32 * N * 4);
            const float* src = Wg + (r + 1) * 32 * wstride;
            for (int idx = t; idx < 32 * N / 4; idx += 256) {
                int wr = idx / (N / 4), wc = (idx - wr * (N / 4)) * 4;
                cp16(dstb + (unsigned)((wr * N + wc) * 4), &src[wr * wstride + wc]);
            }
            CP_COMMIT();
            CP_WAIT1();
        } else {
            CP_WAIT0();
        }
        __syncthreads();
        const float* wb = ws + (r & 1) * 32 * N;
        const int kt = r * 32;
#pragma unroll
        for (int k4 = 0; k4 < 8; k4++) {
            float4 av[RPT];
#pragma unroll
            for (int rr = 0; rr < RPT; rr++)
                av[rr] = *(const float4*)&sIn[(r0 + rr) * K + kt + k4 * 4];
#pragma unroll
            for (int kk = 0; kk < 4; kk++) {
                const float* wr_ = &wb[(k4 * 4 + kk) * N + c0];
                float4 w0 = *(const float4*)&wr_[0];
                float4 w1 = *(const float4*)&wr_[4];
                unsigned long long b0 = pk2(w0.x, w0.y), b1 = pk2(w0.z, w0.w);
                unsigned long long b2 = pk2(w1.x, w1.y), b3 = pk2(w1.z, w1.w);
#pragma unroll
                for (int rr = 0; rr < RPT; rr++) {
                    float a = (kk == 0) ? av[rr].x : (kk == 1) ? av[rr].y
                            : (kk == 2) ? av[rr].z : av[rr].w;
                    unsigned long long a2 = pk2(a, a);
                    fma2(acc[rr][0], a2, b0);
                    fma2(acc[rr][1], a2, b1);
                    fma2(acc[rr][2], a2, b2);
                    fma2(acc[rr][3], a2, b3);
                }
            }
        }
        __syncthreads();
    }
#pragma unroll
    for (int rr = 0; rr < RPT; rr++)
#pragma unroll
        for (int p = 0; p < 4; p++) {
            float lo, hi;
            upk2(acc[rr][p], lo, hi);
            int c = c0 + p * 2;
            if (bias) {
                float2 bb = *(const float2*)&bias[c];
                lo += bb.x;
                hi += bb.y;
            }
            if (ACT) { lo = silu_f(lo); hi = silu_f(hi); }
            float2 o; o.x = lo; o.y = hi;
            *(float2*)&out[(r0 + rr) * ostride + c] = o;
        }
    __syncthreads();
}

// ---------------- prep kernels ----------------
__global__ void prep_hc(const float* __restrict__ x, const float* __restrict__ h) {
    int n = blockIdx.x, t = threadIdx.x;
    if (t < 128) g_hc[n * 192 + t] = h[n * 128 + t];
    else if (t < 192) {
        int p = t - 128, a = p >> 3, b = p & 7;
        float dx = x[n * 24 + a * 3] - x[n * 24 + b * 3];
        float dy = x[n * 24 + a * 3 + 1] - x[n * 24 + b * 3 + 1];
        float dz = x[n * 24 + a * 3 + 2] - x[n * 24 + b * 3 + 2];
        g_hc[n * 192 + 128 + p] = dx * dx + dy * dy + dz * dz;
    }
    g_mi[n * 256 + t] = 0.f;
    if (t < 24) g_shift[n * 24 + t] = 0.f;
}
__global__ void prep_w(const float* __restrict__ We1, const float* __restrict__ Wx0,
                       const float* __restrict__ Wx1) {
    __shared__ float tile[32][33];
    int sel = blockIdx.z;
    const float* W = (sel == 0) ? We1 : (sel == 1) ? Wx0 : Wx1;
    int n0 = blockIdx.x * 32, k0 = blockIdx.y * 32;
    int tx = threadIdx.x, ty = threadIdx.y;
    for (int r = ty; r < 32; r += 8) tile[r][tx] = W[(k0 + r) * 256 + n0 + tx];
    __syncthreads();
    for (int r = ty; r < 32; r += 8) {
        float v = tile[tx][r];  // = W[k0+tx][n0+r]
        int n = n0 + r, k = k0 + tx;
        int chunk = k >> 6, kin = k & 63;
        if (sel == 0) {
            unsigned off = (unsigned)(chunk * 32768 + n * 128 +
                                      (((kin >> 3) * 16) ^ ((n & 7) * 16)) +
                                      (kin & 7) * 2);
            *(__half*)(g_Wstage + off) = __float2half_rn(v);
        } else {
            unsigned u = (unsigned)((kin >> 4) ^ ((n >> 1) & 3));
            unsigned off = (unsigned)(131072 + ((sel - 1) * 4 + chunk) * 16384 +
                                      n * 64 + u * 16 + (kin & 15));
            g_Wstage[off] = (char)(f8pack2(v, 0.f) & 0xff);
        }
    }
}
__global__ void __launch_bounds__(256) prep_ab(const float* __restrict__ We0) {
    extern __shared__ float sm[];
    float* sIn = sm;              // 16*192
    float* ws = sm + 16 * 192;    // 2*32*128
    int r0g = blockIdx.x * 16, t = threadIdx.x;
    int sel = blockIdx.y, nh = blockIdx.z;
    for (int idx = t; idx < 16 * 192 / 4; idx += 256)
        *(float4*)&sIn[idx * 4] = *(const float4*)&g_hc[r0g * 192 + idx * 4];
    __syncthreads();
    const float* Wg = We0 + (sel == 0 ? 8 : 200) * 256 + nh * 128;
    float* outp = (sel == 0 ? g_A : g_B) + r0g * 256 + nh * 128;
    gemmR<16, 128, false>(sIn, 192, Wg, 256, nullptr, outp, 256, ws);
}

// ---------------- edge kernel ----------------
#define OFF_A 0          // 33792 (fp16 plane: 64 rows x 264 halves)
#define OFF_W 33792      // l0: 2x32KB fp16 bufs; l>=1: 2x16KB fp8 bufs
#define OFF_A8 66560     // 17408 (fp8 act plane: 64 rows x 272B) inside W region
#define OFF_XJ 99328     // 6144
#define OFF_SQN 105472   // 2048
#define OFF_BI 107520    // 1024 (T0 only; aliased by PX later)
#define OFF_WINF 108544  // 1024 (l0 only; aliased by PX later)
#define OFF_PX OFF_BI    // 2048 (l2 only)
#define OFF_BIAS 109568  // 3072
#define OFF_PE 112640    // 256
#define OFF_E 112896     // 256
#define OFF_XI 113152    // 128
#define OFF_SH 113280    // 128
#define OFF_MB 113408    // 16
#define EDGE_SMEM 113424

__global__ void __launch_bounds__(256, 2) edge_kernel(
    const float* __restrict__ x, const float* __restrict__ We0,
    const float* __restrict__ be0, const float* __restrict__ be1,
    const float* __restrict__ Winf, const float* __restrict__ binf,
    const float* __restrict__ bx0, const float* __restrict__ bx1,
    const float* __restrict__ bxo, const float* __restrict__ Wxo) {
    extern __shared__ char smc[];
    const unsigned sb = smem_u32(smc);
    const int t = threadIdx.x;
    const int lane = t & 31, w = t >> 5;
    const int band = w >> 1, ng = w & 1;
    const int r0 = band * 16 + (lane >> 2);
    const int k4 = lane & 3;
    const int i = blockIdx.y, j0 = blockIdx.x * 64;

    // ldmatrix lane decode (q = which 8x8 matrix, qr = row within it)
    const int q = lane >> 3, qr = lane & 7;
    const unsigned aRow = (unsigned)(band * 16 + (q & 1) * 8 + qr);
    const unsigned aBase16 = sb + OFF_A + aRow * 528 + (unsigned)((q >> 1) * 16);
    const unsigned aBase8 = sb + OFF_A8 + aRow * 272 + (unsigned)((q >> 1) * 16);
    const int subAdd = q >> 1, hs = q & 1;
    const unsigned bn = (unsigned)(ng * 128 + subAdd * 8 + qr);
    const unsigned bkey16 = (unsigned)(qr * 16);

    float* sXj = (float*)(smc + OFF_XJ);
    float* sSqn = (float*)(smc + OFF_SQN);
    float* sBi = (float*)(smc + OFF_BI);
    float* sWinf = (float*)(smc + OFF_WINF);
    float* sBias = (float*)(smc + OFF_BIAS);
    float* sPE = (float*)(smc + OFF_PE);
    float* sE = (float*)(smc + OFF_E);
    float* sPx = (float*)(smc + OFF_PX);
    float* sXi = (float*)(smc + OFF_XI);
    float* sSh = (float*)(smc + OFF_SH);
    const unsigned mb0 = sb + OFF_MB, mb1 = sb + OFF_MB + 8;

    if (t == 0) { MBAR_INIT(mb0, 1); MBAR_INIT(mb1, 1); }
    for (int idx = t; idx < 1536; idx += 256) sXj[idx] = x[j0 * 24 + idx];
    sBi[t] = g_B[i * 256 + t] + be0[t];
    sWinf[t] = Winf[t];
    sBias[t] = be1[t];
    sBias[256 + t] = bx0[t];
    sBias[512 + t] = bx1[t];
    if (t < 64) sPE[t] = 0.f;
    if (t < 24) { sXi[t] = x[i * 24 + t]; sSh[t] = 0.f; }
    __syncthreads();

    if (t == 0) {
        EXPECT_TX(mb0, 32768u);
        bulk_cp(sb + OFF_W, g_Wstage, 32768u, mb0);
    }

    for (int p = t; p < 512; p += 256) {
        int j = p >> 3, hh = p & 7;
        float dx = sXj[j * 24 + hh * 3] - sXi[hh * 3];
        float dy = sXj[j * 24 + hh * 3 + 1] - sXi[hh * 3 + 1];
        float dz = sXj[j * 24 + hh * 3 + 2] - sXi[hh * 3 + 2];
        sSqn[p] = dx * dx + dy * dy + dz * dz;
    }
    __syncthreads();

    // T0 = silu(A[j] + (B[i]+be0) + sqn@We0[0:8]) -> fp16 A plane
    for (int it = 0; it < 16; ++it) {
        int idx = it * 256 + t;
        int j = idx >> 6, c = (idx & 63) * 4;
        float4 v = *(const float4*)&g_A[(j0 + j) * 256 + c];
        v.x += sBi[c]; v.y += sBi[c + 1]; v.z += sBi[c + 2]; v.w += sBi[c + 3];
#pragma unroll
        for (int qq = 0; qq < 8; qq++) {
            float s = sSqn[j * 8 + qq];
            float4 w4 = __ldg((const float4*)&We0[qq * 256 + c]);
            v.x += s * w4.x; v.y += s * w4.y; v.z += s * w4.z; v.w += s * w4.w;
        }
        v.x = silu_f(v.x); v.y = silu_f(v.y); v.z = silu_f(v.z); v.w = silu_f(v.w);
        unsigned off = (unsigned)(j * 528 + c * 2);
        sts32(sb + OFF_A + off, hpack2(v.x, v.y));
        sts32(sb + OFF_A + off + 4, hpack2(v.z, v.w));
    }
    __syncthreads();

    const float binf0 = binf[0];

    for (int l = 0; l < 3; ++l) {
        float accf[16][4];
#pragma unroll
        for (int s2 = 0; s2 < 16; ++s2)
#pragma unroll
            for (int qq = 0; qq < 4; ++qq) accf[s2][qq] = 0.f;

        for (int c = 0; c < 4; ++c) {
            int g = l * 4 + c;
            int gn = g + 1;
            if (gn < 12 && t == 0) {
                unsigned mb = (gn & 1) ? mb1 : mb0;
                if (gn < 4) {
                    EXPECT_TX(mb, 32768u);
                    bulk_cp(sb + OFF_W + (unsigned)((gn & 1) * 32768),
                            g_Wstage + gn * 32768, 32768u, mb);
                } else {
                    EXPECT_TX(mb, 16384u);
                    bulk_cp(sb + OFF_W + (unsigned)((gn & 1) * 16384),
                            g_Wstage + 131072 + (gn - 4) * 16384, 16384u, mb);
                }
            }
            mbar_wait((g & 1) ? mb1 : mb0, (g >> 1) & 1);
            if (l == 0) {
                const unsigned wb = sb + OFF_W + (unsigned)((g & 1) * 32768);
#pragma unroll
                for (int ks = 0; ks < 4; ++ks) {
                    unsigned ah[4];
                    ldmat4(ah, aBase16 + (unsigned)(c * 128 + ks * 32));
                    unsigned xt = ((unsigned)(ks * 32 + hs * 16)) ^ bkey16;
                    unsigned bb = wb + bn * 128 + xt;
#pragma unroll
                    for (int s = 0; s < 16; s += 2) {
                        unsigned bm[4];
                        ldmat4(bm, bb + (unsigned)(s * 1024));
                        mma16816(accf[s], ah, bm[0], bm[1]);
                        mma16816(accf[s + 1], ah, bm[2], bm[3]);
                    }
                }
            } else {
                const unsigned wb = sb + OFF_W + (unsigned)((g & 1) * 16384);
#pragma unroll
                for (int ks = 0; ks < 2; ++ks) {
                    unsigned ah[4];
                    ldmat4(ah, aBase8 + (unsigned)(c * 64 + ks * 32));
                    unsigned kx = (unsigned)(ks * 2 + hs);
#pragma unroll
                    for (int s = 0; s < 16; s += 2) {
                        unsigned n = bn + (unsigned)(s * 8);
                        unsigned addr = wb + n * 64 + ((kx ^ ((n >> 1) & 3u)) * 16u);
                        unsigned bm[4];
                        ldmat4(bm, addr);
                        mma16832f8(accf[s], ah, bm[0], bm[1]);
                        mma16832f8(accf[s + 1], ah, bm[2], bm[3]);
                    }
                }
            }
            __syncthreads();
        }

        // ---------------- epilogues ----------------
        if (l == 0) {
            float pe0 = 0.f, pe1 = 0.f;
#pragma unroll
            for (int sub = 0; sub < 16; ++sub) {
                int col = ng * 128 + sub * 8 + k4 * 2;
                float v0 = silu_f(accf[sub][0] + sBias[col]);
                float v1 = silu_f(accf[sub][1] + sBias[col + 1]);
                float v2 = silu_f(accf[sub][2] + sBias[col]);
                float v3 = silu_f(accf[sub][3] + sBias[col + 1]);
                pe0 += v0 * sWinf[col] + v1 * sWinf[col + 1];
                pe1 += v2 * sWinf[col] + v3 * sWinf[col + 1];
                unsigned off = (unsigned)(r0 * 528 + col * 2);
                sts32(sb + OFF_A + off, hpack2(v0, v1));
                sts32(sb + OFF_A + off + 8 * 528, hpack2(v2, v3));
                unsigned a8 = sb + OFF_A8 + (unsigned)(r0 * 272 + col);
                sts16(a8, f8pack2(v0, v1));
                sts16(a8 + 8 * 272, f8pack2(v2, v3));
            }
            pe0 += __shfl_xor_sync(0xffffffffu, pe0, 1);
            pe0 += __shfl_xor_sync(0xffffffffu, pe0, 2);
            pe1 += __shfl_xor_sync(0xffffffffu, pe1, 1);
            pe1 += __shfl_xor_sync(0xffffffffu, pe1, 2);
            if (k4 == 0) {
                atomicAdd(&sPE[r0], pe0);
                atomicAdd(&sPE[r0 + 8], pe1);
            }
            __syncthreads();
            if (t < 64) {
                float z = sPE[t] + binf0;
                float e = 1.0f / (1.0f + __expf(-z));
                if (j0 + t == i) e = 0.f;
                sE[t] = e;
            }
            __syncthreads();
            {
                const __half* mh = (const __half*)(smc + OFF_A);
                float a_ = 0.f;
#pragma unroll 4
                for (int j = 0; j < 64; ++j)
                    a_ += __half2float(mh[j * 264 + t]) * sE[j];
                atomicAdd(&g_mi[i * 256 + t], a_);
            }
        } else if (l == 1) {
#pragma unroll
            for (int sub = 0; sub < 16; ++sub) {
                int col = ng * 128 + sub * 8 + k4 * 2;
                float v0 = silu_f(accf[sub][0] + sBias[256 + col]);
                float v1 = silu_f(accf[sub][1] + sBias[256 + col + 1]);
                float v2 = silu_f(accf[sub][2] + sBias[256 + col]);
                float v3 = silu_f(accf[sub][3] + sBias[256 + col + 1]);
                unsigned a8 = sb + OFF_A8 + (unsigned)(r0 * 272 + col);
                sts16(a8, f8pack2(v0, v1));
                sts16(a8 + 8 * 272, f8pack2(v2, v3));
            }
            for (int p = t; p < 512; p += 256) sPx[p] = 0.f;
        } else {
            float* sWxo = (float*)(smc + OFF_A);
            for (int idx = t; idx < 2048; idx += 256) sWxo[idx] = Wxo[idx];
            __syncthreads();
            float pxa0[8], pxa1[8];
#pragma unroll
            for (int hh = 0; hh < 8; ++hh) { pxa0[hh] = 0.f; pxa1[hh] = 0.f; }
#pragma unroll
            for (int sub = 0; sub < 16; ++sub) {
                int col = ng * 128 + sub * 8 + k4 * 2;
                float v0 = silu_f(accf[sub][0] + sBias[512 + col]);
                float v1 = silu_f(accf[sub][1] + sBias[512 + col + 1]);
                float v2 = silu_f(accf[sub][2] + sBias[512 + col]);
                float v3 = silu_f(accf[sub][3] + sBias[512 + col + 1]);
                const float* w0 = &sWxo[col * 8];
                const float* w1 = &sWxo[(col + 1) * 8];
#pragma unroll
                for (int hh = 0; hh < 8; ++hh) {
                    pxa0[hh] += v0 * w0[hh] + v1 * w1[hh];
                    pxa1[hh] += v2 * w0[hh] + v3 * w1[hh];
                }
            }
#pragma unroll
            for (int hh = 0; hh < 8; ++hh) {
                pxa0[hh] += __shfl_xor_sync(0xffffffffu, pxa0[hh], 1);
                pxa0[hh] += __shfl_xor_sync(0xffffffffu, pxa0[hh], 2);
                pxa1[hh] += __shfl_xor_sync(0xffffffffu, pxa1[hh], 1);
                pxa1[hh] += __shfl_xor_sync(0xffffffffu, pxa1[hh], 2);
            }
            if (k4 == 0) {
#pragma unroll
                for (int hh = 0; hh < 8; ++hh) {
                    atomicAdd(&sPx[r0 * 8 + hh], pxa0[hh]);
                    atomicAdd(&sPx[(r0 + 8) * 8 + hh], pxa1[hh]);
                }
            }
            __syncthreads();
            for (int p = t; p < 512; p += 256) {
                int j = p >> 3, hh = p & 7;
                float px = sPx[p] + bxo[hh];
                if (j0 + j == i) px = 0.f;
                float nrm = sqrtf(sSqn[p] + 1e-8f) + 1.0f;
                float wgt = px / nrm;
#pragma unroll
                for (int d = 0; d < 3; ++d)
                    atomicAdd(&sSh[hh * 3 + d],
                              wgt * (sXj[j * 24 + hh * 3 + d] - sXi[hh * 3 + d]));
            }
            __syncthreads();
            if (t < 24) atomicAdd(&g_shift[i * 24 + t], sSh[t]);
        }
        __syncthreads();
    }
}

// ---------------- node kernels ----------------
__global__ void __launch_bounds__(256) hnew_kernel(
    const float* __restrict__ h, const float* __restrict__ Wh0,
    const float* __restrict__ bh0, const float* __restrict__ Wh1,
    const float* __restrict__ bh1, const float* __restrict__ Who,
    const float* __restrict__ bho, float* __restrict__ out) {
    extern __shared__ float sm[];
    float* buf0 = sm;                 // 16*384
    float* buf1 = buf0 + 16 * 384;    // 16*256
    float* ws = buf1 + 16 * 256;      // 2*32*256
    int r0g = blockIdx.x * 16, t = threadIdx.x;
    for (int idx = t; idx < 16 * 384; idx += 256) {
        int row = idx / 384, c = idx - row * 384;
        buf0[idx] = (c < 256) ? g_mi[(r0g + row) * 256 + c]
                              : h[(r0g + row) * 128 + (c - 256)];
    }
    __syncthreads();
    gemmR<16, 256, true>(buf0, 384, Wh0, 256, bh0, buf1, 256, ws);
    gemmR<16, 256, true>(buf1, 256, Wh1, 256, bh1, buf0, 256, ws);
    gemmR<16, 128, false>(buf0, 256, Who, 128, bho, buf1, 128, ws);
    for (int idx = t; idx < 16 * 128; idx += 256)
        out[r0g * 128 + idx] = buf1[idx] + h[r0g * 128 + idx];
}
__global__ void xnew_kernel(const float* __restrict__ x, float* __restrict__ out) {
    int idx = blockIdx.x * 256 + threadIdx.x;
    if (idx < NN * 24) out[idx] = x[idx] + g_shift[idx] * (1.0f / 511.0f);
}

// ---------------- launch ----------------
extern "C" void kernel_launch(void* const* d_in, const int* in_sizes, int n_in,
                              void* d_out, int out_size) {
    const float* x = (const float*)d_in[0];
    const float* h = (const float*)d_in[1];
    const float* We0 = (const float*)d_in[2];
    const float* be0 = (const float*)d_in[3];
    const float* We1 = (const float*)d_in[4];
    const float* be1 = (const float*)d_in[5];
    const float* Winf = (const float*)d_in[6];
    const float* binf = (const float*)d_in[7];
    const float* Wx0 = (const float*)d_in[8];
    const float* bx0 = (const float*)d_in[9];
    const float* Wx1 = (const float*)d_in[10];
    const float* bx1 = (const float*)d_in[11];
    const float* Wxo = (const float*)d_in[12];
    const float* bxo = (const float*)d_in[13];
    const float* Wh0 = (const float*)d_in[14];
    const float* bh0 = (const float*)d_in[15];
    const float* Wh1 = (const float*)d_in[16];
    const float* bh1 = (const float*)d_in[17];
    const float* Who = (const float*)d_in[18];
    const float* bho = (const float*)d_in[19];
    float* out = (float*)d_out;  // [x_new (512*24) | h_new (512*128)]

    const int AB_SMEM = (16 * 192 + 2 * 32 * 128) * 4;
    const int HNEW_SMEM = (16 * 384 + 16 * 256 + 2 * 32 * 256) * 4;
    cudaFuncSetAttribute(edge_kernel, cudaFuncAttributeMaxDynamicSharedMemorySize,
                         EDGE_SMEM);
    cudaFuncSetAttribute(prep_ab, cudaFuncAttributeMaxDynamicSharedMemorySize, AB_SMEM);
    cudaFuncSetAttribute(hnew_kernel, cudaFuncAttributeMaxDynamicSharedMemorySize,
                         HNEW_SMEM);

    prep_hc<<<NN, 256>>>(x, h);
    prep_w<<<dim3(8, 8, 3), dim3(32, 8)>>>(We1, Wx0, Wx1);
    prep_ab<<<dim3(32, 2, 2), 256, AB_SMEM>>>(We0);
    edge_kernel<<<dim3(8, NN), 256, EDGE_SMEM>>>(x, We0, be0, be1, Winf, binf, bx0,
                                                 bx1, bxo, Wxo);
    hnew_kernel<<<32, 256, HNEW_SMEM>>>(h, Wh0, bh0, Wh1, bh1, Who, bho, out + NN * 24);
    xnew_kernel<<<48, 256>>>(x, out);
}